// round 8
// baseline (speedup 1.0000x reference)
#include <cuda_runtime.h>
#include <cstdint>

#define BATCH 16
#define CDIM 128
#define NTOK 16384
#define NHEADS 8
#define HDIM 16
#define PCH 16
#define KC (NTOK / PCH)   // 1024

// ---------------- scratch (static device globals; no allocations) ----------
__device__ float g_Gpart[BATCH * PCH * CDIM * CDIM]; // ~16.8 MB
__device__ float g_spart[BATCH * PCH * CDIM];
__device__ float g_G[BATCH * CDIM * CDIM];   // tf32-rounded Gram
__device__ float g_R[BATCH * CDIM * CDIM];   // tf32-rounded Wq@G
__device__ float g_Tt[BATCH * CDIM * CDIM];  // tf32-rounded T^T
__device__ float g_M[BATCH * CDIM * CDIM];   // tf32-rounded M
__device__ float g_cv[BATCH * CDIM];

// ---------------- helpers ---------------------------------------------------
__device__ __forceinline__ uint32_t f2tf32u(float x) {
    uint32_t r;
    asm("cvt.rna.tf32.f32 %0, %1;" : "=r"(r) : "f"(x));
    return r;
}

__device__ __forceinline__ void mma_tf32(float& d0, float& d1, float& d2, float& d3,
                                         uint32_t a0, uint32_t a1, uint32_t a2, uint32_t a3,
                                         uint32_t b0, uint32_t b1) {
    asm volatile(
        "mma.sync.aligned.m16n8k8.row.col.f32.tf32.tf32.f32 "
        "{%0,%1,%2,%3}, {%4,%5,%6,%7}, {%8,%9}, {%0,%1,%2,%3};"
        : "+f"(d0), "+f"(d1), "+f"(d2), "+f"(d3)
        : "r"(a0), "r"(a1), "r"(a2), "r"(a3), "r"(b0), "r"(b1));
}

// 128x128x128 GEMM stage: C = A @ B^T, A row-major [m][k], B row-major [n][k].
// Each of 8 warps computes a 64x32 tile into acc. RoundA/RoundB: apply tf32
// rounding at load (otherwise operand is assumed pre-rounded).
template <bool RoundA, bool RoundB>
__device__ __forceinline__ void gemm128_abT(const float* __restrict__ A,
                                            const float* __restrict__ B,
                                            float acc[4][4][4],
                                            int mbase, int nbase, int gid, int tig) {
#pragma unroll
    for (int i = 0; i < 4; i++)
#pragma unroll
        for (int j = 0; j < 4; j++)
#pragma unroll
            for (int q = 0; q < 4; q++) acc[i][j][q] = 0.f;

#pragma unroll 4
    for (int ks = 0; ks < 16; ks++) {
        const int kb = ks * 8;
        uint32_t af[4][4], bf[4][2];
#pragma unroll
        for (int i = 0; i < 4; i++) {
            const int m = mbase + i * 16 + gid;
            float a0 = __ldg(&A[m * CDIM + kb + tig]);
            float a1 = __ldg(&A[(m + 8) * CDIM + kb + tig]);
            float a2 = __ldg(&A[m * CDIM + kb + tig + 4]);
            float a3 = __ldg(&A[(m + 8) * CDIM + kb + tig + 4]);
            if (RoundA) {
                af[i][0] = f2tf32u(a0); af[i][1] = f2tf32u(a1);
                af[i][2] = f2tf32u(a2); af[i][3] = f2tf32u(a3);
            } else {
                af[i][0] = __float_as_uint(a0); af[i][1] = __float_as_uint(a1);
                af[i][2] = __float_as_uint(a2); af[i][3] = __float_as_uint(a3);
            }
        }
#pragma unroll
        for (int j = 0; j < 4; j++) {
            const int n = nbase + j * 8 + gid;
            float b0 = __ldg(&B[n * CDIM + kb + tig]);
            float b1 = __ldg(&B[n * CDIM + kb + tig + 4]);
            if (RoundB) {
                bf[j][0] = f2tf32u(b0); bf[j][1] = f2tf32u(b1);
            } else {
                bf[j][0] = __float_as_uint(b0); bf[j][1] = __float_as_uint(b1);
            }
        }
#pragma unroll
        for (int i = 0; i < 4; i++)
#pragma unroll
            for (int j = 0; j < 4; j++)
                mma_tf32(acc[i][j][0], acc[i][j][1], acc[i][j][2], acc[i][j][3],
                         af[i][0], af[i][1], af[i][2], af[i][3], bf[j][0], bf[j][1]);
    }
}

// write a warp's 64x32 accumulator tile to a 128x128 row-major buffer, tf32-rounded
__device__ __forceinline__ void store_tile_tf32(float* __restrict__ C,
                                                const float acc[4][4][4],
                                                int mbase, int nbase, int gid, int tig) {
#pragma unroll
    for (int i = 0; i < 4; i++) {
        const int r0 = mbase + i * 16 + gid;
#pragma unroll
        for (int j = 0; j < 4; j++) {
            const int c0 = nbase + j * 8 + tig * 2;
            float2 v0 = make_float2(__uint_as_float(f2tf32u(acc[i][j][0])),
                                    __uint_as_float(f2tf32u(acc[i][j][1])));
            float2 v1 = make_float2(__uint_as_float(f2tf32u(acc[i][j][2])),
                                    __uint_as_float(f2tf32u(acc[i][j][3])));
            *reinterpret_cast<float2*>(&C[r0 * CDIM + c0]) = v0;
            *reinterpret_cast<float2*>(&C[(r0 + 8) * CDIM + c0]) = v1;
        }
    }
}

// ---------------- kernel 1: partial Gram G = X X^T (tf32 MMA) --------------
// grid (PCH, BATCH), block 256. Each CTA: 128x128 output over a 1024-wide K chunk.
__global__ __launch_bounds__(256) void k_gram(const float* __restrict__ x) {
    __shared__ float Xs[CDIM * 36];  // 128 rows x 32 k, stride 36 (pad 4)
    const int b = blockIdx.y, p = blockIdx.x;
    const int tid = threadIdx.x;
    const int lane = tid & 31, warp = tid >> 5;
    const int gid = lane >> 2, tig = lane & 3;
    const int mbase = (warp >> 2) * 64, nbase = (warp & 3) * 32;
    const float* xb = x + (size_t)b * CDIM * NTOK;

    float acc[4][4][4];
#pragma unroll
    for (int i = 0; i < 4; i++)
#pragma unroll
        for (int j = 0; j < 4; j++)
#pragma unroll
            for (int q = 0; q < 4; q++) acc[i][j][q] = 0.f;

    const int k0base = p * KC;
    for (int kt = 0; kt < KC / 32; kt++) {
        const int k0 = k0base + kt * 32;
#pragma unroll
        for (int pass = 0; pass < 4; pass++) {
            const int c = pass * 32 + (tid >> 3);
            const int kslot = tid & 7;
            float4 v = *reinterpret_cast<const float4*>(xb + (size_t)c * NTOK + k0 + kslot * 4);
            v.x = __uint_as_float(f2tf32u(v.x));
            v.y = __uint_as_float(f2tf32u(v.y));
            v.z = __uint_as_float(f2tf32u(v.z));
            v.w = __uint_as_float(f2tf32u(v.w));
            *reinterpret_cast<float4*>(&Xs[c * 36 + kslot * 4]) = v;
        }
        __syncthreads();
#pragma unroll
        for (int ks = 0; ks < 4; ks++) {
            const int kb = ks * 8;
            uint32_t af[4][4], bf[4][2];
#pragma unroll
            for (int i = 0; i < 4; i++) {
                const int m = mbase + i * 16 + gid;
                af[i][0] = __float_as_uint(Xs[m * 36 + kb + tig]);
                af[i][1] = __float_as_uint(Xs[(m + 8) * 36 + kb + tig]);
                af[i][2] = __float_as_uint(Xs[m * 36 + kb + tig + 4]);
                af[i][3] = __float_as_uint(Xs[(m + 8) * 36 + kb + tig + 4]);
            }
#pragma unroll
            for (int j = 0; j < 4; j++) {
                const int n = nbase + j * 8 + gid;
                bf[j][0] = __float_as_uint(Xs[n * 36 + kb + tig]);
                bf[j][1] = __float_as_uint(Xs[n * 36 + kb + tig + 4]);
            }
#pragma unroll
            for (int i = 0; i < 4; i++)
#pragma unroll
                for (int j = 0; j < 4; j++)
                    mma_tf32(acc[i][j][0], acc[i][j][1], acc[i][j][2], acc[i][j][3],
                             af[i][0], af[i][1], af[i][2], af[i][3], bf[j][0], bf[j][1]);
        }
        __syncthreads();
    }

    float* gp = g_Gpart + ((size_t)b * PCH + p) * CDIM * CDIM;
#pragma unroll
    for (int i = 0; i < 4; i++) {
        const int r0 = mbase + i * 16 + gid;
#pragma unroll
        for (int j = 0; j < 4; j++) {
            const int c0 = nbase + j * 8 + tig * 2;
            *reinterpret_cast<float2*>(&gp[r0 * CDIM + c0]) =
                make_float2(acc[i][j][0], acc[i][j][1]);
            *reinterpret_cast<float2*>(&gp[(r0 + 8) * CDIM + c0]) =
                make_float2(acc[i][j][2], acc[i][j][3]);
        }
    }

    // partial row sums s = X @ 1 over this K chunk (exact fp32 from global)
    const int r = tid >> 1;
    const float* row = xb + (size_t)r * NTOK + k0base + (tid & 1) * 512;
    float sum = 0.f;
    for (int k = 0; k < 512; k += 4) {
        float4 v = *reinterpret_cast<const float4*>(row + k);
        sum += v.x + v.y + v.z + v.w;
    }
    sum += __shfl_xor_sync(0xffffffffu, sum, 1);
    if (!(tid & 1)) g_spart[((size_t)b * PCH + p) * CDIM + r] = sum;
}

// ---------------- kernel 2 (fused): reduce + attention + M -----------------
// grid (BATCH), block 256. One CTA per batch; everything GEMM-shaped.
__global__ __launch_bounds__(256) void k_mid(const float* __restrict__ w_qkv,
                                             const float* __restrict__ b_qkv,
                                             const float* __restrict__ w_out,
                                             const float* __restrict__ b_out) {
    __shared__ float s_sh[CDIM];
    __shared__ float qs_sh[CDIM], kss_sh[CDIM];
    __shared__ float u_sh[CDIM];
    __shared__ float Ss[NHEADS][HDIM][HDIM + 1];

    const int b = blockIdx.x;
    const int tid = threadIdx.x;
    const int lane = tid & 31, warp = tid >> 5;
    const int gid = lane >> 2, tig = lane & 3;
    const int mbase = (warp >> 2) * 64, nbase = (warp & 3) * 32;

    const float* Gb  = g_G  + (size_t)b * CDIM * CDIM;
    const float* Rb  = g_R  + (size_t)b * CDIM * CDIM;
    const float* Ttb = g_Tt + (size_t)b * CDIM * CDIM;

    // ---- phase 1: reduce Gram partials -> g_G (tf32-rounded); s -> s_sh ----
    {
        const float4* gp = reinterpret_cast<const float4*>(
            g_Gpart + (size_t)b * PCH * CDIM * CDIM);
        float4* go = reinterpret_cast<float4*>(g_G + (size_t)b * CDIM * CDIM);
#pragma unroll
        for (int i = 0; i < 16; i++) {
            const int idx = i * 256 + tid;
            float4 a = gp[idx];
#pragma unroll
            for (int p = 1; p < PCH; p++) {
                float4 v = gp[(size_t)p * (CDIM * CDIM / 4) + idx];
                a.x += v.x; a.y += v.y; a.z += v.z; a.w += v.w;
            }
            a.x = __uint_as_float(f2tf32u(a.x));
            a.y = __uint_as_float(f2tf32u(a.y));
            a.z = __uint_as_float(f2tf32u(a.z));
            a.w = __uint_as_float(f2tf32u(a.w));
            go[idx] = a;
        }
        if (tid < CDIM) {
            float s = 0.f;
#pragma unroll
            for (int p = 0; p < PCH; p++)
                s += g_spart[((size_t)b * PCH + p) * CDIM + tid];
            s_sh[tid] = s;
        }
    }
    __syncthreads();

    // ---- phase 1.5: qs_all = Wq @ s, kss_all = Wk @ s (row tid of w_qkv) ----
    {
        const float* W = w_qkv + (size_t)tid * CDIM;  // rows 0..127 Wq, 128..255 Wk
        float a = 0.f;
#pragma unroll 8
        for (int c = 0; c < CDIM; c += 4)
            a += __ldg(&W[c]) * s_sh[c] + __ldg(&W[c + 1]) * s_sh[c + 1] +
                 __ldg(&W[c + 2]) * s_sh[c + 2] + __ldg(&W[c + 3]) * s_sh[c + 3];
        if (tid < CDIM) qs_sh[tid] = a;
        else            kss_sh[tid - CDIM] = a;
    }

    float acc[4][4][4];

    // ---- phase 2: R = Wq @ G (G symmetric -> B-frags are G rows) ----
    gemm128_abT<true, false>(w_qkv, Gb, acc, mbase, nbase, gid, tig);
    store_tile_tf32(g_R + (size_t)b * CDIM * CDIM, acc, mbase, nbase, gid, tig);
    __syncthreads();

    // ---- phase 3a: S_full = R @ Wk^T; keep diag 16x16 blocks + bias ----
    gemm128_abT<false, true>(Rb, w_qkv + (size_t)CDIM * CDIM, acc,
                             mbase, nbase, gid, tig);
    {
        const float scale = 0.08838834764831845f;  // 1/sqrt(128)
#pragma unroll
        for (int i = 0; i < 4; i++) {
            const int r0 = mbase + i * 16 + gid;
#pragma unroll
            for (int j = 0; j < 4; j++) {
                const int c0 = nbase + j * 8 + tig * 2;
#pragma unroll
                for (int q = 0; q < 4; q++) {
                    const int r = r0 + (q >= 2 ? 8 : 0);
                    const int c = c0 + (q & 1);
                    if ((r >> 4) == (c >> 4)) {
                        const float bq = __ldg(&b_qkv[r]);
                        const float bk = __ldg(&b_qkv[CDIM + c]);
                        float v = acc[i][j][q] + qs_sh[r] * bk + bq * kss_sh[c] +
                                  (float)NTOK * bq * bk;
                        Ss[r >> 4][r & 15][c & 15] = v * scale;
                    }
                }
            }
        }
    }
    __syncthreads();

    // ---- phase 3b: softmax rows + u = A @ bv ----
    if (tid < CDIM) {
        const int h = tid >> 4, d = tid & 15;
        float m = -1e30f;
#pragma unroll
        for (int e = 0; e < HDIM; e++) m = fmaxf(m, Ss[h][d][e]);
        float ex[HDIM], sum = 0.f;
#pragma unroll
        for (int e = 0; e < HDIM; e++) { ex[e] = expf(Ss[h][d][e] - m); sum += ex[e]; }
        const float inv = 1.f / sum;
        float u = 0.f;
#pragma unroll
        for (int e = 0; e < HDIM; e++) {
            const float p = ex[e] * inv;
            Ss[h][d][e] = p;
            u += p * __ldg(&b_qkv[2 * CDIM + h * HDIM + e]);
        }
        u_sh[tid] = u;
    }
    __syncthreads();

    // ---- phase 3c: T^T[c][r] = sum_e A[h][d][e] * Wv[h*16+e][c] ----
    {
        float* tt = g_Tt + (size_t)b * CDIM * CDIM;
#pragma unroll
        for (int it = 0; it < 16; it++) {
            const int flat = it * 256 + tid;     // float4 index into T row-major
            const int r = flat >> 5;             // T row (0..127)
            const int c4 = flat & 31;            // float4 col group
            const int h = r >> 4, d = r & 15;
            float4 a = make_float4(0.f, 0.f, 0.f, 0.f);
#pragma unroll
            for (int e = 0; e < HDIM; e++) {
                const float p = Ss[h][d][e];
                const float4 w = __ldg(reinterpret_cast<const float4*>(
                    w_qkv + (size_t)(2 * CDIM + h * HDIM + e) * CDIM + c4 * 4));
                a.x += p * w.x; a.y += p * w.y; a.z += p * w.z; a.w += p * w.w;
            }
            const int c = c4 * 4;
            tt[(c + 0) * CDIM + r] = __uint_as_float(f2tf32u(a.x));
            tt[(c + 1) * CDIM + r] = __uint_as_float(f2tf32u(a.y));
            tt[(c + 2) * CDIM + r] = __uint_as_float(f2tf32u(a.z));
            tt[(c + 3) * CDIM + r] = __uint_as_float(f2tf32u(a.w));
        }
    }
    __syncthreads();

    // ---- phase 4: M = W_out @ T  (B-frags = T^T rows) ----
    gemm128_abT<true, false>(w_out, Ttb, acc, mbase, nbase, gid, tig);
    store_tile_tf32(g_M + (size_t)b * CDIM * CDIM, acc, mbase, nbase, gid, tig);

    // ---- phase 5: cvec = W_out @ u + b_out ----
    if (tid < CDIM) {
        float a = __ldg(&b_out[tid]);
#pragma unroll 8
        for (int r = 0; r < CDIM; r++)
            a += __ldg(&w_out[tid * CDIM + r]) * u_sh[r];
        g_cv[b * CDIM + tid] = a;
    }
}

// ---------------- kernel 3: final = M @ X + c (tf32 MMA) -------------------
// grid (NTOK/128, BATCH), block 256. CTA tile 128(m) x 128(n), K=128.
__global__ __launch_bounds__(256) void k_final(const float* __restrict__ x,
                                               float* __restrict__ out) {
    __shared__ float Xs[64 * 132];
    const int b = blockIdx.y;
    const int n0 = blockIdx.x * 128;
    const int tid = threadIdx.x;
    const int lane = tid & 31, warp = tid >> 5;
    const int gid = lane >> 2, tig = lane & 3;
    const int mbase = (warp >> 2) * 64, nbase = (warp & 3) * 32;
    const float* xb = x + (size_t)b * CDIM * NTOK;
    const float* Mb = g_M + (size_t)b * CDIM * CDIM;

    float acc[4][4][4];
#pragma unroll
    for (int i = 0; i < 4; i++)
#pragma unroll
        for (int j = 0; j < 4; j++)
#pragma unroll
            for (int q = 0; q < 4; q++) acc[i][j][q] = 0.f;

    for (int kp = 0; kp < 2; kp++) {
#pragma unroll
        for (int pass = 0; pass < 8; pass++) {
            const int r = pass * 8 + (tid >> 5);
            const int slot = tid & 31;
            float4 v = *reinterpret_cast<const float4*>(
                xb + (size_t)(kp * 64 + r) * NTOK + n0 + slot * 4);
            v.x = __uint_as_float(f2tf32u(v.x));
            v.y = __uint_as_float(f2tf32u(v.y));
            v.z = __uint_as_float(f2tf32u(v.z));
            v.w = __uint_as_float(f2tf32u(v.w));
            *reinterpret_cast<float4*>(&Xs[r * 132 + slot * 4]) = v;
        }
        __syncthreads();
#pragma unroll
        for (int ks = 0; ks < 8; ks++) {
            const int kb = ks * 8;
            const int kglob = kp * 64 + kb;
            uint32_t af[4][4], bf[4][2];
#pragma unroll
            for (int i = 0; i < 4; i++) {
                const int m = mbase + i * 16 + gid;
                af[i][0] = __float_as_uint(__ldg(&Mb[m * CDIM + kglob + tig]));
                af[i][1] = __float_as_uint(__ldg(&Mb[(m + 8) * CDIM + kglob + tig]));
                af[i][2] = __float_as_uint(__ldg(&Mb[m * CDIM + kglob + tig + 4]));
                af[i][3] = __float_as_uint(__ldg(&Mb[(m + 8) * CDIM + kglob + tig + 4]));
            }
#pragma unroll
            for (int j = 0; j < 4; j++) {
                const int n = nbase + j * 8 + gid;
                bf[j][0] = __float_as_uint(Xs[(kb + tig) * 132 + n]);
                bf[j][1] = __float_as_uint(Xs[(kb + tig + 4) * 132 + n]);
            }
#pragma unroll
            for (int i = 0; i < 4; i++)
#pragma unroll
                for (int j = 0; j < 4; j++)
                    mma_tf32(acc[i][j][0], acc[i][j][1], acc[i][j][2], acc[i][j][3],
                             af[i][0], af[i][1], af[i][2], af[i][3], bf[j][0], bf[j][1]);
        }
        __syncthreads();
    }

#pragma unroll
    for (int i = 0; i < 4; i++) {
        const int r0 = mbase + i * 16 + gid;
        const float cv0 = g_cv[b * CDIM + r0];
        const float cv1 = g_cv[b * CDIM + r0 + 8];
        float* op0 = out + ((size_t)b * CDIM + r0) * NTOK + n0;
        float* op1 = op0 + (size_t)8 * NTOK;
#pragma unroll
        for (int j = 0; j < 4; j++) {
            const int c0 = nbase + j * 8 + tig * 2;
            *reinterpret_cast<float2*>(op0 + c0) =
                make_float2(acc[i][j][0] + cv0, acc[i][j][1] + cv0);
            *reinterpret_cast<float2*>(op1 + c0) =
                make_float2(acc[i][j][2] + cv1, acc[i][j][3] + cv1);
        }
    }
}

// ---------------- launch -----------------------------------------------------
extern "C" void kernel_launch(void* const* d_in, const int* in_sizes, int n_in,
                              void* d_out, int out_size) {
    (void)in_sizes; (void)n_in; (void)out_size;
    const float* x     = (const float*)d_in[0];
    const float* w_qkv = (const float*)d_in[1];
    const float* b_qkv = (const float*)d_in[2];
    const float* w_out = (const float*)d_in[3];
    const float* b_out = (const float*)d_in[4];
    float* out = (float*)d_out;

    k_gram<<<dim3(PCH, BATCH), 256>>>(x);
    k_mid<<<BATCH, 256>>>(w_qkv, b_qkv, w_out, b_out);
    k_final<<<dim3(NTOK / 128, BATCH), 256>>>(x, out);
}

// round 9
// speedup vs baseline: 1.0987x; 1.0987x over previous
#include <cuda_runtime.h>
#include <cstdint>

#define BATCH 16
#define CDIM 128
#define NTOK 16384
#define NHEADS 8
#define HDIM 16
#define PCH 16
#define KC (NTOK / PCH)   // 1024

// ---------------- scratch (static device globals; no allocations) ----------
__device__ float g_Gpart[BATCH * PCH * CDIM * CDIM]; // ~16.8 MB
__device__ float g_spart[BATCH * PCH * CDIM];
__device__ float g_G[BATCH * CDIM * CDIM];   // fp32 Gram
__device__ float g_s[BATCH * CDIM];
__device__ float g_Tt[BATCH * CDIM * CDIM];  // tf32-rounded T^T
__device__ float g_u[BATCH * CDIM];
__device__ float g_M[BATCH * CDIM * CDIM];   // tf32-rounded M
__device__ float g_cv[BATCH * CDIM];

// ---------------- helpers ---------------------------------------------------
__device__ __forceinline__ uint32_t f2tf32u(float x) {
    uint32_t r;
    asm("cvt.rna.tf32.f32 %0, %1;" : "=r"(r) : "f"(x));
    return r;
}

__device__ __forceinline__ void mma_tf32(float& d0, float& d1, float& d2, float& d3,
                                         uint32_t a0, uint32_t a1, uint32_t a2, uint32_t a3,
                                         uint32_t b0, uint32_t b1) {
    asm volatile(
        "mma.sync.aligned.m16n8k8.row.col.f32.tf32.tf32.f32 "
        "{%0,%1,%2,%3}, {%4,%5,%6,%7}, {%8,%9}, {%0,%1,%2,%3};"
        : "+f"(d0), "+f"(d1), "+f"(d2), "+f"(d3)
        : "r"(a0), "r"(a1), "r"(a2), "r"(a3), "r"(b0), "r"(b1));
}

// ---------------- kernel 1: partial Gram G = X X^T (tf32 MMA) --------------
// grid (PCH, BATCH), block 256. Double-buffered smem, fused row sums.
__global__ __launch_bounds__(256) void k_gram(const float* __restrict__ x) {
    __shared__ float Xs[2][CDIM * 36];  // 2 x (128 rows x 32 k), stride 36
    const int b = blockIdx.y, p = blockIdx.x;
    const int tid = threadIdx.x;
    const int lane = tid & 31, warp = tid >> 5;
    const int gid = lane >> 2, tig = lane & 3;
    const int mbase = (warp >> 2) * 64, nbase = (warp & 3) * 32;
    const float* xb = x + (size_t)b * CDIM * NTOK;
    const int k0base = p * KC;
    const int lc = tid >> 3;      // 0..31 row-within-pass
    const int kslot = tid & 7;

    float acc[4][4][4];
#pragma unroll
    for (int i = 0; i < 4; i++)
#pragma unroll
        for (int j = 0; j < 4; j++)
#pragma unroll
            for (int q = 0; q < 4; q++) acc[i][j][q] = 0.f;

    float rs[4] = {0.f, 0.f, 0.f, 0.f};  // fused row-sum partials

    auto load_tile = [&](int kt, int buf) {
        const int k0 = k0base + kt * 32;
#pragma unroll
        for (int pass = 0; pass < 4; pass++) {
            const int c = pass * 32 + lc;
            float4 v = *reinterpret_cast<const float4*>(
                xb + (size_t)c * NTOK + k0 + kslot * 4);
            rs[pass] += v.x + v.y + v.z + v.w;
            v.x = __uint_as_float(f2tf32u(v.x));
            v.y = __uint_as_float(f2tf32u(v.y));
            v.z = __uint_as_float(f2tf32u(v.z));
            v.w = __uint_as_float(f2tf32u(v.w));
            *reinterpret_cast<float4*>(&Xs[buf][c * 36 + kslot * 4]) = v;
        }
    };

    load_tile(0, 0);
    __syncthreads();

    for (int kt = 0; kt < KC / 32; kt++) {
        const int cur = kt & 1;
        if (kt + 1 < KC / 32) load_tile(kt + 1, cur ^ 1);
#pragma unroll
        for (int ks = 0; ks < 4; ks++) {
            const int kb = ks * 8;
            uint32_t af[4][4], bf[4][2];
#pragma unroll
            for (int i = 0; i < 4; i++) {
                const int m = mbase + i * 16 + gid;
                af[i][0] = __float_as_uint(Xs[cur][m * 36 + kb + tig]);
                af[i][1] = __float_as_uint(Xs[cur][(m + 8) * 36 + kb + tig]);
                af[i][2] = __float_as_uint(Xs[cur][m * 36 + kb + tig + 4]);
                af[i][3] = __float_as_uint(Xs[cur][(m + 8) * 36 + kb + tig + 4]);
            }
#pragma unroll
            for (int j = 0; j < 4; j++) {
                const int n = nbase + j * 8 + gid;
                bf[j][0] = __float_as_uint(Xs[cur][n * 36 + kb + tig]);
                bf[j][1] = __float_as_uint(Xs[cur][n * 36 + kb + tig + 4]);
            }
#pragma unroll
            for (int i = 0; i < 4; i++)
#pragma unroll
                for (int j = 0; j < 4; j++)
                    mma_tf32(acc[i][j][0], acc[i][j][1], acc[i][j][2], acc[i][j][3],
                             af[i][0], af[i][1], af[i][2], af[i][3], bf[j][0], bf[j][1]);
        }
        __syncthreads();
    }

    // write partial G
    float* gp = g_Gpart + ((size_t)b * PCH + p) * CDIM * CDIM;
#pragma unroll
    for (int i = 0; i < 4; i++) {
        const int r0 = mbase + i * 16 + gid;
#pragma unroll
        for (int j = 0; j < 4; j++) {
            const int c0 = nbase + j * 8 + tig * 2;
            *reinterpret_cast<float2*>(&gp[r0 * CDIM + c0]) =
                make_float2(acc[i][j][0], acc[i][j][1]);
            *reinterpret_cast<float2*>(&gp[(r0 + 8) * CDIM + c0]) =
                make_float2(acc[i][j][2], acc[i][j][3]);
        }
    }

    // row-sum reduction across the 8 kslot lanes (consecutive within warp)
#pragma unroll
    for (int off = 1; off < 8; off <<= 1)
#pragma unroll
        for (int pass = 0; pass < 4; pass++)
            rs[pass] += __shfl_xor_sync(0xffffffffu, rs[pass], off);
    if (kslot == 0) {
#pragma unroll
        for (int pass = 0; pass < 4; pass++)
            g_spart[((size_t)b * PCH + p) * CDIM + pass * 32 + lc] = rs[pass];
    }
}

// ---------------- kernel 2: reduce partials (fp32, vectorized) -------------
// grid (8, BATCH), block 256
__global__ __launch_bounds__(256) void k_reduceG() {
    const int b = blockIdx.y;
    const float4* gp = reinterpret_cast<const float4*>(
        g_Gpart + (size_t)b * PCH * CDIM * CDIM);
    float4* go = reinterpret_cast<float4*>(g_G + (size_t)b * CDIM * CDIM);
    const int base = blockIdx.x * 512;  // float4 units; 8*512 = 4096 = 16384 floats
#pragma unroll
    for (int it = 0; it < 2; it++) {
        const int idx = base + it * 256 + threadIdx.x;
        float4 a = gp[idx];
#pragma unroll
        for (int p = 1; p < PCH; p++) {
            float4 v = gp[(size_t)p * (CDIM * CDIM / 4) + idx];
            a.x += v.x; a.y += v.y; a.z += v.z; a.w += v.w;
        }
        go[idx] = a;
    }
    if (blockIdx.x == 0 && threadIdx.x < CDIM) {
        float s = 0.f;
#pragma unroll
        for (int p = 0; p < PCH; p++)
            s += g_spart[((size_t)b * PCH + p) * CDIM + threadIdx.x];
        g_s[b * CDIM + threadIdx.x] = s;
    }
}

// ---------------- kernel 3: per-(batch,head) scores/softmax/T^T ------------
// grid (NHEADS, BATCH), block 256. All score math in fp32.
__global__ __launch_bounds__(256) void k_attn(const float* __restrict__ w_qkv,
                                              const float* __restrict__ b_qkv) {
    __shared__ float Rs[HDIM][CDIM];
    __shared__ float Ss[HDIM][HDIM];
    __shared__ float qs[HDIM], kssum[HDIM];
    const int h = blockIdx.x, b = blockIdx.y;
    const int tid = threadIdx.x;
    const int d = tid >> 4, cg = tid & 15;
    const float* G = g_G + (size_t)b * CDIM * CDIM;
    const float* Wq = w_qkv + (size_t)(h * HDIM) * CDIM;
    const float* Wk = w_qkv + (size_t)(CDIM + h * HDIM) * CDIM;
    const float* Wv = w_qkv + (size_t)(2 * CDIM + h * HDIM) * CDIM;

    if (tid < 2 * HDIM) {
        const int dd = tid & 15;
        const float* W = (tid < HDIM) ? Wq : Wk;
        float acc = 0.f;
        for (int c = 0; c < CDIM; c++) acc += W[dd * CDIM + c] * g_s[b * CDIM + c];
        if (tid < HDIM) qs[dd] = acc; else kssum[dd] = acc;
    }

    // R = Wq_h @ G (16x128, fp32)
    {
        float a[8] = {0, 0, 0, 0, 0, 0, 0, 0};
#pragma unroll 4
        for (int c = 0; c < CDIM; c++) {
            const float wq = __ldg(&Wq[d * CDIM + c]);
            const float4* gp = reinterpret_cast<const float4*>(G + c * CDIM + cg * 8);
            const float4 g0 = __ldg(gp), g1 = __ldg(gp + 1);
            a[0] += wq * g0.x; a[1] += wq * g0.y; a[2] += wq * g0.z; a[3] += wq * g0.w;
            a[4] += wq * g1.x; a[5] += wq * g1.y; a[6] += wq * g1.z; a[7] += wq * g1.w;
        }
#pragma unroll
        for (int j = 0; j < 8; j++) Rs[d][cg * 8 + j] = a[j];
    }
    __syncthreads();

    // scores (fp32)
    {
        const int e = cg;
        float acc = 0.f;
#pragma unroll 4
        for (int c = 0; c < CDIM; c++) acc += Rs[d][c] * __ldg(&Wk[e * CDIM + c]);
        const float bq = b_qkv[h * HDIM + d];
        const float bk = b_qkv[CDIM + h * HDIM + e];
        acc += qs[d] * bk + bq * kssum[e] + (float)NTOK * bq * bk;
        Ss[d][e] = acc * 0.08838834764831845f;  // 1/sqrt(128)
    }
    __syncthreads();

    // softmax rows + u
    if (tid < HDIM) {
        float m = -1e30f;
#pragma unroll
        for (int e = 0; e < HDIM; e++) m = fmaxf(m, Ss[tid][e]);
        float ex[HDIM], sum = 0.f;
#pragma unroll
        for (int e = 0; e < HDIM; e++) { ex[e] = expf(Ss[tid][e] - m); sum += ex[e]; }
        const float inv = 1.f / sum;
        float u = 0.f;
#pragma unroll
        for (int e = 0; e < HDIM; e++) {
            const float pv = ex[e] * inv;
            Ss[tid][e] = pv;
            u += pv * __ldg(&b_qkv[2 * CDIM + h * HDIM + e]);
        }
        g_u[b * CDIM + h * HDIM + tid] = u;
    }
    __syncthreads();

    // T^T (tf32-rounded): T[h*16+d][c] = sum_e A[d][e] Wv[e][c]
    {
        float a[8] = {0, 0, 0, 0, 0, 0, 0, 0};
#pragma unroll
        for (int e = 0; e < HDIM; e++) {
            const float av = Ss[d][e];
            const float4* vp = reinterpret_cast<const float4*>(Wv + e * CDIM + cg * 8);
            const float4 v0 = __ldg(vp), v1 = __ldg(vp + 1);
            a[0] += av * v0.x; a[1] += av * v0.y; a[2] += av * v0.z; a[3] += av * v0.w;
            a[4] += av * v1.x; a[5] += av * v1.y; a[6] += av * v1.z; a[7] += av * v1.w;
        }
        float* tt = g_Tt + (size_t)b * CDIM * CDIM;
        const int r = h * HDIM + d;
#pragma unroll
        for (int j = 0; j < 8; j++)
            tt[(cg * 8 + j) * CDIM + r] = __uint_as_float(f2tf32u(a[j]));
    }
}

// ---------------- kernel 4: M = W_out @ T via tf32 MMA; cvec ---------------
// grid (BATCH), block 256. B-frags are T^T rows (pre-rounded).
__global__ __launch_bounds__(256) void k_mout(const float* __restrict__ w_out,
                                              const float* __restrict__ b_out) {
    const int b = blockIdx.x;
    const int tid = threadIdx.x;
    const int lane = tid & 31, warp = tid >> 5;
    const int gid = lane >> 2, tig = lane & 3;
    const int mbase = (warp >> 2) * 64, nbase = (warp & 3) * 32;
    const float* Tt = g_Tt + (size_t)b * CDIM * CDIM;

    float acc[4][4][4];
#pragma unroll
    for (int i = 0; i < 4; i++)
#pragma unroll
        for (int j = 0; j < 4; j++)
#pragma unroll
            for (int q = 0; q < 4; q++) acc[i][j][q] = 0.f;

#pragma unroll 4
    for (int ks = 0; ks < 16; ks++) {
        const int kb = ks * 8;
        uint32_t af[4][4], bf[4][2];
#pragma unroll
        for (int i = 0; i < 4; i++) {
            const int m = mbase + i * 16 + gid;
            af[i][0] = f2tf32u(__ldg(&w_out[m * CDIM + kb + tig]));
            af[i][1] = f2tf32u(__ldg(&w_out[(m + 8) * CDIM + kb + tig]));
            af[i][2] = f2tf32u(__ldg(&w_out[m * CDIM + kb + tig + 4]));
            af[i][3] = f2tf32u(__ldg(&w_out[(m + 8) * CDIM + kb + tig + 4]));
        }
#pragma unroll
        for (int j = 0; j < 4; j++) {
            const int n = nbase + j * 8 + gid;
            bf[j][0] = __float_as_uint(__ldg(&Tt[n * CDIM + kb + tig]));
            bf[j][1] = __float_as_uint(__ldg(&Tt[n * CDIM + kb + tig + 4]));
        }
#pragma unroll
        for (int i = 0; i < 4; i++)
#pragma unroll
            for (int j = 0; j < 4; j++)
                mma_tf32(acc[i][j][0], acc[i][j][1], acc[i][j][2], acc[i][j][3],
                         af[i][0], af[i][1], af[i][2], af[i][3], bf[j][0], bf[j][1]);
    }

    float* Mb = g_M + (size_t)b * CDIM * CDIM;
#pragma unroll
    for (int i = 0; i < 4; i++) {
        const int r0 = mbase + i * 16 + gid;
#pragma unroll
        for (int j = 0; j < 4; j++) {
            const int c0 = nbase + j * 8 + tig * 2;
            float2 v0 = make_float2(__uint_as_float(f2tf32u(acc[i][j][0])),
                                    __uint_as_float(f2tf32u(acc[i][j][1])));
            float2 v1 = make_float2(__uint_as_float(f2tf32u(acc[i][j][2])),
                                    __uint_as_float(f2tf32u(acc[i][j][3])));
            *reinterpret_cast<float2*>(&Mb[r0 * CDIM + c0]) = v0;
            *reinterpret_cast<float2*>(&Mb[(r0 + 8) * CDIM + c0]) = v1;
        }
    }

    // cvec = W_out @ u + b_out (fp32)
    if (tid < CDIM) {
        float a = __ldg(&b_out[tid]);
#pragma unroll 8
        for (int r = 0; r < CDIM; r++)
            a += __ldg(&w_out[tid * CDIM + r]) * g_u[b * CDIM + r];
        g_cv[b * CDIM + tid] = a;
    }
}

// ---------------- kernel 5: final = M @ X + c (tf32 MMA, double-buffered) --
// grid (NTOK/128, BATCH), block 256. CTA tile 128(m) x 128(n), K=128 in 4x32.
__global__ __launch_bounds__(256) void k_final(const float* __restrict__ x,
                                               float* __restrict__ out) {
    __shared__ float Xs[2][32 * 132];
    const int b = blockIdx.y;
    const int n0 = blockIdx.x * 128;
    const int tid = threadIdx.x;
    const int lane = tid & 31, warp = tid >> 5;
    const int gid = lane >> 2, tig = lane & 3;
    const int mbase = (warp >> 2) * 64, nbase = (warp & 3) * 32;
    const float* xb = x + (size_t)b * CDIM * NTOK;
    const float* Mb = g_M + (size_t)b * CDIM * CDIM;

    float acc[4][4][4];
#pragma unroll
    for (int i = 0; i < 4; i++)
#pragma unroll
        for (int j = 0; j < 4; j++)
#pragma unroll
            for (int q = 0; q < 4; q++) acc[i][j][q] = 0.f;

    auto load_tile = [&](int kt, int buf) {
#pragma unroll
        for (int pass = 0; pass < 4; pass++) {
            const int r = pass * 8 + (tid >> 5);
            const int slot = tid & 31;
            float4 v = *reinterpret_cast<const float4*>(
                xb + (size_t)(kt * 32 + r) * NTOK + n0 + slot * 4);
            v.x = __uint_as_float(f2tf32u(v.x));
            v.y = __uint_as_float(f2tf32u(v.y));
            v.z = __uint_as_float(f2tf32u(v.z));
            v.w = __uint_as_float(f2tf32u(v.w));
            *reinterpret_cast<float4*>(&Xs[buf][r * 132 + slot * 4]) = v;
        }
    };

    load_tile(0, 0);
    __syncthreads();

    for (int kt = 0; kt < 4; kt++) {
        const int cur = kt & 1;
        if (kt + 1 < 4) load_tile(kt + 1, cur ^ 1);
#pragma unroll
        for (int ks = 0; ks < 4; ks++) {
            const int kb = ks * 8;
            const int kglob = kt * 32 + kb;
            uint32_t af[4][4], bf[4][2];
#pragma unroll
            for (int i = 0; i < 4; i++) {
                const int m = mbase + i * 16 + gid;
                af[i][0] = __float_as_uint(__ldg(&Mb[m * CDIM + kglob + tig]));
                af[i][1] = __float_as_uint(__ldg(&Mb[(m + 8) * CDIM + kglob + tig]));
                af[i][2] = __float_as_uint(__ldg(&Mb[m * CDIM + kglob + tig + 4]));
                af[i][3] = __float_as_uint(__ldg(&Mb[(m + 8) * CDIM + kglob + tig + 4]));
            }
#pragma unroll
            for (int j = 0; j < 4; j++) {
                const int n = nbase + j * 8 + gid;
                bf[j][0] = __float_as_uint(Xs[cur][(kb + tig) * 132 + n]);
                bf[j][1] = __float_as_uint(Xs[cur][(kb + tig + 4) * 132 + n]);
            }
#pragma unroll
            for (int i = 0; i < 4; i++)
#pragma unroll
                for (int j = 0; j < 4; j++)
                    mma_tf32(acc[i][j][0], acc[i][j][1], acc[i][j][2], acc[i][j][3],
                             af[i][0], af[i][1], af[i][2], af[i][3], bf[j][0], bf[j][1]);
        }
        __syncthreads();
    }

    // epilogue: + cvec, write out
#pragma unroll
    for (int i = 0; i < 4; i++) {
        const int r0 = mbase + i * 16 + gid;
        const float cv0 = g_cv[b * CDIM + r0];
        const float cv1 = g_cv[b * CDIM + r0 + 8];
        float* op0 = out + ((size_t)b * CDIM + r0) * NTOK + n0;
        float* op1 = op0 + (size_t)8 * NTOK;
#pragma unroll
        for (int j = 0; j < 4; j++) {
            const int c0 = nbase + j * 8 + tig * 2;
            *reinterpret_cast<float2*>(op0 + c0) =
                make_float2(acc[i][j][0] + cv0, acc[i][j][1] + cv0);
            *reinterpret_cast<float2*>(op1 + c0) =
                make_float2(acc[i][j][2] + cv1, acc[i][j][3] + cv1);
        }
    }
}

// ---------------- launch -----------------------------------------------------
extern "C" void kernel_launch(void* const* d_in, const int* in_sizes, int n_in,
                              void* d_out, int out_size) {
    (void)in_sizes; (void)n_in; (void)out_size;
    const float* x     = (const float*)d_in[0];
    const float* w_qkv = (const float*)d_in[1];
    const float* b_qkv = (const float*)d_in[2];
    const float* w_out = (const float*)d_in[3];
    const float* b_out = (const float*)d_in[4];
    float* out = (float*)d_out;

    k_gram<<<dim3(PCH, BATCH), 256>>>(x);
    k_reduceG<<<dim3(8, BATCH), 256>>>();
    k_attn<<<dim3(NHEADS, BATCH), 256>>>(w_qkv, b_qkv);
    k_mout<<<BATCH, 256>>>(w_out, b_out);
    k_final<<<dim3(NTOK / 128, BATCH), 256>>>(x, out);
}

// round 10
// speedup vs baseline: 1.2126x; 1.1036x over previous
#include <cuda_runtime.h>
#include <cstdint>

#define BATCH 16
#define CDIM 128
#define NTOK 16384
#define NHEADS 8
#define HDIM 16
#define PCH 16
#define KC (NTOK / PCH)   // 1024

// ---------------- scratch (static device globals; no allocations) ----------
__device__ float g_Gpart[BATCH * PCH * CDIM * CDIM]; // ~16.8 MB
__device__ float g_spart[BATCH * PCH * CDIM];
__device__ float g_G[BATCH * CDIM * CDIM];   // fp32 Gram
__device__ float g_s[BATCH * CDIM];
__device__ float g_Tt[BATCH * CDIM * CDIM];  // tf32-rounded T^T
__device__ float g_u[BATCH * CDIM];
__device__ float g_M[BATCH * CDIM * CDIM];   // tf32-rounded M
__device__ float g_cv[BATCH * CDIM];

// ---------------- helpers ---------------------------------------------------
__device__ __forceinline__ uint32_t f2tf32u(float x) {
    uint32_t r;
    asm("cvt.rna.tf32.f32 %0, %1;" : "=r"(r) : "f"(x));
    return r;
}

__device__ __forceinline__ void mma_tf32(float& d0, float& d1, float& d2, float& d3,
                                         uint32_t a0, uint32_t a1, uint32_t a2, uint32_t a3,
                                         uint32_t b0, uint32_t b1) {
    asm volatile(
        "mma.sync.aligned.m16n8k8.row.col.f32.tf32.tf32.f32 "
        "{%0,%1,%2,%3}, {%4,%5,%6,%7}, {%8,%9}, {%0,%1,%2,%3};"
        : "+f"(d0), "+f"(d1), "+f"(d2), "+f"(d3)
        : "r"(a0), "r"(a1), "r"(a2), "r"(a3), "r"(b0), "r"(b1));
}

// ---------------- kernel 1: partial Gram G = X X^T (tf32 MMA) --------------
// grid (PCH, BATCH), block 256. Double-buffered smem, fused row sums.
__global__ __launch_bounds__(256) void k_gram(const float* __restrict__ x) {
    __shared__ float Xs[2][CDIM * 36];  // 2 x (128 rows x 32 k), stride 36
    const int b = blockIdx.y, p = blockIdx.x;
    const int tid = threadIdx.x;
    const int lane = tid & 31, warp = tid >> 5;
    const int gid = lane >> 2, tig = lane & 3;
    const int mbase = (warp >> 2) * 64, nbase = (warp & 3) * 32;
    const float* xb = x + (size_t)b * CDIM * NTOK;
    const int k0base = p * KC;
    const int lc = tid >> 3;      // 0..31 row-within-pass
    const int kslot = tid & 7;

    float acc[4][4][4];
#pragma unroll
    for (int i = 0; i < 4; i++)
#pragma unroll
        for (int j = 0; j < 4; j++)
#pragma unroll
            for (int q = 0; q < 4; q++) acc[i][j][q] = 0.f;

    float rs[4] = {0.f, 0.f, 0.f, 0.f};  // fused row-sum partials

    auto load_tile = [&](int kt, int buf) {
        const int k0 = k0base + kt * 32;
#pragma unroll
        for (int pass = 0; pass < 4; pass++) {
            const int c = pass * 32 + lc;
            float4 v = *reinterpret_cast<const float4*>(
                xb + (size_t)c * NTOK + k0 + kslot * 4);
            rs[pass] += v.x + v.y + v.z + v.w;
            v.x = __uint_as_float(f2tf32u(v.x));
            v.y = __uint_as_float(f2tf32u(v.y));
            v.z = __uint_as_float(f2tf32u(v.z));
            v.w = __uint_as_float(f2tf32u(v.w));
            *reinterpret_cast<float4*>(&Xs[buf][c * 36 + kslot * 4]) = v;
        }
    };

    load_tile(0, 0);
    __syncthreads();

    for (int kt = 0; kt < KC / 32; kt++) {
        const int cur = kt & 1;
        if (kt + 1 < KC / 32) load_tile(kt + 1, cur ^ 1);
#pragma unroll
        for (int ks = 0; ks < 4; ks++) {
            const int kb = ks * 8;
            uint32_t af[4][4], bf[4][2];
#pragma unroll
            for (int i = 0; i < 4; i++) {
                const int m = mbase + i * 16 + gid;
                af[i][0] = __float_as_uint(Xs[cur][m * 36 + kb + tig]);
                af[i][1] = __float_as_uint(Xs[cur][(m + 8) * 36 + kb + tig]);
                af[i][2] = __float_as_uint(Xs[cur][m * 36 + kb + tig + 4]);
                af[i][3] = __float_as_uint(Xs[cur][(m + 8) * 36 + kb + tig + 4]);
            }
#pragma unroll
            for (int j = 0; j < 4; j++) {
                const int n = nbase + j * 8 + gid;
                bf[j][0] = __float_as_uint(Xs[cur][n * 36 + kb + tig]);
                bf[j][1] = __float_as_uint(Xs[cur][n * 36 + kb + tig + 4]);
            }
#pragma unroll
            for (int i = 0; i < 4; i++)
#pragma unroll
                for (int j = 0; j < 4; j++)
                    mma_tf32(acc[i][j][0], acc[i][j][1], acc[i][j][2], acc[i][j][3],
                             af[i][0], af[i][1], af[i][2], af[i][3], bf[j][0], bf[j][1]);
        }
        __syncthreads();
    }

    // write partial G
    float* gp = g_Gpart + ((size_t)b * PCH + p) * CDIM * CDIM;
#pragma unroll
    for (int i = 0; i < 4; i++) {
        const int r0 = mbase + i * 16 + gid;
#pragma unroll
        for (int j = 0; j < 4; j++) {
            const int c0 = nbase + j * 8 + tig * 2;
            *reinterpret_cast<float2*>(&gp[r0 * CDIM + c0]) =
                make_float2(acc[i][j][0], acc[i][j][1]);
            *reinterpret_cast<float2*>(&gp[(r0 + 8) * CDIM + c0]) =
                make_float2(acc[i][j][2], acc[i][j][3]);
        }
    }

    // row-sum reduction across the 8 kslot lanes (consecutive within warp)
#pragma unroll
    for (int off = 1; off < 8; off <<= 1)
#pragma unroll
        for (int pass = 0; pass < 4; pass++)
            rs[pass] += __shfl_xor_sync(0xffffffffu, rs[pass], off);
    if (kslot == 0) {
#pragma unroll
        for (int pass = 0; pass < 4; pass++)
            g_spart[((size_t)b * PCH + p) * CDIM + pass * 32 + lc] = rs[pass];
    }
}

// ---------------- kernel 2: reduce partials (fp32, vectorized) -------------
// grid (8, BATCH), block 256
__global__ __launch_bounds__(256) void k_reduceG() {
    const int b = blockIdx.y;
    const float4* gp = reinterpret_cast<const float4*>(
        g_Gpart + (size_t)b * PCH * CDIM * CDIM);
    float4* go = reinterpret_cast<float4*>(g_G + (size_t)b * CDIM * CDIM);
    const int base = blockIdx.x * 512;  // float4 units
#pragma unroll
    for (int it = 0; it < 2; it++) {
        const int idx = base + it * 256 + threadIdx.x;
        float4 a = gp[idx];
#pragma unroll
        for (int p = 1; p < PCH; p++) {
            float4 v = gp[(size_t)p * (CDIM * CDIM / 4) + idx];
            a.x += v.x; a.y += v.y; a.z += v.z; a.w += v.w;
        }
        go[idx] = a;
    }
    if (blockIdx.x == 0 && threadIdx.x < CDIM) {
        float s = 0.f;
#pragma unroll
        for (int p = 0; p < PCH; p++)
            s += g_spart[((size_t)b * PCH + p) * CDIM + threadIdx.x];
        g_s[b * CDIM + threadIdx.x] = s;
    }
}

// ---------------- kernel 3: per-(batch,head) scores/softmax/T^T ------------
// grid (NHEADS, BATCH), block 256. All score math in fp32.
__global__ __launch_bounds__(256) void k_attn(const float* __restrict__ w_qkv,
                                              const float* __restrict__ b_qkv) {
    __shared__ float Rs[HDIM][CDIM];
    __shared__ float Ss[HDIM][HDIM];
    __shared__ float qs[HDIM], kssum[HDIM];
    const int h = blockIdx.x, b = blockIdx.y;
    const int tid = threadIdx.x;
    const int d = tid >> 4, cg = tid & 15;
    const float* G = g_G + (size_t)b * CDIM * CDIM;
    const float* Wq = w_qkv + (size_t)(h * HDIM) * CDIM;
    const float* Wk = w_qkv + (size_t)(CDIM + h * HDIM) * CDIM;
    const float* Wv = w_qkv + (size_t)(2 * CDIM + h * HDIM) * CDIM;

    if (tid < 2 * HDIM) {
        const int dd = tid & 15;
        const float* W = (tid < HDIM) ? Wq : Wk;
        float acc = 0.f;
        for (int c = 0; c < CDIM; c++) acc += W[dd * CDIM + c] * g_s[b * CDIM + c];
        if (tid < HDIM) qs[dd] = acc; else kssum[dd] = acc;
    }

    // R = Wq_h @ G (16x128, fp32)
    {
        float a[8] = {0, 0, 0, 0, 0, 0, 0, 0};
#pragma unroll 4
        for (int c = 0; c < CDIM; c++) {
            const float wq = __ldg(&Wq[d * CDIM + c]);
            const float4* gp = reinterpret_cast<const float4*>(G + c * CDIM + cg * 8);
            const float4 g0 = __ldg(gp), g1 = __ldg(gp + 1);
            a[0] += wq * g0.x; a[1] += wq * g0.y; a[2] += wq * g0.z; a[3] += wq * g0.w;
            a[4] += wq * g1.x; a[5] += wq * g1.y; a[6] += wq * g1.z; a[7] += wq * g1.w;
        }
#pragma unroll
        for (int j = 0; j < 8; j++) Rs[d][cg * 8 + j] = a[j];
    }
    __syncthreads();

    // scores (fp32)
    {
        const int e = cg;
        float acc = 0.f;
#pragma unroll 4
        for (int c = 0; c < CDIM; c++) acc += Rs[d][c] * __ldg(&Wk[e * CDIM + c]);
        const float bq = b_qkv[h * HDIM + d];
        const float bk = b_qkv[CDIM + h * HDIM + e];
        acc += qs[d] * bk + bq * kssum[e] + (float)NTOK * bq * bk;
        Ss[d][e] = acc * 0.08838834764831845f;  // 1/sqrt(128)
    }
    __syncthreads();

    // softmax rows + u
    if (tid < HDIM) {
        float m = -1e30f;
#pragma unroll
        for (int e = 0; e < HDIM; e++) m = fmaxf(m, Ss[tid][e]);
        float ex[HDIM], sum = 0.f;
#pragma unroll
        for (int e = 0; e < HDIM; e++) { ex[e] = expf(Ss[tid][e] - m); sum += ex[e]; }
        const float inv = 1.f / sum;
        float u = 0.f;
#pragma unroll
        for (int e = 0; e < HDIM; e++) {
            const float pv = ex[e] * inv;
            Ss[tid][e] = pv;
            u += pv * __ldg(&b_qkv[2 * CDIM + h * HDIM + e]);
        }
        g_u[b * CDIM + h * HDIM + tid] = u;
    }
    __syncthreads();

    // T^T (tf32-rounded): T[h*16+d][c] = sum_e A[d][e] Wv[e][c]
    {
        float a[8] = {0, 0, 0, 0, 0, 0, 0, 0};
#pragma unroll
        for (int e = 0; e < HDIM; e++) {
            const float av = Ss[d][e];
            const float4* vp = reinterpret_cast<const float4*>(Wv + e * CDIM + cg * 8);
            const float4 v0 = __ldg(vp), v1 = __ldg(vp + 1);
            a[0] += av * v0.x; a[1] += av * v0.y; a[2] += av * v0.z; a[3] += av * v0.w;
            a[4] += av * v1.x; a[5] += av * v1.y; a[6] += av * v1.z; a[7] += av * v1.w;
        }
        float* tt = g_Tt + (size_t)b * CDIM * CDIM;
        const int r = h * HDIM + d;
#pragma unroll
        for (int j = 0; j < 8; j++)
            tt[(cg * 8 + j) * CDIM + r] = __uint_as_float(f2tf32u(a[j]));
    }
}

// ---------------- kernel 4: M = W_out @ T via tf32 MMA; cvec ---------------
// grid (8, BATCH), block 256. N split 8 ways -> 128 CTAs, short chains.
__global__ __launch_bounds__(256) void k_mout(const float* __restrict__ w_out,
                                              const float* __restrict__ b_out) {
    const int b = blockIdx.y;
    const int n0 = blockIdx.x * 16;
    const int tid = threadIdx.x;
    const int lane = tid & 31, warp = tid >> 5;
    const int gid = lane >> 2, tig = lane & 3;
    const float* Tt = g_Tt + (size_t)b * CDIM * CDIM;

    float acc[2][4];
#pragma unroll
    for (int j = 0; j < 2; j++)
#pragma unroll
        for (int q = 0; q < 4; q++) acc[j][q] = 0.f;

    const int m = warp * 16 + gid;  // warp covers rows warp*16..+16
#pragma unroll
    for (int ks = 0; ks < 16; ks++) {
        const int kb = ks * 8;
        uint32_t af[4], bf[2][2];
        af[0] = f2tf32u(__ldg(&w_out[m * CDIM + kb + tig]));
        af[1] = f2tf32u(__ldg(&w_out[(m + 8) * CDIM + kb + tig]));
        af[2] = f2tf32u(__ldg(&w_out[m * CDIM + kb + tig + 4]));
        af[3] = f2tf32u(__ldg(&w_out[(m + 8) * CDIM + kb + tig + 4]));
#pragma unroll
        for (int j = 0; j < 2; j++) {
            const int n = n0 + j * 8 + gid;
            bf[j][0] = __float_as_uint(__ldg(&Tt[n * CDIM + kb + tig]));
            bf[j][1] = __float_as_uint(__ldg(&Tt[n * CDIM + kb + tig + 4]));
        }
#pragma unroll
        for (int j = 0; j < 2; j++)
            mma_tf32(acc[j][0], acc[j][1], acc[j][2], acc[j][3],
                     af[0], af[1], af[2], af[3], bf[j][0], bf[j][1]);
    }

    float* Mb = g_M + (size_t)b * CDIM * CDIM;
#pragma unroll
    for (int j = 0; j < 2; j++) {
        const int c0 = n0 + j * 8 + tig * 2;
        float2 v0 = make_float2(__uint_as_float(f2tf32u(acc[j][0])),
                                __uint_as_float(f2tf32u(acc[j][1])));
        float2 v1 = make_float2(__uint_as_float(f2tf32u(acc[j][2])),
                                __uint_as_float(f2tf32u(acc[j][3])));
        *reinterpret_cast<float2*>(&Mb[m * CDIM + c0]) = v0;
        *reinterpret_cast<float2*>(&Mb[(m + 8) * CDIM + c0]) = v1;
    }

    // cvec = W_out @ u + b_out (fp32)
    if (blockIdx.x == 0 && tid < CDIM) {
        float a = __ldg(&b_out[tid]);
#pragma unroll 8
        for (int r = 0; r < CDIM; r++)
            a += __ldg(&w_out[tid * CDIM + r]) * g_u[b * CDIM + r];
        g_cv[b * CDIM + tid] = a;
    }
}

// ---------------- kernel 5: final = M @ X + c (tf32 MMA) -------------------
// grid (NTOK/64, BATCH), block 256. CTA tile 128(m) x 64(n), K=128 in one
// smem tile (single barrier), warp tile 32x32 -> low regs, 2-3 CTAs/SM.
__global__ __launch_bounds__(256) void k_final(const float* __restrict__ x,
                                               float* __restrict__ out) {
    __shared__ float Xs[CDIM * 68];   // 128 k-rows x 64 n-cols, stride 68
    const int b = blockIdx.y;
    const int n0 = blockIdx.x * 64;
    const int tid = threadIdx.x;
    const int lane = tid & 31, warp = tid >> 5;
    const int gid = lane >> 2, tig = lane & 3;
    const int mbase = (warp >> 1) * 32;   // 4 m-warps
    const int nwarp = (warp & 1) * 32;    // 2 n-warps
    const float* xb = x + (size_t)b * CDIM * NTOK;
    const float* Mb = g_M + (size_t)b * CDIM * CDIM;

    // load full 128x64 X tile (tf32-rounded), one barrier total
    {
        const int rbase = tid >> 4;       // 0..15
        const int slot = tid & 15;        // float4 column group
#pragma unroll
        for (int pass = 0; pass < 8; pass++) {
            const int r = pass * 16 + rbase;
            float4 v = *reinterpret_cast<const float4*>(
                xb + (size_t)r * NTOK + n0 + slot * 4);
            v.x = __uint_as_float(f2tf32u(v.x));
            v.y = __uint_as_float(f2tf32u(v.y));
            v.z = __uint_as_float(f2tf32u(v.z));
            v.w = __uint_as_float(f2tf32u(v.w));
            *reinterpret_cast<float4*>(&Xs[r * 68 + slot * 4]) = v;
        }
    }
    __syncthreads();

    float acc[2][4][4];
#pragma unroll
    for (int i = 0; i < 2; i++)
#pragma unroll
        for (int j = 0; j < 4; j++)
#pragma unroll
            for (int q = 0; q < 4; q++) acc[i][j][q] = 0.f;

#pragma unroll
    for (int ks = 0; ks < 16; ks++) {
        const int kb = ks * 8;
        uint32_t af[2][4], bf[4][2];
#pragma unroll
        for (int i = 0; i < 2; i++) {
            const int m = mbase + i * 16 + gid;
            af[i][0] = __float_as_uint(__ldg(&Mb[m * CDIM + kb + tig]));
            af[i][1] = __float_as_uint(__ldg(&Mb[(m + 8) * CDIM + kb + tig]));
            af[i][2] = __float_as_uint(__ldg(&Mb[m * CDIM + kb + tig + 4]));
            af[i][3] = __float_as_uint(__ldg(&Mb[(m + 8) * CDIM + kb + tig + 4]));
        }
#pragma unroll
        for (int j = 0; j < 4; j++) {
            const int n = nwarp + j * 8 + gid;
            bf[j][0] = __float_as_uint(Xs[(kb + tig) * 68 + n]);
            bf[j][1] = __float_as_uint(Xs[(kb + tig + 4) * 68 + n]);
        }
#pragma unroll
        for (int i = 0; i < 2; i++)
#pragma unroll
            for (int j = 0; j < 4; j++)
                mma_tf32(acc[i][j][0], acc[i][j][1], acc[i][j][2], acc[i][j][3],
                         af[i][0], af[i][1], af[i][2], af[i][3], bf[j][0], bf[j][1]);
    }

    // epilogue: + cvec, write out
#pragma unroll
    for (int i = 0; i < 2; i++) {
        const int r0 = mbase + i * 16 + gid;
        const float cv0 = g_cv[b * CDIM + r0];
        const float cv1 = g_cv[b * CDIM + r0 + 8];
        float* op0 = out + ((size_t)b * CDIM + r0) * NTOK + n0;
        float* op1 = op0 + (size_t)8 * NTOK;
#pragma unroll
        for (int j = 0; j < 4; j++) {
            const int c0 = nwarp + j * 8 + tig * 2;
            *reinterpret_cast<float2*>(op0 + c0) =
                make_float2(acc[i][j][0] + cv0, acc[i][j][1] + cv0);
            *reinterpret_cast<float2*>(op1 + c0) =
                make_float2(acc[i][j][2] + cv1, acc[i][j][3] + cv1);
        }
    }
}

// ---------------- launch -----------------------------------------------------
extern "C" void kernel_launch(void* const* d_in, const int* in_sizes, int n_in,
                              void* d_out, int out_size) {
    (void)in_sizes; (void)n_in; (void)out_size;
    const float* x     = (const float*)d_in[0];
    const float* w_qkv = (const float*)d_in[1];
    const float* b_qkv = (const float*)d_in[2];
    const float* w_out = (const float*)d_in[3];
    const float* b_out = (const float*)d_in[4];
    float* out = (float*)d_out;

    k_gram<<<dim3(PCH, BATCH), 256>>>(x);
    k_reduceG<<<dim3(8, BATCH), 256>>>();
    k_attn<<<dim3(NHEADS, BATCH), 256>>>(w_qkv, b_qkv);
    k_mout<<<dim3(8, BATCH), 256>>>(w_out, b_out);
    k_final<<<dim3(NTOK / 64, BATCH), 256>>>(x, out);
}

// round 11
// speedup vs baseline: 1.6040x; 1.3228x over previous
#include <cuda_runtime.h>
#include <cstdint>

#define BATCH 16
#define CDIM 128
#define NTOK 16384
#define NHEADS 8
#define HDIM 16
#define PCH 16
#define KC (NTOK / PCH)   // 1024

// k_final dynamic smem: M tile (128 x 132) + X tile (128 x 68)
#define MS_STRIDE 132
#define XS_STRIDE 68
#define SMEM_FINAL_BYTES ((CDIM * MS_STRIDE + CDIM * XS_STRIDE) * 4)

// ---------------- scratch (static device globals; no allocations) ----------
__device__ float g_Gpart[BATCH * PCH * CDIM * CDIM]; // ~16.8 MB
__device__ float g_spart[BATCH * PCH * CDIM];
__device__ float g_G[BATCH * CDIM * CDIM];                 // fp32 Gram
__device__ float g_s[BATCH * CDIM];
__device__ float g_Mpart[BATCH * NHEADS * CDIM * CDIM];    // 8 MB per-head M parts
__device__ float g_u[BATCH * CDIM];
__device__ float g_M[BATCH * CDIM * CDIM];                 // tf32-rounded M
__device__ float g_cv[BATCH * CDIM];

// ---------------- helpers ---------------------------------------------------
__device__ __forceinline__ uint32_t f2tf32u(float x) {
    uint32_t r;
    asm("cvt.rna.tf32.f32 %0, %1;" : "=r"(r) : "f"(x));
    return r;
}

__device__ __forceinline__ void mma_tf32(float& d0, float& d1, float& d2, float& d3,
                                         uint32_t a0, uint32_t a1, uint32_t a2, uint32_t a3,
                                         uint32_t b0, uint32_t b1) {
    asm volatile(
        "mma.sync.aligned.m16n8k8.row.col.f32.tf32.tf32.f32 "
        "{%0,%1,%2,%3}, {%4,%5,%6,%7}, {%8,%9}, {%0,%1,%2,%3};"
        : "+f"(d0), "+f"(d1), "+f"(d2), "+f"(d3)
        : "r"(a0), "r"(a1), "r"(a2), "r"(a3), "r"(b0), "r"(b1));
}

// ---------------- kernel 1: partial Gram G = X X^T (tf32 MMA) --------------
// grid (PCH, BATCH), block 256. Double-buffered smem, fused row sums.
__global__ __launch_bounds__(256) void k_gram(const float* __restrict__ x) {
    __shared__ float Xs[2][CDIM * 36];  // 2 x (128 rows x 32 k), stride 36
    const int b = blockIdx.y, p = blockIdx.x;
    const int tid = threadIdx.x;
    const int lane = tid & 31, warp = tid >> 5;
    const int gid = lane >> 2, tig = lane & 3;
    const int mbase = (warp >> 2) * 64, nbase = (warp & 3) * 32;
    const float* xb = x + (size_t)b * CDIM * NTOK;
    const int k0base = p * KC;
    const int lc = tid >> 3;      // 0..31 row-within-pass
    const int kslot = tid & 7;

    float acc[4][4][4];
#pragma unroll
    for (int i = 0; i < 4; i++)
#pragma unroll
        for (int j = 0; j < 4; j++)
#pragma unroll
            for (int q = 0; q < 4; q++) acc[i][j][q] = 0.f;

    float rs[4] = {0.f, 0.f, 0.f, 0.f};  // fused row-sum partials

    auto load_tile = [&](int kt, int buf) {
        const int k0 = k0base + kt * 32;
#pragma unroll
        for (int pass = 0; pass < 4; pass++) {
            const int c = pass * 32 + lc;
            float4 v = *reinterpret_cast<const float4*>(
                xb + (size_t)c * NTOK + k0 + kslot * 4);
            rs[pass] += v.x + v.y + v.z + v.w;
            v.x = __uint_as_float(f2tf32u(v.x));
            v.y = __uint_as_float(f2tf32u(v.y));
            v.z = __uint_as_float(f2tf32u(v.z));
            v.w = __uint_as_float(f2tf32u(v.w));
            *reinterpret_cast<float4*>(&Xs[buf][c * 36 + kslot * 4]) = v;
        }
    };

    load_tile(0, 0);
    __syncthreads();

    for (int kt = 0; kt < KC / 32; kt++) {
        const int cur = kt & 1;
        if (kt + 1 < KC / 32) load_tile(kt + 1, cur ^ 1);
#pragma unroll
        for (int ks = 0; ks < 4; ks++) {
            const int kb = ks * 8;
            uint32_t af[4][4], bf[4][2];
#pragma unroll
            for (int i = 0; i < 4; i++) {
                const int m = mbase + i * 16 + gid;
                af[i][0] = __float_as_uint(Xs[cur][m * 36 + kb + tig]);
                af[i][1] = __float_as_uint(Xs[cur][(m + 8) * 36 + kb + tig]);
                af[i][2] = __float_as_uint(Xs[cur][m * 36 + kb + tig + 4]);
                af[i][3] = __float_as_uint(Xs[cur][(m + 8) * 36 + kb + tig + 4]);
            }
#pragma unroll
            for (int j = 0; j < 4; j++) {
                const int n = nbase + j * 8 + gid;
                bf[j][0] = __float_as_uint(Xs[cur][n * 36 + kb + tig]);
                bf[j][1] = __float_as_uint(Xs[cur][n * 36 + kb + tig + 4]);
            }
#pragma unroll
            for (int i = 0; i < 4; i++)
#pragma unroll
                for (int j = 0; j < 4; j++)
                    mma_tf32(acc[i][j][0], acc[i][j][1], acc[i][j][2], acc[i][j][3],
                             af[i][0], af[i][1], af[i][2], af[i][3], bf[j][0], bf[j][1]);
        }
        __syncthreads();
    }

    // write partial G
    float* gp = g_Gpart + ((size_t)b * PCH + p) * CDIM * CDIM;
#pragma unroll
    for (int i = 0; i < 4; i++) {
        const int r0 = mbase + i * 16 + gid;
#pragma unroll
        for (int j = 0; j < 4; j++) {
            const int c0 = nbase + j * 8 + tig * 2;
            *reinterpret_cast<float2*>(&gp[r0 * CDIM + c0]) =
                make_float2(acc[i][j][0], acc[i][j][1]);
            *reinterpret_cast<float2*>(&gp[(r0 + 8) * CDIM + c0]) =
                make_float2(acc[i][j][2], acc[i][j][3]);
        }
    }

    // row-sum reduction across the 8 kslot lanes
#pragma unroll
    for (int off = 1; off < 8; off <<= 1)
#pragma unroll
        for (int pass = 0; pass < 4; pass++)
            rs[pass] += __shfl_xor_sync(0xffffffffu, rs[pass], off);
    if (kslot == 0) {
#pragma unroll
        for (int pass = 0; pass < 4; pass++)
            g_spart[((size_t)b * PCH + p) * CDIM + pass * 32 + lc] = rs[pass];
    }
}

// ---------------- kernel 2: reduce partials (fp32, vectorized) -------------
// grid (8, BATCH), block 256
__global__ __launch_bounds__(256) void k_reduceG() {
    const int b = blockIdx.y;
    const float4* gp = reinterpret_cast<const float4*>(
        g_Gpart + (size_t)b * PCH * CDIM * CDIM);
    float4* go = reinterpret_cast<float4*>(g_G + (size_t)b * CDIM * CDIM);
    const int base = blockIdx.x * 512;  // float4 units
#pragma unroll
    for (int it = 0; it < 2; it++) {
        const int idx = base + it * 256 + threadIdx.x;
        float4 a = gp[idx];
#pragma unroll
        for (int p = 1; p < PCH; p++) {
            float4 v = gp[(size_t)p * (CDIM * CDIM / 4) + idx];
            a.x += v.x; a.y += v.y; a.z += v.z; a.w += v.w;
        }
        go[idx] = a;
    }
    if (blockIdx.x == 0 && threadIdx.x < CDIM) {
        float s = 0.f;
#pragma unroll
        for (int p = 0; p < PCH; p++)
            s += g_spart[((size_t)b * PCH + p) * CDIM + threadIdx.x];
        g_s[b * CDIM + threadIdx.x] = s;
    }
}

// ---------------- kernel 3: scores/softmax/T + per-head M part -------------
// grid (NHEADS, BATCH), block 256. Score math fp32; C_h = Wout_h@T_h via MMA.
__global__ __launch_bounds__(256) void k_attn(const float* __restrict__ w_qkv,
                                              const float* __restrict__ b_qkv,
                                              const float* __restrict__ w_out) {
    __shared__ float Rs[HDIM][CDIM];
    __shared__ float Ss[HDIM][HDIM];
    __shared__ float Ts[HDIM][136];     // tf32-rounded T_h, conflict-free stride
    __shared__ float qs[HDIM], kssum[HDIM];
    const int h = blockIdx.x, b = blockIdx.y;
    const int tid = threadIdx.x;
    const int lane = tid & 31, warp = tid >> 5;
    const int gid = lane >> 2, tig = lane & 3;
    const int d = tid >> 4, cg = tid & 15;
    const float* G = g_G + (size_t)b * CDIM * CDIM;
    const float* Wq = w_qkv + (size_t)(h * HDIM) * CDIM;
    const float* Wk = w_qkv + (size_t)(CDIM + h * HDIM) * CDIM;
    const float* Wv = w_qkv + (size_t)(2 * CDIM + h * HDIM) * CDIM;

    if (tid < 2 * HDIM) {
        const int dd = tid & 15;
        const float* W = (tid < HDIM) ? Wq : Wk;
        float acc = 0.f;
        for (int c = 0; c < CDIM; c++) acc += W[dd * CDIM + c] * g_s[b * CDIM + c];
        if (tid < HDIM) qs[dd] = acc; else kssum[dd] = acc;
    }

    // R = Wq_h @ G (16x128, fp32)
    {
        float a[8] = {0, 0, 0, 0, 0, 0, 0, 0};
#pragma unroll 4
        for (int c = 0; c < CDIM; c++) {
            const float wq = __ldg(&Wq[d * CDIM + c]);
            const float4* gp = reinterpret_cast<const float4*>(G + c * CDIM + cg * 8);
            const float4 g0 = __ldg(gp), g1 = __ldg(gp + 1);
            a[0] += wq * g0.x; a[1] += wq * g0.y; a[2] += wq * g0.z; a[3] += wq * g0.w;
            a[4] += wq * g1.x; a[5] += wq * g1.y; a[6] += wq * g1.z; a[7] += wq * g1.w;
        }
#pragma unroll
        for (int j = 0; j < 8; j++) Rs[d][cg * 8 + j] = a[j];
    }
    __syncthreads();

    // scores (fp32)
    {
        const int e = cg;
        float acc = 0.f;
#pragma unroll 4
        for (int c = 0; c < CDIM; c++) acc += Rs[d][c] * __ldg(&Wk[e * CDIM + c]);
        const float bq = b_qkv[h * HDIM + d];
        const float bk = b_qkv[CDIM + h * HDIM + e];
        acc += qs[d] * bk + bq * kssum[e] + (float)NTOK * bq * bk;
        Ss[d][e] = acc * 0.08838834764831845f;  // 1/sqrt(128)
    }
    __syncthreads();

    // softmax rows + u
    if (tid < HDIM) {
        float m = -1e30f;
#pragma unroll
        for (int e = 0; e < HDIM; e++) m = fmaxf(m, Ss[tid][e]);
        float ex[HDIM], sum = 0.f;
#pragma unroll
        for (int e = 0; e < HDIM; e++) { ex[e] = expf(Ss[tid][e] - m); sum += ex[e]; }
        const float inv = 1.f / sum;
        float u = 0.f;
#pragma unroll
        for (int e = 0; e < HDIM; e++) {
            const float pv = ex[e] * inv;
            Ss[tid][e] = pv;
            u += pv * __ldg(&b_qkv[2 * CDIM + h * HDIM + e]);
        }
        g_u[b * CDIM + h * HDIM + tid] = u;
    }
    __syncthreads();

    // T_h[d][c] = sum_e A[d][e] Wv[e][c]  -> Ts smem (tf32-rounded)
    {
        float a[8] = {0, 0, 0, 0, 0, 0, 0, 0};
#pragma unroll
        for (int e = 0; e < HDIM; e++) {
            const float av = Ss[d][e];
            const float4* vp = reinterpret_cast<const float4*>(Wv + e * CDIM + cg * 8);
            const float4 v0 = __ldg(vp), v1 = __ldg(vp + 1);
            a[0] += av * v0.x; a[1] += av * v0.y; a[2] += av * v0.z; a[3] += av * v0.w;
            a[4] += av * v1.x; a[5] += av * v1.y; a[6] += av * v1.z; a[7] += av * v1.w;
        }
#pragma unroll
        for (int j = 0; j < 8; j++)
            Ts[d][cg * 8 + j] = __uint_as_float(f2tf32u(a[j]));
    }
    __syncthreads();

    // C_h = Wout[:, h*16:+16] @ T_h  (128x128x16 tf32 MMA; warp = 16 m-rows)
    {
        float cacc[16][4];
#pragma unroll
        for (int j = 0; j < 16; j++)
#pragma unroll
            for (int q = 0; q < 4; q++) cacc[j][q] = 0.f;

        uint32_t af[2][4];
#pragma unroll
        for (int ks = 0; ks < 2; ks++) {
            const int kb = ks * 8;
            const int m = warp * 16 + gid;
            af[ks][0] = f2tf32u(__ldg(&w_out[m * CDIM + h * HDIM + kb + tig]));
            af[ks][1] = f2tf32u(__ldg(&w_out[(m + 8) * CDIM + h * HDIM + kb + tig]));
            af[ks][2] = f2tf32u(__ldg(&w_out[m * CDIM + h * HDIM + kb + tig + 4]));
            af[ks][3] = f2tf32u(__ldg(&w_out[(m + 8) * CDIM + h * HDIM + kb + tig + 4]));
        }
#pragma unroll
        for (int j = 0; j < 16; j++) {
            const int n = j * 8 + gid;
#pragma unroll
            for (int ks = 0; ks < 2; ks++) {
                const int kb = ks * 8;
                uint32_t b0 = __float_as_uint(Ts[kb + tig][n]);
                uint32_t b1 = __float_as_uint(Ts[kb + tig + 4][n]);
                mma_tf32(cacc[j][0], cacc[j][1], cacc[j][2], cacc[j][3],
                         af[ks][0], af[ks][1], af[ks][2], af[ks][3], b0, b1);
            }
        }

        float* Mp = g_Mpart + ((size_t)(b * NHEADS) + h) * CDIM * CDIM;
        const int r0 = warp * 16 + gid;
#pragma unroll
        for (int j = 0; j < 16; j++) {
            const int c0 = j * 8 + tig * 2;
            *reinterpret_cast<float2*>(&Mp[r0 * CDIM + c0]) =
                make_float2(cacc[j][0], cacc[j][1]);
            *reinterpret_cast<float2*>(&Mp[(r0 + 8) * CDIM + c0]) =
                make_float2(cacc[j][2], cacc[j][3]);
        }
    }
}

// ---------------- kernel 4: M = sum_h Mpart (tf32-rounded); cvec -----------
// grid (8, BATCH), block 256. Pure bandwidth.
__global__ __launch_bounds__(256) void k_mred(const float* __restrict__ w_out,
                                              const float* __restrict__ b_out) {
    const int b = blockIdx.y;
    const float4* mp = reinterpret_cast<const float4*>(
        g_Mpart + (size_t)(b * NHEADS) * CDIM * CDIM);
    float4* mo = reinterpret_cast<float4*>(g_M + (size_t)b * CDIM * CDIM);
    const int base = blockIdx.x * 512;
#pragma unroll
    for (int it = 0; it < 2; it++) {
        const int idx = base + it * 256 + threadIdx.x;
        float4 a = mp[idx];
#pragma unroll
        for (int h = 1; h < NHEADS; h++) {
            float4 v = mp[(size_t)h * (CDIM * CDIM / 4) + idx];
            a.x += v.x; a.y += v.y; a.z += v.z; a.w += v.w;
        }
        a.x = __uint_as_float(f2tf32u(a.x));
        a.y = __uint_as_float(f2tf32u(a.y));
        a.z = __uint_as_float(f2tf32u(a.z));
        a.w = __uint_as_float(f2tf32u(a.w));
        mo[idx] = a;
    }
    // cvec = W_out @ u + b_out (fp32)
    if (blockIdx.x == 0 && threadIdx.x < CDIM) {
        const int o = threadIdx.x;
        float a = __ldg(&b_out[o]);
#pragma unroll 8
        for (int r = 0; r < CDIM; r++)
            a += __ldg(&w_out[o * CDIM + r]) * g_u[b * CDIM + r];
        g_cv[b * CDIM + o] = a;
    }
}

// ---------------- kernel 5: final = M @ X + c (tf32 MMA, M in smem) --------
// grid (NTOK/64, BATCH), block 256, 100 KB dynamic smem -> 2 CTAs/SM.
// CTA tile 128(m) x 64(n), K=128; single __syncthreads; all frags from smem.
__global__ __launch_bounds__(256) void k_final(const float* __restrict__ x,
                                               float* __restrict__ out) {
    extern __shared__ float smem[];
    float* Ms = smem;                       // 128 x 132
    float* Xs = smem + CDIM * MS_STRIDE;    // 128 x 68
    const int b = blockIdx.y;
    const int n0 = blockIdx.x * 64;
    const int tid = threadIdx.x;
    const int lane = tid & 31, warp = tid >> 5;
    const int gid = lane >> 2, tig = lane & 3;
    const int mbase = (warp >> 1) * 32;   // 4 m-warps
    const int nwarp = (warp & 1) * 32;    // 2 n-warps
    const float* xb = x + (size_t)b * CDIM * NTOK;
    const float* Mb = g_M + (size_t)b * CDIM * CDIM;

    // stage M (128x128, pre-rounded) into smem, coalesced float4
    {
        const float4* mg = reinterpret_cast<const float4*>(Mb);
#pragma unroll
        for (int i = 0; i < 16; i++) {
            const int idx = i * 256 + tid;     // 0..4095 float4
            const int row = idx >> 5;
            const int c4 = idx & 31;
            float4 v = mg[idx];
            *reinterpret_cast<float4*>(&Ms[row * MS_STRIDE + c4 * 4]) = v;
        }
    }
    // stage X tile 128k x 64n (tf32-rounded)
    {
        const int rbase = tid >> 4;
        const int slot = tid & 15;
#pragma unroll
        for (int pass = 0; pass < 8; pass++) {
            const int r = pass * 16 + rbase;
            float4 v = *reinterpret_cast<const float4*>(
                xb + (size_t)r * NTOK + n0 + slot * 4);
            v.x = __uint_as_float(f2tf32u(v.x));
            v.y = __uint_as_float(f2tf32u(v.y));
            v.z = __uint_as_float(f2tf32u(v.z));
            v.w = __uint_as_float(f2tf32u(v.w));
            *reinterpret_cast<float4*>(&Xs[r * XS_STRIDE + slot * 4]) = v;
        }
    }
    __syncthreads();

    float acc[2][4][4];
#pragma unroll
    for (int i = 0; i < 2; i++)
#pragma unroll
        for (int j = 0; j < 4; j++)
#pragma unroll
            for (int q = 0; q < 4; q++) acc[i][j][q] = 0.f;

#pragma unroll
    for (int ks = 0; ks < 16; ks++) {
        const int kb = ks * 8;
        uint32_t af[2][4], bf[4][2];
#pragma unroll
        for (int i = 0; i < 2; i++) {
            const int m = mbase + i * 16 + gid;
            af[i][0] = __float_as_uint(Ms[m * MS_STRIDE + kb + tig]);
            af[i][1] = __float_as_uint(Ms[(m + 8) * MS_STRIDE + kb + tig]);
            af[i][2] = __float_as_uint(Ms[m * MS_STRIDE + kb + tig + 4]);
            af[i][3] = __float_as_uint(Ms[(m + 8) * MS_STRIDE + kb + tig + 4]);
        }
#pragma unroll
        for (int j = 0; j < 4; j++) {
            const int n = nwarp + j * 8 + gid;
            bf[j][0] = __float_as_uint(Xs[(kb + tig) * XS_STRIDE + n]);
            bf[j][1] = __float_as_uint(Xs[(kb + tig + 4) * XS_STRIDE + n]);
        }
#pragma unroll
        for (int i = 0; i < 2; i++)
#pragma unroll
            for (int j = 0; j < 4; j++)
                mma_tf32(acc[i][j][0], acc[i][j][1], acc[i][j][2], acc[i][j][3],
                         af[i][0], af[i][1], af[i][2], af[i][3], bf[j][0], bf[j][1]);
    }

    // epilogue: + cvec, write out
#pragma unroll
    for (int i = 0; i < 2; i++) {
        const int r0 = mbase + i * 16 + gid;
        const float cv0 = g_cv[b * CDIM + r0];
        const float cv1 = g_cv[b * CDIM + r0 + 8];
        float* op0 = out + ((size_t)b * CDIM + r0) * NTOK + n0;
        float* op1 = op0 + (size_t)8 * NTOK;
#pragma unroll
        for (int j = 0; j < 4; j++) {
            const int c0 = nwarp + j * 8 + tig * 2;
            *reinterpret_cast<float2*>(op0 + c0) =
                make_float2(acc[i][j][0] + cv0, acc[i][j][1] + cv0);
            *reinterpret_cast<float2*>(op1 + c0) =
                make_float2(acc[i][j][2] + cv1, acc[i][j][3] + cv1);
        }
    }
}

// ---------------- launch -----------------------------------------------------
extern "C" void kernel_launch(void* const* d_in, const int* in_sizes, int n_in,
                              void* d_out, int out_size) {
    (void)in_sizes; (void)n_in; (void)out_size;
    const float* x     = (const float*)d_in[0];
    const float* w_qkv = (const float*)d_in[1];
    const float* b_qkv = (const float*)d_in[2];
    const float* w_out = (const float*)d_in[3];
    const float* b_out = (const float*)d_in[4];
    float* out = (float*)d_out;

    cudaFuncSetAttribute(k_final, cudaFuncAttributeMaxDynamicSharedMemorySize,
                         SMEM_FINAL_BYTES);

    k_gram<<<dim3(PCH, BATCH), 256>>>(x);
    k_reduceG<<<dim3(8, BATCH), 256>>>();
    k_attn<<<dim3(NHEADS, BATCH), 256>>>(w_qkv, b_qkv, w_out);
    k_mred<<<dim3(8, BATCH), 256>>>(w_out, b_out);
    k_final<<<dim3(NTOK / 64, BATCH), 256, SMEM_FINAL_BYTES>>>(x, out);
}

// round 12
// speedup vs baseline: 1.6501x; 1.0288x over previous
#include <cuda_runtime.h>
#include <cstdint>

#define BATCH 16
#define CDIM 128
#define NTOK 16384
#define NHEADS 8
#define HDIM 16
#define PCH 16
#define KC (NTOK / PCH)   // 1024

// k_final dynamic smem: M tile (128 x 132) + X tile (128 x 68)
#define MS_STRIDE 132
#define XS_STRIDE 68
#define SMEM_FINAL_BYTES ((CDIM * MS_STRIDE + CDIM * XS_STRIDE) * 4)

// ---------------- scratch (static device globals; no allocations) ----------
__device__ float g_Gpart[BATCH * PCH * CDIM * CDIM]; // ~16.8 MB
__device__ float g_spart[BATCH * PCH * CDIM];
__device__ float g_G[BATCH * CDIM * CDIM];                 // fp32 Gram
__device__ float g_s[BATCH * CDIM];
__device__ float g_Mpart[BATCH * NHEADS * CDIM * CDIM];    // 8 MB per-head M parts
__device__ float g_u[BATCH * CDIM];
__device__ float g_M[BATCH * CDIM * CDIM];                 // tf32-rounded M
__device__ float g_cv[BATCH * CDIM];

// ---------------- helpers ---------------------------------------------------
__device__ __forceinline__ uint32_t f2tf32u(float x) {
    uint32_t r;
    asm("cvt.rna.tf32.f32 %0, %1;" : "=r"(r) : "f"(x));
    return r;
}

__device__ __forceinline__ void mma_tf32(float& d0, float& d1, float& d2, float& d3,
                                         uint32_t a0, uint32_t a1, uint32_t a2, uint32_t a3,
                                         uint32_t b0, uint32_t b1) {
    asm volatile(
        "mma.sync.aligned.m16n8k8.row.col.f32.tf32.tf32.f32 "
        "{%0,%1,%2,%3}, {%4,%5,%6,%7}, {%8,%9}, {%0,%1,%2,%3};"
        : "+f"(d0), "+f"(d1), "+f"(d2), "+f"(d3)
        : "r"(a0), "r"(a1), "r"(a2), "r"(a3), "r"(b0), "r"(b1));
}

// ---------------- kernel 1: partial Gram G = X X^T (tf32 MMA) --------------
// grid (PCH, BATCH), block 256. Double-buffered smem, fused row sums.
__global__ __launch_bounds__(256) void k_gram(const float* __restrict__ x) {
    __shared__ float Xs[2][CDIM * 36];  // 2 x (128 rows x 32 k), stride 36
    const int b = blockIdx.y, p = blockIdx.x;
    const int tid = threadIdx.x;
    const int lane = tid & 31, warp = tid >> 5;
    const int gid = lane >> 2, tig = lane & 3;
    const int mbase = (warp >> 2) * 64, nbase = (warp & 3) * 32;
    const float* xb = x + (size_t)b * CDIM * NTOK;
    const int k0base = p * KC;
    const int lc = tid >> 3;      // 0..31 row-within-pass
    const int kslot = tid & 7;

    float acc[4][4][4];
#pragma unroll
    for (int i = 0; i < 4; i++)
#pragma unroll
        for (int j = 0; j < 4; j++)
#pragma unroll
            for (int q = 0; q < 4; q++) acc[i][j][q] = 0.f;

    float rs[4] = {0.f, 0.f, 0.f, 0.f};  // fused row-sum partials

    auto load_tile = [&](int kt, int buf) {
        const int k0 = k0base + kt * 32;
#pragma unroll
        for (int pass = 0; pass < 4; pass++) {
            const int c = pass * 32 + lc;
            float4 v = __ldcs(reinterpret_cast<const float4*>(
                xb + (size_t)c * NTOK + k0 + kslot * 4));
            rs[pass] += v.x + v.y + v.z + v.w;
            v.x = __uint_as_float(f2tf32u(v.x));
            v.y = __uint_as_float(f2tf32u(v.y));
            v.z = __uint_as_float(f2tf32u(v.z));
            v.w = __uint_as_float(f2tf32u(v.w));
            *reinterpret_cast<float4*>(&Xs[buf][c * 36 + kslot * 4]) = v;
        }
    };

    load_tile(0, 0);
    __syncthreads();

    for (int kt = 0; kt < KC / 32; kt++) {
        const int cur = kt & 1;
        if (kt + 1 < KC / 32) load_tile(kt + 1, cur ^ 1);
#pragma unroll
        for (int ks = 0; ks < 4; ks++) {
            const int kb = ks * 8;
            uint32_t af[4][4], bf[4][2];
#pragma unroll
            for (int i = 0; i < 4; i++) {
                const int m = mbase + i * 16 + gid;
                af[i][0] = __float_as_uint(Xs[cur][m * 36 + kb + tig]);
                af[i][1] = __float_as_uint(Xs[cur][(m + 8) * 36 + kb + tig]);
                af[i][2] = __float_as_uint(Xs[cur][m * 36 + kb + tig + 4]);
                af[i][3] = __float_as_uint(Xs[cur][(m + 8) * 36 + kb + tig + 4]);
            }
#pragma unroll
            for (int j = 0; j < 4; j++) {
                const int n = nbase + j * 8 + gid;
                bf[j][0] = __float_as_uint(Xs[cur][n * 36 + kb + tig]);
                bf[j][1] = __float_as_uint(Xs[cur][n * 36 + kb + tig + 4]);
            }
#pragma unroll
            for (int i = 0; i < 4; i++)
#pragma unroll
                for (int j = 0; j < 4; j++)
                    mma_tf32(acc[i][j][0], acc[i][j][1], acc[i][j][2], acc[i][j][3],
                             af[i][0], af[i][1], af[i][2], af[i][3], bf[j][0], bf[j][1]);
        }
        __syncthreads();
    }

    // write partial G
    float* gp = g_Gpart + ((size_t)b * PCH + p) * CDIM * CDIM;
#pragma unroll
    for (int i = 0; i < 4; i++) {
        const int r0 = mbase + i * 16 + gid;
#pragma unroll
        for (int j = 0; j < 4; j++) {
            const int c0 = nbase + j * 8 + tig * 2;
            *reinterpret_cast<float2*>(&gp[r0 * CDIM + c0]) =
                make_float2(acc[i][j][0], acc[i][j][1]);
            *reinterpret_cast<float2*>(&gp[(r0 + 8) * CDIM + c0]) =
                make_float2(acc[i][j][2], acc[i][j][3]);
        }
    }

    // row-sum reduction across the 8 kslot lanes
#pragma unroll
    for (int off = 1; off < 8; off <<= 1)
#pragma unroll
        for (int pass = 0; pass < 4; pass++)
            rs[pass] += __shfl_xor_sync(0xffffffffu, rs[pass], off);
    if (kslot == 0) {
#pragma unroll
        for (int pass = 0; pass < 4; pass++)
            g_spart[((size_t)b * PCH + p) * CDIM + pass * 32 + lc] = rs[pass];
    }
}

// ---------------- kernel 2: reduce partials (fp32, wide grid) --------------
// grid (16, BATCH), block 256. One float4 per thread, 16 loads in flight.
__global__ __launch_bounds__(256) void k_reduceG() {
    const int b = blockIdx.y;
    const float4* gp = reinterpret_cast<const float4*>(
        g_Gpart + (size_t)b * PCH * CDIM * CDIM);
    float4* go = reinterpret_cast<float4*>(g_G + (size_t)b * CDIM * CDIM);
    const int idx = blockIdx.x * 256 + threadIdx.x;   // 0..4095 float4
    float4 a = gp[idx];
#pragma unroll
    for (int p = 1; p < PCH; p++) {
        float4 v = gp[(size_t)p * (CDIM * CDIM / 4) + idx];
        a.x += v.x; a.y += v.y; a.z += v.z; a.w += v.w;
    }
    go[idx] = a;
    if (blockIdx.x == 0 && threadIdx.x < CDIM) {
        float s = 0.f;
#pragma unroll
        for (int p = 0; p < PCH; p++)
            s += g_spart[((size_t)b * PCH + p) * CDIM + threadIdx.x];
        g_s[b * CDIM + threadIdx.x] = s;
    }
}

// ---------------- kernel 3: scores/softmax/T + per-head M part -------------
// grid (NHEADS, BATCH), block 256. Score math fp32; C_h = Wout_h@T_h via MMA.
__global__ __launch_bounds__(256) void k_attn(const float* __restrict__ w_qkv,
                                              const float* __restrict__ b_qkv,
                                              const float* __restrict__ w_out) {
    __shared__ float Rs[HDIM][CDIM];
    __shared__ float Ss[HDIM][HDIM];
    __shared__ float Ts[HDIM][136];     // tf32-rounded T_h, conflict-free stride
    __shared__ float qs[HDIM], kssum[HDIM];
    const int h = blockIdx.x, b = blockIdx.y;
    const int tid = threadIdx.x;
    const int lane = tid & 31, warp = tid >> 5;
    const int gid = lane >> 2, tig = lane & 3;
    const int d = tid >> 4, cg = tid & 15;
    const float* G = g_G + (size_t)b * CDIM * CDIM;
    const float* Wq = w_qkv + (size_t)(h * HDIM) * CDIM;
    const float* Wk = w_qkv + (size_t)(CDIM + h * HDIM) * CDIM;
    const float* Wv = w_qkv + (size_t)(2 * CDIM + h * HDIM) * CDIM;

    if (tid < 2 * HDIM) {
        const int dd = tid & 15;
        const float* W = (tid < HDIM) ? Wq : Wk;
        float acc = 0.f;
        for (int c = 0; c < CDIM; c++) acc += W[dd * CDIM + c] * g_s[b * CDIM + c];
        if (tid < HDIM) qs[dd] = acc; else kssum[dd] = acc;
    }

    // R = Wq_h @ G (16x128, fp32)
    {
        float a[8] = {0, 0, 0, 0, 0, 0, 0, 0};
#pragma unroll 4
        for (int c = 0; c < CDIM; c++) {
            const float wq = __ldg(&Wq[d * CDIM + c]);
            const float4* gp = reinterpret_cast<const float4*>(G + c * CDIM + cg * 8);
            const float4 g0 = __ldg(gp), g1 = __ldg(gp + 1);
            a[0] += wq * g0.x; a[1] += wq * g0.y; a[2] += wq * g0.z; a[3] += wq * g0.w;
            a[4] += wq * g1.x; a[5] += wq * g1.y; a[6] += wq * g1.z; a[7] += wq * g1.w;
        }
#pragma unroll
        for (int j = 0; j < 8; j++) Rs[d][cg * 8 + j] = a[j];
    }
    __syncthreads();

    // scores (fp32)
    {
        const int e = cg;
        float acc = 0.f;
#pragma unroll 4
        for (int c = 0; c < CDIM; c++) acc += Rs[d][c] * __ldg(&Wk[e * CDIM + c]);
        const float bq = b_qkv[h * HDIM + d];
        const float bk = b_qkv[CDIM + h * HDIM + e];
        acc += qs[d] * bk + bq * kssum[e] + (float)NTOK * bq * bk;
        Ss[d][e] = acc * 0.08838834764831845f;  // 1/sqrt(128)
    }
    __syncthreads();

    // softmax rows + u
    if (tid < HDIM) {
        float m = -1e30f;
#pragma unroll
        for (int e = 0; e < HDIM; e++) m = fmaxf(m, Ss[tid][e]);
        float ex[HDIM], sum = 0.f;
#pragma unroll
        for (int e = 0; e < HDIM; e++) { ex[e] = expf(Ss[tid][e] - m); sum += ex[e]; }
        const float inv = 1.f / sum;
        float u = 0.f;
#pragma unroll
        for (int e = 0; e < HDIM; e++) {
            const float pv = ex[e] * inv;
            Ss[tid][e] = pv;
            u += pv * __ldg(&b_qkv[2 * CDIM + h * HDIM + e]);
        }
        g_u[b * CDIM + h * HDIM + tid] = u;
    }
    __syncthreads();

    // T_h[d][c] = sum_e A[d][e] Wv[e][c]  -> Ts smem (tf32-rounded)
    {
        float a[8] = {0, 0, 0, 0, 0, 0, 0, 0};
#pragma unroll
        for (int e = 0; e < HDIM; e++) {
            const float av = Ss[d][e];
            const float4* vp = reinterpret_cast<const float4*>(Wv + e * CDIM + cg * 8);
            const float4 v0 = __ldg(vp), v1 = __ldg(vp + 1);
            a[0] += av * v0.x; a[1] += av * v0.y; a[2] += av * v0.z; a[3] += av * v0.w;
            a[4] += av * v1.x; a[5] += av * v1.y; a[6] += av * v1.z; a[7] += av * v1.w;
        }
#pragma unroll
        for (int j = 0; j < 8; j++)
            Ts[d][cg * 8 + j] = __uint_as_float(f2tf32u(a[j]));
    }
    __syncthreads();

    // C_h = Wout[:, h*16:+16] @ T_h  (128x128x16 tf32 MMA; warp = 16 m-rows)
    {
        float cacc[16][4];
#pragma unroll
        for (int j = 0; j < 16; j++)
#pragma unroll
            for (int q = 0; q < 4; q++) cacc[j][q] = 0.f;

        uint32_t af[2][4];
#pragma unroll
        for (int ks = 0; ks < 2; ks++) {
            const int kb = ks * 8;
            const int m = warp * 16 + gid;
            af[ks][0] = f2tf32u(__ldg(&w_out[m * CDIM + h * HDIM + kb + tig]));
            af[ks][1] = f2tf32u(__ldg(&w_out[(m + 8) * CDIM + h * HDIM + kb + tig]));
            af[ks][2] = f2tf32u(__ldg(&w_out[m * CDIM + h * HDIM + kb + tig + 4]));
            af[ks][3] = f2tf32u(__ldg(&w_out[(m + 8) * CDIM + h * HDIM + kb + tig + 4]));
        }
#pragma unroll
        for (int j = 0; j < 16; j++) {
            const int n = j * 8 + gid;
#pragma unroll
            for (int ks = 0; ks < 2; ks++) {
                const int kb = ks * 8;
                uint32_t b0 = __float_as_uint(Ts[kb + tig][n]);
                uint32_t b1 = __float_as_uint(Ts[kb + tig + 4][n]);
                mma_tf32(cacc[j][0], cacc[j][1], cacc[j][2], cacc[j][3],
                         af[ks][0], af[ks][1], af[ks][2], af[ks][3], b0, b1);
            }
        }

        float* Mp = g_Mpart + ((size_t)(b * NHEADS) + h) * CDIM * CDIM;
        const int r0 = warp * 16 + gid;
#pragma unroll
        for (int j = 0; j < 16; j++) {
            const int c0 = j * 8 + tig * 2;
            *reinterpret_cast<float2*>(&Mp[r0 * CDIM + c0]) =
                make_float2(cacc[j][0], cacc[j][1]);
            *reinterpret_cast<float2*>(&Mp[(r0 + 8) * CDIM + c0]) =
                make_float2(cacc[j][2], cacc[j][3]);
        }
    }
}

// ---------------- kernel 4: M = sum_h Mpart (tf32-rounded); cvec -----------
// grid (16, BATCH), block 256. One float4 per thread, 8 loads in flight.
__global__ __launch_bounds__(256) void k_mred(const float* __restrict__ w_out,
                                              const float* __restrict__ b_out) {
    const int b = blockIdx.y;
    const float4* mp = reinterpret_cast<const float4*>(
        g_Mpart + (size_t)(b * NHEADS) * CDIM * CDIM);
    float4* mo = reinterpret_cast<float4*>(g_M + (size_t)b * CDIM * CDIM);
    const int idx = blockIdx.x * 256 + threadIdx.x;   // 0..4095 float4
    float4 a = mp[idx];
#pragma unroll
    for (int h = 1; h < NHEADS; h++) {
        float4 v = mp[(size_t)h * (CDIM * CDIM / 4) + idx];
        a.x += v.x; a.y += v.y; a.z += v.z; a.w += v.w;
    }
    a.x = __uint_as_float(f2tf32u(a.x));
    a.y = __uint_as_float(f2tf32u(a.y));
    a.z = __uint_as_float(f2tf32u(a.z));
    a.w = __uint_as_float(f2tf32u(a.w));
    mo[idx] = a;

    // cvec = W_out @ u + b_out (fp32)
    if (blockIdx.x == 0 && threadIdx.x < CDIM) {
        const int o = threadIdx.x;
        float a2 = __ldg(&b_out[o]);
#pragma unroll 8
        for (int r = 0; r < CDIM; r++)
            a2 += __ldg(&w_out[o * CDIM + r]) * g_u[b * CDIM + r];
        g_cv[b * CDIM + o] = a2;
    }
}

// ---------------- kernel 5: final = M @ X + c (tf32 MMA, M in smem) --------
// grid (NTOK/64, BATCH), block 256, 100 KB dynamic smem -> 2 CTAs/SM.
// CTA tile 128(m) x 64(n), K=128; single __syncthreads; all frags from smem.
__global__ __launch_bounds__(256) void k_final(const float* __restrict__ x,
                                               float* __restrict__ out) {
    extern __shared__ float smem[];
    float* Ms = smem;                       // 128 x 132
    float* Xs = smem + CDIM * MS_STRIDE;    // 128 x 68
    const int b = blockIdx.y;
    const int n0 = blockIdx.x * 64;
    const int tid = threadIdx.x;
    const int lane = tid & 31, warp = tid >> 5;
    const int gid = lane >> 2, tig = lane & 3;
    const int mbase = (warp >> 1) * 32;   // 4 m-warps
    const int nwarp = (warp & 1) * 32;    // 2 n-warps
    const float* xb = x + (size_t)b * CDIM * NTOK;
    const float* Mb = g_M + (size_t)b * CDIM * CDIM;

    // stage M (128x128, pre-rounded) into smem, coalesced float4 (L2-hot)
    {
        const float4* mg = reinterpret_cast<const float4*>(Mb);
#pragma unroll
        for (int i = 0; i < 16; i++) {
            const int idx = i * 256 + tid;     // 0..4095 float4
            const int row = idx >> 5;
            const int c4 = idx & 31;
            float4 v = __ldg(&mg[idx]);
            *reinterpret_cast<float4*>(&Ms[row * MS_STRIDE + c4 * 4]) = v;
        }
    }
    // stage X tile 128k x 64n (tf32-rounded), streaming (no reuse)
    {
        const int rbase = tid >> 4;
        const int slot = tid & 15;
#pragma unroll
        for (int pass = 0; pass < 8; pass++) {
            const int r = pass * 16 + rbase;
            float4 v = __ldcs(reinterpret_cast<const float4*>(
                xb + (size_t)r * NTOK + n0 + slot * 4));
            v.x = __uint_as_float(f2tf32u(v.x));
            v.y = __uint_as_float(f2tf32u(v.y));
            v.z = __uint_as_float(f2tf32u(v.z));
            v.w = __uint_as_float(f2tf32u(v.w));
            *reinterpret_cast<float4*>(&Xs[r * XS_STRIDE + slot * 4]) = v;
        }
    }
    __syncthreads();

    float acc[2][4][4];
#pragma unroll
    for (int i = 0; i < 2; i++)
#pragma unroll
        for (int j = 0; j < 4; j++)
#pragma unroll
            for (int q = 0; q < 4; q++) acc[i][j][q] = 0.f;

#pragma unroll
    for (int ks = 0; ks < 16; ks++) {
        const int kb = ks * 8;
        uint32_t af[2][4], bf[4][2];
#pragma unroll
        for (int i = 0; i < 2; i++) {
            const int m = mbase + i * 16 + gid;
            af[i][0] = __float_as_uint(Ms[m * MS_STRIDE + kb + tig]);
            af[i][1] = __float_as_uint(Ms[(m + 8) * MS_STRIDE + kb + tig]);
            af[i][2] = __float_as_uint(Ms[m * MS_STRIDE + kb + tig + 4]);
            af[i][3] = __float_as_uint(Ms[(m + 8) * MS_STRIDE + kb + tig + 4]);
        }
#pragma unroll
        for (int j = 0; j < 4; j++) {
            const int n = nwarp + j * 8 + gid;
            bf[j][0] = __float_as_uint(Xs[(kb + tig) * XS_STRIDE + n]);
            bf[j][1] = __float_as_uint(Xs[(kb + tig + 4) * XS_STRIDE + n]);
        }
#pragma unroll
        for (int i = 0; i < 2; i++)
#pragma unroll
            for (int j = 0; j < 4; j++)
                mma_tf32(acc[i][j][0], acc[i][j][1], acc[i][j][2], acc[i][j][3],
                         af[i][0], af[i][1], af[i][2], af[i][3], bf[j][0], bf[j][1]);
    }

    // epilogue: + cvec, streaming stores
#pragma unroll
    for (int i = 0; i < 2; i++) {
        const int r0 = mbase + i * 16 + gid;
        const float cv0 = g_cv[b * CDIM + r0];
        const float cv1 = g_cv[b * CDIM + r0 + 8];
        float* op0 = out + ((size_t)b * CDIM + r0) * NTOK + n0;
        float* op1 = op0 + (size_t)8 * NTOK;
#pragma unroll
        for (int j = 0; j < 4; j++) {
            const int c0 = nwarp + j * 8 + tig * 2;
            __stcs(reinterpret_cast<float2*>(op0 + c0),
                   make_float2(acc[i][j][0] + cv0, acc[i][j][1] + cv0));
            __stcs(reinterpret_cast<float2*>(op1 + c0),
                   make_float2(acc[i][j][2] + cv1, acc[i][j][3] + cv1));
        }
    }
}

// ---------------- launch -----------------------------------------------------
extern "C" void kernel_launch(void* const* d_in, const int* in_sizes, int n_in,
                              void* d_out, int out_size) {
    (void)in_sizes; (void)n_in; (void)out_size;
    const float* x     = (const float*)d_in[0];
    const float* w_qkv = (const float*)d_in[1];
    const float* b_qkv = (const float*)d_in[2];
    const float* w_out = (const float*)d_in[3];
    const float* b_out = (const float*)d_in[4];
    float* out = (float*)d_out;

    cudaFuncSetAttribute(k_final, cudaFuncAttributeMaxDynamicSharedMemorySize,
                         SMEM_FINAL_BYTES);

    k_gram<<<dim3(PCH, BATCH), 256>>>(x);
    k_reduceG<<<dim3(16, BATCH), 256>>>();
    k_attn<<<dim3(NHEADS, BATCH), 256>>>(w_qkv, b_qkv, w_out);
    k_mred<<<dim3(16, BATCH), 256>>>(w_out, b_out);
    k_final<<<dim3(NTOK / 64, BATCH), 256, SMEM_FINAL_BYTES>>>(x, out);
}

// round 13
// speedup vs baseline: 1.7012x; 1.0310x over previous
#include <cuda_runtime.h>
#include <cstdint>

#define BATCH 16
#define CDIM 128
#define NTOK 16384
#define NHEADS 8
#define HDIM 16
#define PCH 16
#define KC (NTOK / PCH)   // 1024

// k_final v3: M tile (128 x 132) + double-buffered X (2 x 128 x 68)
#define MS_STRIDE 132
#define XS_STRIDE 68
#define FIN_NCHUNK 4
#define FIN_NSPAN (64 * FIN_NCHUNK)   // 256 columns per CTA
#define SMEM_FINAL_BYTES ((CDIM * MS_STRIDE + 2 * CDIM * XS_STRIDE) * 4)

// ---------------- scratch (static device globals; no allocations) ----------
__device__ float g_Gpart[BATCH * PCH * CDIM * CDIM]; // ~16.8 MB
__device__ float g_spart[BATCH * PCH * CDIM];
__device__ float g_G[BATCH * CDIM * CDIM];                 // fp32 Gram
__device__ float g_s[BATCH * CDIM];
__device__ float g_Mpart[BATCH * NHEADS * CDIM * CDIM];    // 8 MB per-head M parts
__device__ float g_u[BATCH * CDIM];
__device__ float g_M[BATCH * CDIM * CDIM];                 // tf32-rounded M
__device__ float g_cv[BATCH * CDIM];

// ---------------- helpers ---------------------------------------------------
__device__ __forceinline__ uint32_t f2tf32u(float x) {
    uint32_t r;
    asm("cvt.rna.tf32.f32 %0, %1;" : "=r"(r) : "f"(x));
    return r;
}

__device__ __forceinline__ void mma_tf32(float& d0, float& d1, float& d2, float& d3,
                                         uint32_t a0, uint32_t a1, uint32_t a2, uint32_t a3,
                                         uint32_t b0, uint32_t b1) {
    asm volatile(
        "mma.sync.aligned.m16n8k8.row.col.f32.tf32.tf32.f32 "
        "{%0,%1,%2,%3}, {%4,%5,%6,%7}, {%8,%9}, {%0,%1,%2,%3};"
        : "+f"(d0), "+f"(d1), "+f"(d2), "+f"(d3)
        : "r"(a0), "r"(a1), "r"(a2), "r"(a3), "r"(b0), "r"(b1));
}

__device__ __forceinline__ void cp_async16(uint32_t saddr, const void* gptr) {
    asm volatile("cp.async.cg.shared.global [%0], [%1], 16;"
                 :: "r"(saddr), "l"(gptr));
}
#define CP_COMMIT() asm volatile("cp.async.commit_group;")
#define CP_WAIT_ALL() asm volatile("cp.async.wait_group 0;")

// ---------------- kernel 1: partial Gram G = X X^T (tf32 MMA) --------------
// grid (PCH, BATCH), block 256. Double-buffered smem, fused row sums.
__global__ __launch_bounds__(256) void k_gram(const float* __restrict__ x) {
    __shared__ float Xs[2][CDIM * 36];  // 2 x (128 rows x 32 k), stride 36
    const int b = blockIdx.y, p = blockIdx.x;
    const int tid = threadIdx.x;
    const int lane = tid & 31, warp = tid >> 5;
    const int gid = lane >> 2, tig = lane & 3;
    const int mbase = (warp >> 2) * 64, nbase = (warp & 3) * 32;
    const float* xb = x + (size_t)b * CDIM * NTOK;
    const int k0base = p * KC;
    const int lc = tid >> 3;      // 0..31 row-within-pass
    const int kslot = tid & 7;

    float acc[4][4][4];
#pragma unroll
    for (int i = 0; i < 4; i++)
#pragma unroll
        for (int j = 0; j < 4; j++)
#pragma unroll
            for (int q = 0; q < 4; q++) acc[i][j][q] = 0.f;

    float rs[4] = {0.f, 0.f, 0.f, 0.f};  // fused row-sum partials

    auto load_tile = [&](int kt, int buf) {
        const int k0 = k0base + kt * 32;
#pragma unroll
        for (int pass = 0; pass < 4; pass++) {
            const int c = pass * 32 + lc;
            float4 v = __ldcs(reinterpret_cast<const float4*>(
                xb + (size_t)c * NTOK + k0 + kslot * 4));
            rs[pass] += v.x + v.y + v.z + v.w;
            v.x = __uint_as_float(f2tf32u(v.x));
            v.y = __uint_as_float(f2tf32u(v.y));
            v.z = __uint_as_float(f2tf32u(v.z));
            v.w = __uint_as_float(f2tf32u(v.w));
            *reinterpret_cast<float4*>(&Xs[buf][c * 36 + kslot * 4]) = v;
        }
    };

    load_tile(0, 0);
    __syncthreads();

    for (int kt = 0; kt < KC / 32; kt++) {
        const int cur = kt & 1;
        if (kt + 1 < KC / 32) load_tile(kt + 1, cur ^ 1);
#pragma unroll
        for (int ks = 0; ks < 4; ks++) {
            const int kb = ks * 8;
            uint32_t af[4][4], bf[4][2];
#pragma unroll
            for (int i = 0; i < 4; i++) {
                const int m = mbase + i * 16 + gid;
                af[i][0] = __float_as_uint(Xs[cur][m * 36 + kb + tig]);
                af[i][1] = __float_as_uint(Xs[cur][(m + 8) * 36 + kb + tig]);
                af[i][2] = __float_as_uint(Xs[cur][m * 36 + kb + tig + 4]);
                af[i][3] = __float_as_uint(Xs[cur][(m + 8) * 36 + kb + tig + 4]);
            }
#pragma unroll
            for (int j = 0; j < 4; j++) {
                const int n = nbase + j * 8 + gid;
                bf[j][0] = __float_as_uint(Xs[cur][n * 36 + kb + tig]);
                bf[j][1] = __float_as_uint(Xs[cur][n * 36 + kb + tig + 4]);
            }
#pragma unroll
            for (int i = 0; i < 4; i++)
#pragma unroll
                for (int j = 0; j < 4; j++)
                    mma_tf32(acc[i][j][0], acc[i][j][1], acc[i][j][2], acc[i][j][3],
                             af[i][0], af[i][1], af[i][2], af[i][3], bf[j][0], bf[j][1]);
        }
        __syncthreads();
    }

    // write partial G
    float* gp = g_Gpart + ((size_t)b * PCH + p) * CDIM * CDIM;
#pragma unroll
    for (int i = 0; i < 4; i++) {
        const int r0 = mbase + i * 16 + gid;
#pragma unroll
        for (int j = 0; j < 4; j++) {
            const int c0 = nbase + j * 8 + tig * 2;
            *reinterpret_cast<float2*>(&gp[r0 * CDIM + c0]) =
                make_float2(acc[i][j][0], acc[i][j][1]);
            *reinterpret_cast<float2*>(&gp[(r0 + 8) * CDIM + c0]) =
                make_float2(acc[i][j][2], acc[i][j][3]);
        }
    }

    // row-sum reduction across the 8 kslot lanes
#pragma unroll
    for (int off = 1; off < 8; off <<= 1)
#pragma unroll
        for (int pass = 0; pass < 4; pass++)
            rs[pass] += __shfl_xor_sync(0xffffffffu, rs[pass], off);
    if (kslot == 0) {
#pragma unroll
        for (int pass = 0; pass < 4; pass++)
            g_spart[((size_t)b * PCH + p) * CDIM + pass * 32 + lc] = rs[pass];
    }
}

// ---------------- kernel 2: reduce partials (fp32, wide grid) --------------
// grid (16, BATCH), block 256. One float4 per thread, 16 loads in flight.
__global__ __launch_bounds__(256) void k_reduceG() {
    const int b = blockIdx.y;
    const float4* gp = reinterpret_cast<const float4*>(
        g_Gpart + (size_t)b * PCH * CDIM * CDIM);
    float4* go = reinterpret_cast<float4*>(g_G + (size_t)b * CDIM * CDIM);
    const int idx = blockIdx.x * 256 + threadIdx.x;   // 0..4095 float4
    float4 a = gp[idx];
#pragma unroll
    for (int p = 1; p < PCH; p++) {
        float4 v = gp[(size_t)p * (CDIM * CDIM / 4) + idx];
        a.x += v.x; a.y += v.y; a.z += v.z; a.w += v.w;
    }
    go[idx] = a;
    if (blockIdx.x == 0 && threadIdx.x < CDIM) {
        float s = 0.f;
#pragma unroll
        for (int p = 0; p < PCH; p++)
            s += g_spart[((size_t)b * PCH + p) * CDIM + threadIdx.x];
        g_s[b * CDIM + threadIdx.x] = s;
    }
}

// ---------------- kernel 3: scores/softmax/T + per-head M part -------------
// grid (NHEADS, BATCH), block 256. Score math fp32; C_h = Wout_h@T_h via MMA.
__global__ __launch_bounds__(256) void k_attn(const float* __restrict__ w_qkv,
                                              const float* __restrict__ b_qkv,
                                              const float* __restrict__ w_out) {
    __shared__ float Rs[HDIM][CDIM];
    __shared__ float Ss[HDIM][HDIM];
    __shared__ float Ts[HDIM][136];     // tf32-rounded T_h, conflict-free stride
    __shared__ float qs[HDIM], kssum[HDIM];
    const int h = blockIdx.x, b = blockIdx.y;
    const int tid = threadIdx.x;
    const int lane = tid & 31, warp = tid >> 5;
    const int gid = lane >> 2, tig = lane & 3;
    const int d = tid >> 4, cg = tid & 15;
    const float* G = g_G + (size_t)b * CDIM * CDIM;
    const float* Wq = w_qkv + (size_t)(h * HDIM) * CDIM;
    const float* Wk = w_qkv + (size_t)(CDIM + h * HDIM) * CDIM;
    const float* Wv = w_qkv + (size_t)(2 * CDIM + h * HDIM) * CDIM;

    if (tid < 2 * HDIM) {
        const int dd = tid & 15;
        const float* W = (tid < HDIM) ? Wq : Wk;
        float acc = 0.f;
        for (int c = 0; c < CDIM; c++) acc += W[dd * CDIM + c] * g_s[b * CDIM + c];
        if (tid < HDIM) qs[dd] = acc; else kssum[dd] = acc;
    }

    // R = Wq_h @ G (16x128, fp32)
    {
        float a[8] = {0, 0, 0, 0, 0, 0, 0, 0};
#pragma unroll 4
        for (int c = 0; c < CDIM; c++) {
            const float wq = __ldg(&Wq[d * CDIM + c]);
            const float4* gp = reinterpret_cast<const float4*>(G + c * CDIM + cg * 8);
            const float4 g0 = __ldg(gp), g1 = __ldg(gp + 1);
            a[0] += wq * g0.x; a[1] += wq * g0.y; a[2] += wq * g0.z; a[3] += wq * g0.w;
            a[4] += wq * g1.x; a[5] += wq * g1.y; a[6] += wq * g1.z; a[7] += wq * g1.w;
        }
#pragma unroll
        for (int j = 0; j < 8; j++) Rs[d][cg * 8 + j] = a[j];
    }
    __syncthreads();

    // scores (fp32)
    {
        const int e = cg;
        float acc = 0.f;
#pragma unroll 4
        for (int c = 0; c < CDIM; c++) acc += Rs[d][c] * __ldg(&Wk[e * CDIM + c]);
        const float bq = b_qkv[h * HDIM + d];
        const float bk = b_qkv[CDIM + h * HDIM + e];
        acc += qs[d] * bk + bq * kssum[e] + (float)NTOK * bq * bk;
        Ss[d][e] = acc * 0.08838834764831845f;  // 1/sqrt(128)
    }
    __syncthreads();

    // softmax rows + u
    if (tid < HDIM) {
        float m = -1e30f;
#pragma unroll
        for (int e = 0; e < HDIM; e++) m = fmaxf(m, Ss[tid][e]);
        float ex[HDIM], sum = 0.f;
#pragma unroll
        for (int e = 0; e < HDIM; e++) { ex[e] = expf(Ss[tid][e] - m); sum += ex[e]; }
        const float inv = 1.f / sum;
        float u = 0.f;
#pragma unroll
        for (int e = 0; e < HDIM; e++) {
            const float pv = ex[e] * inv;
            Ss[tid][e] = pv;
            u += pv * __ldg(&b_qkv[2 * CDIM + h * HDIM + e]);
        }
        g_u[b * CDIM + h * HDIM + tid] = u;
    }
    __syncthreads();

    // T_h[d][c] = sum_e A[d][e] Wv[e][c]  -> Ts smem (tf32-rounded)
    {
        float a[8] = {0, 0, 0, 0, 0, 0, 0, 0};
#pragma unroll
        for (int e = 0; e < HDIM; e++) {
            const float av = Ss[d][e];
            const float4* vp = reinterpret_cast<const float4*>(Wv + e * CDIM + cg * 8);
            const float4 v0 = __ldg(vp), v1 = __ldg(vp + 1);
            a[0] += av * v0.x; a[1] += av * v0.y; a[2] += av * v0.z; a[3] += av * v0.w;
            a[4] += av * v1.x; a[5] += av * v1.y; a[6] += av * v1.z; a[7] += av * v1.w;
        }
#pragma unroll
        for (int j = 0; j < 8; j++)
            Ts[d][cg * 8 + j] = __uint_as_float(f2tf32u(a[j]));
    }
    __syncthreads();

    // C_h = Wout[:, h*16:+16] @ T_h  (128x128x16 tf32 MMA; warp = 16 m-rows)
    {
        float cacc[16][4];
#pragma unroll
        for (int j = 0; j < 16; j++)
#pragma unroll
            for (int q = 0; q < 4; q++) cacc[j][q] = 0.f;

        uint32_t af[2][4];
#pragma unroll
        for (int ks = 0; ks < 2; ks++) {
            const int kb = ks * 8;
            const int m = warp * 16 + gid;
            af[ks][0] = f2tf32u(__ldg(&w_out[m * CDIM + h * HDIM + kb + tig]));
            af[ks][1] = f2tf32u(__ldg(&w_out[(m + 8) * CDIM + h * HDIM + kb + tig]));
            af[ks][2] = f2tf32u(__ldg(&w_out[m * CDIM + h * HDIM + kb + tig + 4]));
            af[ks][3] = f2tf32u(__ldg(&w_out[(m + 8) * CDIM + h * HDIM + kb + tig + 4]));
        }
#pragma unroll
        for (int j = 0; j < 16; j++) {
            const int n = j * 8 + gid;
#pragma unroll
            for (int ks = 0; ks < 2; ks++) {
                const int kb = ks * 8;
                uint32_t b0 = __float_as_uint(Ts[kb + tig][n]);
                uint32_t b1 = __float_as_uint(Ts[kb + tig + 4][n]);
                mma_tf32(cacc[j][0], cacc[j][1], cacc[j][2], cacc[j][3],
                         af[ks][0], af[ks][1], af[ks][2], af[ks][3], b0, b1);
            }
        }

        float* Mp = g_Mpart + ((size_t)(b * NHEADS) + h) * CDIM * CDIM;
        const int r0 = warp * 16 + gid;
#pragma unroll
        for (int j = 0; j < 16; j++) {
            const int c0 = j * 8 + tig * 2;
            *reinterpret_cast<float2*>(&Mp[r0 * CDIM + c0]) =
                make_float2(cacc[j][0], cacc[j][1]);
            *reinterpret_cast<float2*>(&Mp[(r0 + 8) * CDIM + c0]) =
                make_float2(cacc[j][2], cacc[j][3]);
        }
    }
}

// ---------------- kernel 4: M = sum_h Mpart (tf32-rounded); cvec -----------
// grid (16, BATCH), block 256.
__global__ __launch_bounds__(256) void k_mred(const float* __restrict__ w_out,
                                              const float* __restrict__ b_out) {
    const int b = blockIdx.y;
    const float4* mp = reinterpret_cast<const float4*>(
        g_Mpart + (size_t)(b * NHEADS) * CDIM * CDIM);
    float4* mo = reinterpret_cast<float4*>(g_M + (size_t)b * CDIM * CDIM);
    const int idx = blockIdx.x * 256 + threadIdx.x;   // 0..4095 float4
    float4 a = mp[idx];
#pragma unroll
    for (int h = 1; h < NHEADS; h++) {
        float4 v = mp[(size_t)h * (CDIM * CDIM / 4) + idx];
        a.x += v.x; a.y += v.y; a.z += v.z; a.w += v.w;
    }
    a.x = __uint_as_float(f2tf32u(a.x));
    a.y = __uint_as_float(f2tf32u(a.y));
    a.z = __uint_as_float(f2tf32u(a.z));
    a.w = __uint_as_float(f2tf32u(a.w));
    mo[idx] = a;

    // cvec = W_out @ u + b_out (fp32)
    if (blockIdx.x == 0 && threadIdx.x < CDIM) {
        const int o = threadIdx.x;
        float a2 = __ldg(&b_out[o]);
#pragma unroll 8
        for (int r = 0; r < CDIM; r++)
            a2 += __ldg(&w_out[o * CDIM + r]) * g_u[b * CDIM + r];
        g_cv[b * CDIM + o] = a2;
    }
}

// ---------------- kernel 5 (v3): final = M @ X + c ------------------------
// grid (NTOK/256, BATCH), block 256, 137 KB smem -> 1 CTA/SM.
// M staged ONCE per CTA (cp.async). X in 4 chunks of 64 cols, double-buffered
// via cp.async prefetch; tf32 rounding of X at fragment load.
__global__ __launch_bounds__(256) void k_final(const float* __restrict__ x,
                                               float* __restrict__ out) {
    extern __shared__ float smem[];
    float* Ms = smem;                         // 128 x 132
    float* Xs0 = smem + CDIM * MS_STRIDE;     // 128 x 68
    float* Xs1 = Xs0 + CDIM * XS_STRIDE;      // 128 x 68
    const int b = blockIdx.y;
    const int n0 = blockIdx.x * FIN_NSPAN;
    const int tid = threadIdx.x;
    const int lane = tid & 31, warp = tid >> 5;
    const int gid = lane >> 2, tig = lane & 3;
    const int mbase = (warp >> 1) * 32;   // 4 m-warps
    const int nwarp = (warp & 1) * 32;    // 2 n-warps
    const float* xb = x + (size_t)b * CDIM * NTOK;
    const float* Mb = g_M + (size_t)b * CDIM * CDIM;

    const uint32_t ms_s = (uint32_t)__cvta_generic_to_shared(Ms);
    const uint32_t xs_s[2] = {(uint32_t)__cvta_generic_to_shared(Xs0),
                              (uint32_t)__cvta_generic_to_shared(Xs1)};

    // issue M staging (16 x 16B per thread)
    {
#pragma unroll
        for (int i = 0; i < 16; i++) {
            const int idx = i * 256 + tid;     // 0..4095 float4
            const int row = idx >> 5;
            const int c4 = idx & 31;
            cp_async16(ms_s + (row * MS_STRIDE + c4 * 4) * 4,
                       reinterpret_cast<const float4*>(Mb) + idx);
        }
    }
    // issue X chunk 0 (8 x 16B per thread)
    const int rbase = tid >> 4;
    const int slot = tid & 15;
    auto stage_x = [&](int nc, int buf) {
        const int nco = n0 + nc * 64;
#pragma unroll
        for (int pass = 0; pass < 8; pass++) {
            const int r = pass * 16 + rbase;
            cp_async16(xs_s[buf] + (r * XS_STRIDE + slot * 4) * 4,
                       xb + (size_t)r * NTOK + nco + slot * 4);
        }
    };
    stage_x(0, 0);
    CP_COMMIT();

    // per-row cvec values (hoisted out of chunk loop)
    float cv[2][2];
#pragma unroll
    for (int i = 0; i < 2; i++) {
        const int r0 = mbase + i * 16 + gid;
        cv[i][0] = g_cv[b * CDIM + r0];
        cv[i][1] = g_cv[b * CDIM + r0 + 8];
    }

    CP_WAIT_ALL();
    __syncthreads();

    for (int nc = 0; nc < FIN_NCHUNK; nc++) {
        const int buf = nc & 1;
        float* Xs = (buf == 0) ? Xs0 : Xs1;
        // prefetch next chunk into the other buffer
        if (nc + 1 < FIN_NCHUNK) {
            stage_x(nc + 1, buf ^ 1);
            CP_COMMIT();
        }

        float acc[2][4][4];
#pragma unroll
        for (int i = 0; i < 2; i++)
#pragma unroll
            for (int j = 0; j < 4; j++)
#pragma unroll
                for (int q = 0; q < 4; q++) acc[i][j][q] = 0.f;

#pragma unroll
        for (int ks = 0; ks < 16; ks++) {
            const int kb = ks * 8;
            uint32_t af[2][4], bf[4][2];
#pragma unroll
            for (int i = 0; i < 2; i++) {
                const int m = mbase + i * 16 + gid;
                af[i][0] = __float_as_uint(Ms[m * MS_STRIDE + kb + tig]);
                af[i][1] = __float_as_uint(Ms[(m + 8) * MS_STRIDE + kb + tig]);
                af[i][2] = __float_as_uint(Ms[m * MS_STRIDE + kb + tig + 4]);
                af[i][3] = __float_as_uint(Ms[(m + 8) * MS_STRIDE + kb + tig + 4]);
            }
#pragma unroll
            for (int j = 0; j < 4; j++) {
                const int n = nwarp + j * 8 + gid;
                bf[j][0] = f2tf32u(Xs[(kb + tig) * XS_STRIDE + n]);
                bf[j][1] = f2tf32u(Xs[(kb + tig + 4) * XS_STRIDE + n]);
            }
#pragma unroll
            for (int i = 0; i < 2; i++)
#pragma unroll
                for (int j = 0; j < 4; j++)
                    mma_tf32(acc[i][j][0], acc[i][j][1], acc[i][j][2], acc[i][j][3],
                             af[i][0], af[i][1], af[i][2], af[i][3], bf[j][0], bf[j][1]);
        }

        // epilogue: + cvec, streaming stores
        const int nco = n0 + nc * 64;
#pragma unroll
        for (int i = 0; i < 2; i++) {
            const int r0 = mbase + i * 16 + gid;
            float* op0 = out + ((size_t)b * CDIM + r0) * NTOK + nco;
            float* op1 = op0 + (size_t)8 * NTOK;
#pragma unroll
            for (int j = 0; j < 4; j++) {
                const int c0 = nwarp + j * 8 + tig * 2;
                __stcs(reinterpret_cast<float2*>(op0 + c0),
                       make_float2(acc[i][j][0] + cv[i][0], acc[i][j][1] + cv[i][0]));
                __stcs(reinterpret_cast<float2*>(op1 + c0),
                       make_float2(acc[i][j][2] + cv[i][1], acc[i][j][3] + cv[i][1]));
            }
        }

        if (nc + 1 < FIN_NCHUNK) {
            CP_WAIT_ALL();       // next chunk resident
            __syncthreads();     // all reads of current buf done before reuse
        }
    }
}

// ---------------- launch -----------------------------------------------------
extern "C" void kernel_launch(void* const* d_in, const int* in_sizes, int n_in,
                              void* d_out, int out_size) {
    (void)in_sizes; (void)n_in; (void)out_size;
    const float* x     = (const float*)d_in[0];
    const float* w_qkv = (const float*)d_in[1];
    const float* b_qkv = (const float*)d_in[2];
    const float* w_out = (const float*)d_in[3];
    const float* b_out = (const float*)d_in[4];
    float* out = (float*)d_out;

    cudaFuncSetAttribute(k_final, cudaFuncAttributeMaxDynamicSharedMemorySize,
                         SMEM_FINAL_BYTES);

    k_gram<<<dim3(PCH, BATCH), 256>>>(x);
    k_reduceG<<<dim3(16, BATCH), 256>>>();
    k_attn<<<dim3(NHEADS, BATCH), 256>>>(w_qkv, b_qkv, w_out);
    k_mred<<<dim3(16, BATCH), 256>>>(w_out, b_out);
    k_final<<<dim3(NTOK / FIN_NSPAN, BATCH), 256, SMEM_FINAL_BYTES>>>(x, out);
}

// round 15
// speedup vs baseline: 2.1909x; 1.2879x over previous
#include <cuda_runtime.h>
#include <cuda_fp16.h>
#include <cstdint>

#define BATCH 16
#define CDIM 128
#define NTOK 16384
#define NHEADS 8
#define HDIM 16
#define PCH 16
#define KC (NTOK / PCH)   // 1024

// k_final: M tile (128 x 136 halfs) + double-buffered X^T (2 x 64 x 136 halfs)
#define MS_H 136
#define XS_H 136
#define FIN_NCHUNK 4
#define FIN_NSPAN (64 * FIN_NCHUNK)   // 256 columns per CTA
#define SMEM_FINAL_BYTES ((CDIM * MS_H + 2 * 64 * XS_H) * 2)

// ---------------- scratch (static device globals; no allocations) ----------
__device__ float g_Gpart[BATCH * PCH * CDIM * CDIM]; // ~16.8 MB
__device__ float g_spart[BATCH * PCH * CDIM];
__device__ float g_G[BATCH * CDIM * CDIM];                 // fp32 Gram
__device__ float g_s[BATCH * CDIM];
__device__ float g_Mpart[BATCH * NHEADS * CDIM * CDIM];    // 8 MB per-head M parts
__device__ float g_u[BATCH * CDIM];
__device__ __half g_Mh[BATCH * CDIM * CDIM];               // fp16 M
__device__ float g_cv[BATCH * CDIM];

// ---------------- helpers ---------------------------------------------------
__device__ __forceinline__ uint32_t f2tf32u(float x) {
    uint32_t r;
    asm("cvt.rna.tf32.f32 %0, %1;" : "=r"(r) : "f"(x));
    return r;
}

__device__ __forceinline__ uint32_t f2h2(float a, float b) {
    __half2 h = __floats2half2_rn(a, b);   // a -> low half
    return *reinterpret_cast<uint32_t*>(&h);
}

// legacy tf32 k8 MMA (still used in k_attn)
__device__ __forceinline__ void mma_tf32(float& d0, float& d1, float& d2, float& d3,
                                         uint32_t a0, uint32_t a1, uint32_t a2, uint32_t a3,
                                         uint32_t b0, uint32_t b1) {
    asm volatile(
        "mma.sync.aligned.m16n8k8.row.col.f32.tf32.tf32.f32 "
        "{%0,%1,%2,%3}, {%4,%5,%6,%7}, {%8,%9}, {%0,%1,%2,%3};"
        : "+f"(d0), "+f"(d1), "+f"(d2), "+f"(d3)
        : "r"(a0), "r"(a1), "r"(a2), "r"(a3), "r"(b0), "r"(b1));
}

// fp16 k16 MMA, fp32 accumulate
__device__ __forceinline__ void mma_f16(float& d0, float& d1, float& d2, float& d3,
                                        uint32_t a0, uint32_t a1, uint32_t a2, uint32_t a3,
                                        uint32_t b0, uint32_t b1) {
    asm volatile(
        "mma.sync.aligned.m16n8k16.row.col.f32.f16.f16.f32 "
        "{%0,%1,%2,%3}, {%4,%5,%6,%7}, {%8,%9}, {%0,%1,%2,%3};"
        : "+f"(d0), "+f"(d1), "+f"(d2), "+f"(d3)
        : "r"(a0), "r"(a1), "r"(a2), "r"(a3), "r"(b0), "r"(b1));
}

__device__ __forceinline__ void cp_async16(uint32_t saddr, const void* gptr) {
    asm volatile("cp.async.cg.shared.global [%0], [%1], 16;"
                 :: "r"(saddr), "l"(gptr));
}
#define CP_COMMIT() asm volatile("cp.async.commit_group;")
#define CP_WAIT_ALL() asm volatile("cp.async.wait_group 0;")

// ---------------- kernel 1: partial Gram G = X X^T (fp16 k16 MMA) ----------
// grid (PCH, BATCH), block 256. 64-wide K tiles, double-buffered, fused rowsum.
__global__ __launch_bounds__(256, 2) void k_gram(const float* __restrict__ x) {
    __shared__ __half Xs[2][CDIM * 72];   // 128 rows x 64 k halfs, stride 72
    const int b = blockIdx.y, p = blockIdx.x;
    const int tid = threadIdx.x;
    const int lane = tid & 31, warp = tid >> 5;
    const int gid = lane >> 2, tig = lane & 3;
    const int mbase = (warp >> 2) * 64, nbase = (warp & 3) * 32;
    const float* xb = x + (size_t)b * CDIM * NTOK;
    const int k0base = p * KC;
    const int rowg = tid >> 4;     // 0..15
    const int kq = tid & 15;       // k = kq*4

    float acc[4][4][4];
#pragma unroll
    for (int i = 0; i < 4; i++)
#pragma unroll
        for (int j = 0; j < 4; j++)
#pragma unroll
            for (int q = 0; q < 4; q++) acc[i][j][q] = 0.f;

    float rs[8] = {0.f, 0.f, 0.f, 0.f, 0.f, 0.f, 0.f, 0.f};

    auto load_tile = [&](int kt, int buf) {
        const int k0 = k0base + kt * 64;
#pragma unroll
        for (int pass = 0; pass < 8; pass++) {
            const int c = pass * 16 + rowg;
            float4 v = __ldcs(reinterpret_cast<const float4*>(
                xb + (size_t)c * NTOK + k0 + kq * 4));
            rs[pass] += v.x + v.y + v.z + v.w;
            uint2 u = make_uint2(f2h2(v.x, v.y), f2h2(v.z, v.w));
            *reinterpret_cast<uint2*>(&Xs[buf][c * 72 + kq * 4]) = u;
        }
    };

    load_tile(0, 0);
    __syncthreads();

    const int NT = KC / 64;   // 16 tiles
    for (int kt = 0; kt < NT; kt++) {
        const int cur = kt & 1;
        if (kt + 1 < NT) load_tile(kt + 1, cur ^ 1);
#pragma unroll
        for (int ks = 0; ks < 4; ks++) {
            const int kb = ks * 16;
            uint32_t af[4][4], bf[4][2];
#pragma unroll
            for (int i = 0; i < 4; i++) {
                const int m = mbase + i * 16 + gid;
                af[i][0] = *reinterpret_cast<const uint32_t*>(&Xs[cur][m * 72 + kb + 2 * tig]);
                af[i][1] = *reinterpret_cast<const uint32_t*>(&Xs[cur][(m + 8) * 72 + kb + 2 * tig]);
                af[i][2] = *reinterpret_cast<const uint32_t*>(&Xs[cur][m * 72 + kb + 8 + 2 * tig]);
                af[i][3] = *reinterpret_cast<const uint32_t*>(&Xs[cur][(m + 8) * 72 + kb + 8 + 2 * tig]);
            }
#pragma unroll
            for (int j = 0; j < 4; j++) {
                const int n = nbase + j * 8 + gid;
                bf[j][0] = *reinterpret_cast<const uint32_t*>(&Xs[cur][n * 72 + kb + 2 * tig]);
                bf[j][1] = *reinterpret_cast<const uint32_t*>(&Xs[cur][n * 72 + kb + 8 + 2 * tig]);
            }
#pragma unroll
            for (int i = 0; i < 4; i++)
#pragma unroll
                for (int j = 0; j < 4; j++)
                    mma_f16(acc[i][j][0], acc[i][j][1], acc[i][j][2], acc[i][j][3],
                            af[i][0], af[i][1], af[i][2], af[i][3], bf[j][0], bf[j][1]);
        }
        __syncthreads();
    }

    // write partial G
    float* gp = g_Gpart + ((size_t)b * PCH + p) * CDIM * CDIM;
#pragma unroll
    for (int i = 0; i < 4; i++) {
        const int r0 = mbase + i * 16 + gid;
#pragma unroll
        for (int j = 0; j < 4; j++) {
            const int c0 = nbase + j * 8 + tig * 2;
            *reinterpret_cast<float2*>(&gp[r0 * CDIM + c0]) =
                make_float2(acc[i][j][0], acc[i][j][1]);
            *reinterpret_cast<float2*>(&gp[(r0 + 8) * CDIM + c0]) =
                make_float2(acc[i][j][2], acc[i][j][3]);
        }
    }

    // rowsum: reduce across the 16 kq lanes (stays within 16-lane half-warp)
#pragma unroll
    for (int off = 1; off < 16; off <<= 1)
#pragma unroll
        for (int pass = 0; pass < 8; pass++)
            rs[pass] += __shfl_xor_sync(0xffffffffu, rs[pass], off);
    if (kq == 0) {
#pragma unroll
        for (int pass = 0; pass < 8; pass++)
            g_spart[((size_t)b * PCH + p) * CDIM + pass * 16 + rowg] = rs[pass];
    }
}

// ---------------- kernel 2: reduce partials (fp32, wide grid) --------------
// grid (16, BATCH), block 256.
__global__ __launch_bounds__(256) void k_reduceG() {
    const int b = blockIdx.y;
    const float4* gp = reinterpret_cast<const float4*>(
        g_Gpart + (size_t)b * PCH * CDIM * CDIM);
    float4* go = reinterpret_cast<float4*>(g_G + (size_t)b * CDIM * CDIM);
    const int idx = blockIdx.x * 256 + threadIdx.x;   // 0..4095 float4
    float4 a = gp[idx];
#pragma unroll
    for (int p = 1; p < PCH; p++) {
        float4 v = gp[(size_t)p * (CDIM * CDIM / 4) + idx];
        a.x += v.x; a.y += v.y; a.z += v.z; a.w += v.w;
    }
    go[idx] = a;
    if (blockIdx.x == 0 && threadIdx.x < CDIM) {
        float s = 0.f;
#pragma unroll
        for (int p = 0; p < PCH; p++)
            s += g_spart[((size_t)b * PCH + p) * CDIM + threadIdx.x];
        g_s[b * CDIM + threadIdx.x] = s;
    }
}

// ---------------- kernel 3: scores/softmax/T + per-head M part -------------
// grid (NHEADS, BATCH), block 256. fp32 score math; C_h = Wout_h@T_h tf32 MMA.
__global__ __launch_bounds__(256) void k_attn(const float* __restrict__ w_qkv,
                                              const float* __restrict__ b_qkv,
                                              const float* __restrict__ w_out) {
    __shared__ float Rs[HDIM][CDIM];
    __shared__ float Ss[HDIM][HDIM];
    __shared__ float Ts[HDIM][136];
    __shared__ float qs[HDIM], kssum[HDIM];
    const int h = blockIdx.x, b = blockIdx.y;
    const int tid = threadIdx.x;
    const int lane = tid & 31, warp = tid >> 5;
    const int gid = lane >> 2, tig = lane & 3;
    const int d = tid >> 4, cg = tid & 15;
    const float* G = g_G + (size_t)b * CDIM * CDIM;
    const float* Wq = w_qkv + (size_t)(h * HDIM) * CDIM;
    const float* Wk = w_qkv + (size_t)(CDIM + h * HDIM) * CDIM;
    const float* Wv = w_qkv + (size_t)(2 * CDIM + h * HDIM) * CDIM;

    if (tid < 2 * HDIM) {
        const int dd = tid & 15;
        const float* W = (tid < HDIM) ? Wq : Wk;
        float acc = 0.f;
        for (int c = 0; c < CDIM; c++) acc += W[dd * CDIM + c] * g_s[b * CDIM + c];
        if (tid < HDIM) qs[dd] = acc; else kssum[dd] = acc;
    }

    // R = Wq_h @ G (fp32)
    {
        float a[8] = {0, 0, 0, 0, 0, 0, 0, 0};
#pragma unroll 4
        for (int c = 0; c < CDIM; c++) {
            const float wq = __ldg(&Wq[d * CDIM + c]);
            const float4* gp = reinterpret_cast<const float4*>(G + c * CDIM + cg * 8);
            const float4 g0 = __ldg(gp), g1 = __ldg(gp + 1);
            a[0] += wq * g0.x; a[1] += wq * g0.y; a[2] += wq * g0.z; a[3] += wq * g0.w;
            a[4] += wq * g1.x; a[5] += wq * g1.y; a[6] += wq * g1.z; a[7] += wq * g1.w;
        }
#pragma unroll
        for (int j = 0; j < 8; j++) Rs[d][cg * 8 + j] = a[j];
    }
    __syncthreads();

    // scores (fp32)
    {
        const int e = cg;
        float acc = 0.f;
#pragma unroll 4
        for (int c = 0; c < CDIM; c++) acc += Rs[d][c] * __ldg(&Wk[e * CDIM + c]);
        const float bq = b_qkv[h * HDIM + d];
        const float bk = b_qkv[CDIM + h * HDIM + e];
        acc += qs[d] * bk + bq * kssum[e] + (float)NTOK * bq * bk;
        Ss[d][e] = acc * 0.08838834764831845f;
    }
    __syncthreads();

    // softmax rows + u
    if (tid < HDIM) {
        float m = -1e30f;
#pragma unroll
        for (int e = 0; e < HDIM; e++) m = fmaxf(m, Ss[tid][e]);
        float ex[HDIM], sum = 0.f;
#pragma unroll
        for (int e = 0; e < HDIM; e++) { ex[e] = expf(Ss[tid][e] - m); sum += ex[e]; }
        const float inv = 1.f / sum;
        float u = 0.f;
#pragma unroll
        for (int e = 0; e < HDIM; e++) {
            const float pv = ex[e] * inv;
            Ss[tid][e] = pv;
            u += pv * __ldg(&b_qkv[2 * CDIM + h * HDIM + e]);
        }
        g_u[b * CDIM + h * HDIM + tid] = u;
    }
    __syncthreads();

    // T_h (tf32-rounded) -> Ts smem
    {
        float a[8] = {0, 0, 0, 0, 0, 0, 0, 0};
#pragma unroll
        for (int e = 0; e < HDIM; e++) {
            const float av = Ss[d][e];
            const float4* vp = reinterpret_cast<const float4*>(Wv + e * CDIM + cg * 8);
            const float4 v0 = __ldg(vp), v1 = __ldg(vp + 1);
            a[0] += av * v0.x; a[1] += av * v0.y; a[2] += av * v0.z; a[3] += av * v0.w;
            a[4] += av * v1.x; a[5] += av * v1.y; a[6] += av * v1.z; a[7] += av * v1.w;
        }
#pragma unroll
        for (int j = 0; j < 8; j++)
            Ts[d][cg * 8 + j] = __uint_as_float(f2tf32u(a[j]));
    }
    __syncthreads();

    // C_h = Wout[:, h*16:+16] @ T_h  (tf32 MMA)
    {
        float cacc[16][4];
#pragma unroll
        for (int j = 0; j < 16; j++)
#pragma unroll
            for (int q = 0; q < 4; q++) cacc[j][q] = 0.f;

        uint32_t af[2][4];
#pragma unroll
        for (int ks = 0; ks < 2; ks++) {
            const int kb = ks * 8;
            const int m = warp * 16 + gid;
            af[ks][0] = f2tf32u(__ldg(&w_out[m * CDIM + h * HDIM + kb + tig]));
            af[ks][1] = f2tf32u(__ldg(&w_out[(m + 8) * CDIM + h * HDIM + kb + tig]));
            af[ks][2] = f2tf32u(__ldg(&w_out[m * CDIM + h * HDIM + kb + tig + 4]));
            af[ks][3] = f2tf32u(__ldg(&w_out[(m + 8) * CDIM + h * HDIM + kb + tig + 4]));
        }
#pragma unroll
        for (int j = 0; j < 16; j++) {
            const int n = j * 8 + gid;
#pragma unroll
            for (int ks = 0; ks < 2; ks++) {
                const int kb = ks * 8;
                uint32_t b0 = __float_as_uint(Ts[kb + tig][n]);
                uint32_t b1 = __float_as_uint(Ts[kb + tig + 4][n]);
                mma_tf32(cacc[j][0], cacc[j][1], cacc[j][2], cacc[j][3],
                         af[ks][0], af[ks][1], af[ks][2], af[ks][3], b0, b1);
            }
        }

        float* Mp = g_Mpart + ((size_t)(b * NHEADS) + h) * CDIM * CDIM;
        const int r0 = warp * 16 + gid;
#pragma unroll
        for (int j = 0; j < 16; j++) {
            const int c0 = j * 8 + tig * 2;
            *reinterpret_cast<float2*>(&Mp[r0 * CDIM + c0]) =
                make_float2(cacc[j][0], cacc[j][1]);
            *reinterpret_cast<float2*>(&Mp[(r0 + 8) * CDIM + c0]) =
                make_float2(cacc[j][2], cacc[j][3]);
        }
    }
}

// ---------------- kernel 4: M = sum_h Mpart -> fp16; cvec ------------------
// grid (16, BATCH), block 256.
__global__ __launch_bounds__(256) void k_mred(const float* __restrict__ w_out,
                                              const float* __restrict__ b_out) {
    const int b = blockIdx.y;
    const float4* mp = reinterpret_cast<const float4*>(
        g_Mpart + (size_t)(b * NHEADS) * CDIM * CDIM);
    const int idx = blockIdx.x * 256 + threadIdx.x;   // 0..4095 float4
    float4 a = mp[idx];
#pragma unroll
    for (int h = 1; h < NHEADS; h++) {
        float4 v = mp[(size_t)h * (CDIM * CDIM / 4) + idx];
        a.x += v.x; a.y += v.y; a.z += v.z; a.w += v.w;
    }
    uint2 o = make_uint2(f2h2(a.x, a.y), f2h2(a.z, a.w));
    *reinterpret_cast<uint2*>(&g_Mh[(size_t)b * CDIM * CDIM + (size_t)idx * 4]) = o;

    // cvec = W_out @ u + b_out (fp32)
    if (blockIdx.x == 0 && threadIdx.x < CDIM) {
        const int o2 = threadIdx.x;
        float a2 = __ldg(&b_out[o2]);
#pragma unroll 8
        for (int r = 0; r < CDIM; r++)
            a2 += __ldg(&w_out[o2 * CDIM + r]) * g_u[b * CDIM + r];
        g_cv[b * CDIM + o2] = a2;
    }
}

// ---------------- kernel 5: final = M @ X + c (fp16 k16 MMA) ---------------
// grid (NTOK/256, BATCH), block 256, 69.6 KB smem -> 2 CTAs/SM.
// M (fp16) cp.async'd once; X staged transposed [n][k] with k-pairs packed.
__global__ __launch_bounds__(256, 2) void k_final(const float* __restrict__ x,
                                                  float* __restrict__ out) {
    extern __shared__ __half smemh[];
    __half* Ms = smemh;                      // 128 x 136 halfs
    __half* Xs0 = smemh + CDIM * MS_H;       // 64 x 136 halfs
    __half* Xs1 = Xs0 + 64 * XS_H;
    const int b = blockIdx.y;
    const int n0 = blockIdx.x * FIN_NSPAN;
    const int tid = threadIdx.x;
    const int lane = tid & 31, warp = tid >> 5;
    const int gid = lane >> 2, tig = lane & 3;
    const int mbase = (warp >> 1) * 32;   // 4 m-warps
    const int nwarp = (warp & 1) * 32;    // 2 n-warps
    const int kgrp = tid >> 5;            // 0..7 for X staging
    const float* xb = x + (size_t)b * CDIM * NTOK;
    const __half* Mb = g_Mh + (size_t)b * CDIM * CDIM;

    // stage M via cp.async: 2048 x 16B chunks = 128 rows x 16 chunks/row
    {
        const uint32_t ms_s = (uint32_t)__cvta_generic_to_shared(Ms);
#pragma unroll
        for (int i = 0; i < 8; i++) {
            const int idx = i * 256 + tid;     // 16B-chunk index, 0..2047
            const int row = idx >> 4;          // 16 chunks (128 halfs) per row
            const int c16 = idx & 15;
            cp_async16(ms_s + (row * MS_H + c16 * 8) * 2, Mb + (size_t)idx * 8);
        }
        CP_COMMIT();
    }

    // X chunk staging: transpose into [n][k] halfs with packed k-pairs
    auto stage_x = [&](int nc, __half* Xs) {
        const int nco = n0 + nc * 64;
#pragma unroll
        for (int pass = 0; pass < 8; pass++) {
            const int kk = pass * 16 + kgrp * 2;
#pragma unroll
            for (int nh = 0; nh < 2; nh++) {
                const int n = lane + nh * 32;
                float v0 = __ldcs(xb + (size_t)kk * NTOK + nco + n);
                float v1 = __ldcs(xb + (size_t)(kk + 1) * NTOK + nco + n);
                *reinterpret_cast<uint32_t*>(&Xs[n * XS_H + kk]) = f2h2(v0, v1);
            }
        }
    };
    stage_x(0, Xs0);

    // hoist cvec
    float cv[2][2];
#pragma unroll
    for (int i = 0; i < 2; i++) {
        const int r0 = mbase + i * 16 + gid;
        cv[i][0] = g_cv[b * CDIM + r0];
        cv[i][1] = g_cv[b * CDIM + r0 + 8];
    }

    CP_WAIT_ALL();
    __syncthreads();

    for (int nc = 0; nc < FIN_NCHUNK; nc++) {
        __half* Xs = (nc & 1) ? Xs1 : Xs0;
        if (nc + 1 < FIN_NCHUNK) stage_x(nc + 1, (nc & 1) ? Xs0 : Xs1);

        float acc[2][4][4];
#pragma unroll
        for (int i = 0; i < 2; i++)
#pragma unroll
            for (int j = 0; j < 4; j++)
#pragma unroll
                for (int q = 0; q < 4; q++) acc[i][j][q] = 0.f;

#pragma unroll
        for (int ks = 0; ks < 8; ks++) {
            const int kb = ks * 16;
            uint32_t af[2][4], bf[4][2];
#pragma unroll
            for (int i = 0; i < 2; i++) {
                const int m = mbase + i * 16 + gid;
                af[i][0] = *reinterpret_cast<const uint32_t*>(&Ms[m * MS_H + kb + 2 * tig]);
                af[i][1] = *reinterpret_cast<const uint32_t*>(&Ms[(m + 8) * MS_H + kb + 2 * tig]);
                af[i][2] = *reinterpret_cast<const uint32_t*>(&Ms[m * MS_H + kb + 8 + 2 * tig]);
                af[i][3] = *reinterpret_cast<const uint32_t*>(&Ms[(m + 8) * MS_H + kb + 8 + 2 * tig]);
            }
#pragma unroll
            for (int j = 0; j < 4; j++) {
                const int n = nwarp + j * 8 + gid;
                bf[j][0] = *reinterpret_cast<const uint32_t*>(&Xs[n * XS_H + kb + 2 * tig]);
                bf[j][1] = *reinterpret_cast<const uint32_t*>(&Xs[n * XS_H + kb + 8 + 2 * tig]);
            }
#pragma unroll
            for (int i = 0; i < 2; i++)
#pragma unroll
                for (int j = 0; j < 4; j++)
                    mma_f16(acc[i][j][0], acc[i][j][1], acc[i][j][2], acc[i][j][3],
                            af[i][0], af[i][1], af[i][2], af[i][3], bf[j][0], bf[j][1]);
        }

        // epilogue: + cvec, streaming stores
        const int nco = n0 + nc * 64;
#pragma unroll
        for (int i = 0; i < 2; i++) {
            const int r0 = mbase + i * 16 + gid;
            float* op0 = out + ((size_t)b * CDIM + r0) * NTOK + nco;
            float* op1 = op0 + (size_t)8 * NTOK;
#pragma unroll
            for (int j = 0; j < 4; j++) {
                const int c0 = nwarp + j * 8 + tig * 2;
                __stcs(reinterpret_cast<float2*>(op0 + c0),
                       make_float2(acc[i][j][0] + cv[i][0], acc[i][j][1] + cv[i][0]));
                __stcs(reinterpret_cast<float2*>(op1 + c0),
                       make_float2(acc[i][j][2] + cv[i][1], acc[i][j][3] + cv[i][1]));
            }
        }
        __syncthreads();
    }
}

// ---------------- launch -----------------------------------------------------
extern "C" void kernel_launch(void* const* d_in, const int* in_sizes, int n_in,
                              void* d_out, int out_size) {
    (void)in_sizes; (void)n_in; (void)out_size;
    const float* x     = (const float*)d_in[0];
    const float* w_qkv = (const float*)d_in[1];
    const float* b_qkv = (const float*)d_in[2];
    const float* w_out = (const float*)d_in[3];
    const float* b_out = (const float*)d_in[4];
    float* out = (float*)d_out;

    cudaFuncSetAttribute(k_final, cudaFuncAttributeMaxDynamicSharedMemorySize,
                         SMEM_FINAL_BYTES);

    k_gram<<<dim3(PCH, BATCH), 256>>>(x);
    k_reduceG<<<dim3(16, BATCH), 256>>>();
    k_attn<<<dim3(NHEADS, BATCH), 256>>>(w_qkv, b_qkv, w_out);
    k_mred<<<dim3(16, BATCH), 256>>>(w_out, b_out);
    k_final<<<dim3(NTOK / FIN_NSPAN, BATCH), 256, SMEM_FINAL_BYTES>>>(x, out);
}

// round 16
// speedup vs baseline: 2.3620x; 1.0781x over previous
#include <cuda_runtime.h>
#include <cuda_fp16.h>
#include <cstdint>

#define BATCH 16
#define CDIM 128
#define NTOK 16384
#define NHEADS 8
#define HDIM 16
#define PCH 16
#define KC (NTOK / PCH)   // 1024

// k_final: M tile (128 x 136 halfs) + double-buffered X^T (2 x 64 x 136 halfs)
#define MS_H 136
#define XS_H 136
#define FIN_NCHUNK 8
#define FIN_NSPAN (64 * FIN_NCHUNK)   // 512 columns per CTA
#define SMEM_FINAL_BYTES ((CDIM * MS_H + 2 * 64 * XS_H) * 2)

// ---------------- scratch (static device globals; no allocations) ----------
__device__ float g_Gpart[BATCH * PCH * CDIM * CDIM]; // ~16.8 MB
__device__ float g_spart[BATCH * PCH * CDIM];
__device__ float g_G[BATCH * CDIM * CDIM];                 // fp32 Gram
__device__ float g_s[BATCH * CDIM];
__device__ float g_Mpart[BATCH * NHEADS * CDIM * CDIM];    // 8 MB per-head M parts
__device__ float g_u[BATCH * CDIM];
__device__ __half g_Mh[BATCH * CDIM * CDIM];               // fp16 M
__device__ float g_cv[BATCH * CDIM];

// ---------------- helpers ---------------------------------------------------
__device__ __forceinline__ uint32_t f2tf32u(float x) {
    uint32_t r;
    asm("cvt.rna.tf32.f32 %0, %1;" : "=r"(r) : "f"(x));
    return r;
}

__device__ __forceinline__ uint32_t f2h2(float a, float b) {
    __half2 h = __floats2half2_rn(a, b);   // a -> low half
    return *reinterpret_cast<uint32_t*>(&h);
}

// legacy tf32 k8 MMA (still used in k_attn)
__device__ __forceinline__ void mma_tf32(float& d0, float& d1, float& d2, float& d3,
                                         uint32_t a0, uint32_t a1, uint32_t a2, uint32_t a3,
                                         uint32_t b0, uint32_t b1) {
    asm volatile(
        "mma.sync.aligned.m16n8k8.row.col.f32.tf32.tf32.f32 "
        "{%0,%1,%2,%3}, {%4,%5,%6,%7}, {%8,%9}, {%0,%1,%2,%3};"
        : "+f"(d0), "+f"(d1), "+f"(d2), "+f"(d3)
        : "r"(a0), "r"(a1), "r"(a2), "r"(a3), "r"(b0), "r"(b1));
}

// fp16 k16 MMA, fp32 accumulate
__device__ __forceinline__ void mma_f16(float& d0, float& d1, float& d2, float& d3,
                                        uint32_t a0, uint32_t a1, uint32_t a2, uint32_t a3,
                                        uint32_t b0, uint32_t b1) {
    asm volatile(
        "mma.sync.aligned.m16n8k16.row.col.f32.f16.f16.f32 "
        "{%0,%1,%2,%3}, {%4,%5,%6,%7}, {%8,%9}, {%0,%1,%2,%3};"
        : "+f"(d0), "+f"(d1), "+f"(d2), "+f"(d3)
        : "r"(a0), "r"(a1), "r"(a2), "r"(a3), "r"(b0), "r"(b1));
}

__device__ __forceinline__ void cp_async16(uint32_t saddr, const void* gptr) {
    asm volatile("cp.async.cg.shared.global [%0], [%1], 16;"
                 :: "r"(saddr), "l"(gptr));
}
#define CP_COMMIT() asm volatile("cp.async.commit_group;")
#define CP_WAIT_ALL() asm volatile("cp.async.wait_group 0;")

// ---------------- kernel 1: partial Gram G = X X^T (fp16 k16 MMA) ----------
// grid (PCH, BATCH), block 256. 64-wide K tiles, double-buffered, fused rowsum.
__global__ __launch_bounds__(256, 2) void k_gram(const float* __restrict__ x) {
    __shared__ __half Xs[2][CDIM * 72];   // 128 rows x 64 k halfs, stride 72
    const int b = blockIdx.y, p = blockIdx.x;
    const int tid = threadIdx.x;
    const int lane = tid & 31, warp = tid >> 5;
    const int gid = lane >> 2, tig = lane & 3;
    const int mbase = (warp >> 2) * 64, nbase = (warp & 3) * 32;
    const float* xb = x + (size_t)b * CDIM * NTOK;
    const int k0base = p * KC;
    const int rowg = tid >> 4;     // 0..15
    const int kq = tid & 15;       // k = kq*4

    float acc[4][4][4];
#pragma unroll
    for (int i = 0; i < 4; i++)
#pragma unroll
        for (int j = 0; j < 4; j++)
#pragma unroll
            for (int q = 0; q < 4; q++) acc[i][j][q] = 0.f;

    float rs[8] = {0.f, 0.f, 0.f, 0.f, 0.f, 0.f, 0.f, 0.f};

    auto load_tile = [&](int kt, int buf) {
        const int k0 = k0base + kt * 64;
#pragma unroll
        for (int pass = 0; pass < 8; pass++) {
            const int c = pass * 16 + rowg;
            float4 v = __ldcs(reinterpret_cast<const float4*>(
                xb + (size_t)c * NTOK + k0 + kq * 4));
            rs[pass] += v.x + v.y + v.z + v.w;
            uint2 u = make_uint2(f2h2(v.x, v.y), f2h2(v.z, v.w));
            *reinterpret_cast<uint2*>(&Xs[buf][c * 72 + kq * 4]) = u;
        }
    };

    load_tile(0, 0);
    __syncthreads();

    const int NT = KC / 64;   // 16 tiles
    for (int kt = 0; kt < NT; kt++) {
        const int cur = kt & 1;
        if (kt + 1 < NT) load_tile(kt + 1, cur ^ 1);
#pragma unroll
        for (int ks = 0; ks < 4; ks++) {
            const int kb = ks * 16;
            uint32_t af[4][4], bf[4][2];
#pragma unroll
            for (int i = 0; i < 4; i++) {
                const int m = mbase + i * 16 + gid;
                af[i][0] = *reinterpret_cast<const uint32_t*>(&Xs[cur][m * 72 + kb + 2 * tig]);
                af[i][1] = *reinterpret_cast<const uint32_t*>(&Xs[cur][(m + 8) * 72 + kb + 2 * tig]);
                af[i][2] = *reinterpret_cast<const uint32_t*>(&Xs[cur][m * 72 + kb + 8 + 2 * tig]);
                af[i][3] = *reinterpret_cast<const uint32_t*>(&Xs[cur][(m + 8) * 72 + kb + 8 + 2 * tig]);
            }
#pragma unroll
            for (int j = 0; j < 4; j++) {
                const int n = nbase + j * 8 + gid;
                bf[j][0] = *reinterpret_cast<const uint32_t*>(&Xs[cur][n * 72 + kb + 2 * tig]);
                bf[j][1] = *reinterpret_cast<const uint32_t*>(&Xs[cur][n * 72 + kb + 8 + 2 * tig]);
            }
#pragma unroll
            for (int i = 0; i < 4; i++)
#pragma unroll
                for (int j = 0; j < 4; j++)
                    mma_f16(acc[i][j][0], acc[i][j][1], acc[i][j][2], acc[i][j][3],
                            af[i][0], af[i][1], af[i][2], af[i][3], bf[j][0], bf[j][1]);
        }
        __syncthreads();
    }

    // write partial G
    float* gp = g_Gpart + ((size_t)b * PCH + p) * CDIM * CDIM;
#pragma unroll
    for (int i = 0; i < 4; i++) {
        const int r0 = mbase + i * 16 + gid;
#pragma unroll
        for (int j = 0; j < 4; j++) {
            const int c0 = nbase + j * 8 + tig * 2;
            *reinterpret_cast<float2*>(&gp[r0 * CDIM + c0]) =
                make_float2(acc[i][j][0], acc[i][j][1]);
            *reinterpret_cast<float2*>(&gp[(r0 + 8) * CDIM + c0]) =
                make_float2(acc[i][j][2], acc[i][j][3]);
        }
    }

    // rowsum: reduce across the 16 kq lanes (stays within 16-lane half-warp)
#pragma unroll
    for (int off = 1; off < 16; off <<= 1)
#pragma unroll
        for (int pass = 0; pass < 8; pass++)
            rs[pass] += __shfl_xor_sync(0xffffffffu, rs[pass], off);
    if (kq == 0) {
#pragma unroll
        for (int pass = 0; pass < 8; pass++)
            g_spart[((size_t)b * PCH + p) * CDIM + pass * 16 + rowg] = rs[pass];
    }
}

// ---------------- kernel 2: reduce partials (fp32, 2 outputs/thread) -------
// grid (8, BATCH), block 256. 32 streaming loads in flight per thread.
__global__ __launch_bounds__(256) void k_reduceG() {
    const int b = blockIdx.y;
    const float4* gp = reinterpret_cast<const float4*>(
        g_Gpart + (size_t)b * PCH * CDIM * CDIM);
    float4* go = reinterpret_cast<float4*>(g_G + (size_t)b * CDIM * CDIM);
    const int i0 = blockIdx.x * 256 + threadIdx.x;   // 0..2047
    const int i1 = i0 + 2048;
    float4 a0 = __ldcs(&gp[i0]);
    float4 a1 = __ldcs(&gp[i1]);
#pragma unroll
    for (int p = 1; p < PCH; p++) {
        float4 v0 = __ldcs(&gp[(size_t)p * (CDIM * CDIM / 4) + i0]);
        float4 v1 = __ldcs(&gp[(size_t)p * (CDIM * CDIM / 4) + i1]);
        a0.x += v0.x; a0.y += v0.y; a0.z += v0.z; a0.w += v0.w;
        a1.x += v1.x; a1.y += v1.y; a1.z += v1.z; a1.w += v1.w;
    }
    go[i0] = a0;
    go[i1] = a1;
    if (blockIdx.x == 0 && threadIdx.x < CDIM) {
        float s = 0.f;
#pragma unroll
        for (int p = 0; p < PCH; p++)
            s += g_spart[((size_t)b * PCH + p) * CDIM + threadIdx.x];
        g_s[b * CDIM + threadIdx.x] = s;
    }
}

// ---------------- kernel 3: scores/softmax/T + per-head M part -------------
// grid (NHEADS, BATCH), block 256. fp32 score math; C_h = Wout_h@T_h tf32 MMA.
__global__ __launch_bounds__(256) void k_attn(const float* __restrict__ w_qkv,
                                              const float* __restrict__ b_qkv,
                                              const float* __restrict__ w_out) {
    __shared__ float Rs[HDIM][CDIM];
    __shared__ float Ss[HDIM][HDIM];
    __shared__ float Ts[HDIM][136];
    __shared__ float qs[HDIM], kssum[HDIM];
    const int h = blockIdx.x, b = blockIdx.y;
    const int tid = threadIdx.x;
    const int lane = tid & 31, warp = tid >> 5;
    const int gid = lane >> 2, tig = lane & 3;
    const int d = tid >> 4, cg = tid & 15;
    const float* G = g_G + (size_t)b * CDIM * CDIM;
    const float* Wq = w_qkv + (size_t)(h * HDIM) * CDIM;
    const float* Wk = w_qkv + (size_t)(CDIM + h * HDIM) * CDIM;
    const float* Wv = w_qkv + (size_t)(2 * CDIM + h * HDIM) * CDIM;

    if (tid < 2 * HDIM) {
        const int dd = tid & 15;
        const float* W = (tid < HDIM) ? Wq : Wk;
        float acc = 0.f;
        for (int c = 0; c < CDIM; c++) acc += W[dd * CDIM + c] * g_s[b * CDIM + c];
        if (tid < HDIM) qs[dd] = acc; else kssum[dd] = acc;
    }

    // R = Wq_h @ G (fp32)
    {
        float a[8] = {0, 0, 0, 0, 0, 0, 0, 0};
#pragma unroll 4
        for (int c = 0; c < CDIM; c++) {
            const float wq = __ldg(&Wq[d * CDIM + c]);
            const float4* gp = reinterpret_cast<const float4*>(G + c * CDIM + cg * 8);
            const float4 g0 = __ldg(gp), g1 = __ldg(gp + 1);
            a[0] += wq * g0.x; a[1] += wq * g0.y; a[2] += wq * g0.z; a[3] += wq * g0.w;
            a[4] += wq * g1.x; a[5] += wq * g1.y; a[6] += wq * g1.z; a[7] += wq * g1.w;
        }
#pragma unroll
        for (int j = 0; j < 8; j++) Rs[d][cg * 8 + j] = a[j];
    }
    __syncthreads();

    // scores (fp32)
    {
        const int e = cg;
        float acc = 0.f;
#pragma unroll 4
        for (int c = 0; c < CDIM; c++) acc += Rs[d][c] * __ldg(&Wk[e * CDIM + c]);
        const float bq = b_qkv[h * HDIM + d];
        const float bk = b_qkv[CDIM + h * HDIM + e];
        acc += qs[d] * bk + bq * kssum[e] + (float)NTOK * bq * bk;
        Ss[d][e] = acc * 0.08838834764831845f;
    }
    __syncthreads();

    // softmax rows + u
    if (tid < HDIM) {
        float m = -1e30f;
#pragma unroll
        for (int e = 0; e < HDIM; e++) m = fmaxf(m, Ss[tid][e]);
        float ex[HDIM], sum = 0.f;
#pragma unroll
        for (int e = 0; e < HDIM; e++) { ex[e] = expf(Ss[tid][e] - m); sum += ex[e]; }
        const float inv = 1.f / sum;
        float u = 0.f;
#pragma unroll
        for (int e = 0; e < HDIM; e++) {
            const float pv = ex[e] * inv;
            Ss[tid][e] = pv;
            u += pv * __ldg(&b_qkv[2 * CDIM + h * HDIM + e]);
        }
        g_u[b * CDIM + h * HDIM + tid] = u;
    }
    __syncthreads();

    // T_h (tf32-rounded) -> Ts smem
    {
        float a[8] = {0, 0, 0, 0, 0, 0, 0, 0};
#pragma unroll
        for (int e = 0; e < HDIM; e++) {
            const float av = Ss[d][e];
            const float4* vp = reinterpret_cast<const float4*>(Wv + e * CDIM + cg * 8);
            const float4 v0 = __ldg(vp), v1 = __ldg(vp + 1);
            a[0] += av * v0.x; a[1] += av * v0.y; a[2] += av * v0.z; a[3] += av * v0.w;
            a[4] += av * v1.x; a[5] += av * v1.y; a[6] += av * v1.z; a[7] += av * v1.w;
        }
#pragma unroll
        for (int j = 0; j < 8; j++)
            Ts[d][cg * 8 + j] = __uint_as_float(f2tf32u(a[j]));
    }
    __syncthreads();

    // C_h = Wout[:, h*16:+16] @ T_h  (tf32 MMA)
    {
        float cacc[16][4];
#pragma unroll
        for (int j = 0; j < 16; j++)
#pragma unroll
            for (int q = 0; q < 4; q++) cacc[j][q] = 0.f;

        uint32_t af[2][4];
#pragma unroll
        for (int ks = 0; ks < 2; ks++) {
            const int kb = ks * 8;
            const int m = warp * 16 + gid;
            af[ks][0] = f2tf32u(__ldg(&w_out[m * CDIM + h * HDIM + kb + tig]));
            af[ks][1] = f2tf32u(__ldg(&w_out[(m + 8) * CDIM + h * HDIM + kb + tig]));
            af[ks][2] = f2tf32u(__ldg(&w_out[m * CDIM + h * HDIM + kb + tig + 4]));
            af[ks][3] = f2tf32u(__ldg(&w_out[(m + 8) * CDIM + h * HDIM + kb + tig + 4]));
        }
#pragma unroll
        for (int j = 0; j < 16; j++) {
            const int n = j * 8 + gid;
#pragma unroll
            for (int ks = 0; ks < 2; ks++) {
                const int kb = ks * 8;
                uint32_t b0 = __float_as_uint(Ts[kb + tig][n]);
                uint32_t b1 = __float_as_uint(Ts[kb + tig + 4][n]);
                mma_tf32(cacc[j][0], cacc[j][1], cacc[j][2], cacc[j][3],
                         af[ks][0], af[ks][1], af[ks][2], af[ks][3], b0, b1);
            }
        }

        float* Mp = g_Mpart + ((size_t)(b * NHEADS) + h) * CDIM * CDIM;
        const int r0 = warp * 16 + gid;
#pragma unroll
        for (int j = 0; j < 16; j++) {
            const int c0 = j * 8 + tig * 2;
            *reinterpret_cast<float2*>(&Mp[r0 * CDIM + c0]) =
                make_float2(cacc[j][0], cacc[j][1]);
            *reinterpret_cast<float2*>(&Mp[(r0 + 8) * CDIM + c0]) =
                make_float2(cacc[j][2], cacc[j][3]);
        }
    }
}

// ---------------- kernel 4: M = sum_h Mpart -> fp16; cvec ------------------
// grid (8, BATCH), block 256. 2 outputs per thread, 16 streaming loads.
__global__ __launch_bounds__(256) void k_mred(const float* __restrict__ w_out,
                                              const float* __restrict__ b_out) {
    const int b = blockIdx.y;
    const float4* mp = reinterpret_cast<const float4*>(
        g_Mpart + (size_t)(b * NHEADS) * CDIM * CDIM);
    const int i0 = blockIdx.x * 256 + threadIdx.x;   // 0..2047
    const int i1 = i0 + 2048;
    float4 a0 = __ldcs(&mp[i0]);
    float4 a1 = __ldcs(&mp[i1]);
#pragma unroll
    for (int h = 1; h < NHEADS; h++) {
        float4 v0 = __ldcs(&mp[(size_t)h * (CDIM * CDIM / 4) + i0]);
        float4 v1 = __ldcs(&mp[(size_t)h * (CDIM * CDIM / 4) + i1]);
        a0.x += v0.x; a0.y += v0.y; a0.z += v0.z; a0.w += v0.w;
        a1.x += v1.x; a1.y += v1.y; a1.z += v1.z; a1.w += v1.w;
    }
    *reinterpret_cast<uint2*>(&g_Mh[(size_t)b * CDIM * CDIM + (size_t)i0 * 4]) =
        make_uint2(f2h2(a0.x, a0.y), f2h2(a0.z, a0.w));
    *reinterpret_cast<uint2*>(&g_Mh[(size_t)b * CDIM * CDIM + (size_t)i1 * 4]) =
        make_uint2(f2h2(a1.x, a1.y), f2h2(a1.z, a1.w));

    // cvec = W_out @ u + b_out (fp32)
    if (blockIdx.x == 0 && threadIdx.x < CDIM) {
        const int o2 = threadIdx.x;
        float a2 = __ldg(&b_out[o2]);
#pragma unroll 8
        for (int r = 0; r < CDIM; r++)
            a2 += __ldg(&w_out[o2 * CDIM + r]) * g_u[b * CDIM + r];
        g_cv[b * CDIM + o2] = a2;
    }
}

// ---------------- kernel 5: final = M @ X + c (fp16 k16 MMA) ---------------
// grid (NTOK/512, BATCH), block 256, 69.6 KB smem -> 2 CTAs/SM.
// M (fp16) cp.async'd once per 512 cols; X transposed chunks double-buffered.
__global__ __launch_bounds__(256, 2) void k_final(const float* __restrict__ x,
                                                  float* __restrict__ out) {
    extern __shared__ __half smemh[];
    __half* Ms = smemh;                      // 128 x 136 halfs
    __half* Xs0 = smemh + CDIM * MS_H;       // 64 x 136 halfs
    __half* Xs1 = Xs0 + 64 * XS_H;
    const int b = blockIdx.y;
    const int n0 = blockIdx.x * FIN_NSPAN;
    const int tid = threadIdx.x;
    const int lane = tid & 31, warp = tid >> 5;
    const int gid = lane >> 2, tig = lane & 3;
    const int mbase = (warp >> 1) * 32;   // 4 m-warps
    const int nwarp = (warp & 1) * 32;    // 2 n-warps
    const int kgrp = tid >> 5;            // 0..7 for X staging
    const float* xb = x + (size_t)b * CDIM * NTOK;
    const __half* Mb = g_Mh + (size_t)b * CDIM * CDIM;

    // stage M via cp.async: 2048 x 16B chunks = 128 rows x 16 chunks/row
    {
        const uint32_t ms_s = (uint32_t)__cvta_generic_to_shared(Ms);
#pragma unroll
        for (int i = 0; i < 8; i++) {
            const int idx = i * 256 + tid;     // 16B-chunk index, 0..2047
            const int row = idx >> 4;          // 16 chunks (128 halfs) per row
            const int c16 = idx & 15;
            cp_async16(ms_s + (row * MS_H + c16 * 8) * 2, Mb + (size_t)idx * 8);
        }
        CP_COMMIT();
    }

    // X chunk staging: transpose into [n][k] halfs with packed k-pairs
    auto stage_x = [&](int nc, __half* Xs) {
        const int nco = n0 + nc * 64;
#pragma unroll
        for (int pass = 0; pass < 8; pass++) {
            const int kk = pass * 16 + kgrp * 2;
#pragma unroll
            for (int nh = 0; nh < 2; nh++) {
                const int n = lane + nh * 32;
                float v0 = __ldcs(xb + (size_t)kk * NTOK + nco + n);
                float v1 = __ldcs(xb + (size_t)(kk + 1) * NTOK + nco + n);
                *reinterpret_cast<uint32_t*>(&Xs[n * XS_H + kk]) = f2h2(v0, v1);
            }
        }
    };
    stage_x(0, Xs0);

    // hoist cvec
    float cv[2][2];
#pragma unroll
    for (int i = 0; i < 2; i++) {
        const int r0 = mbase + i * 16 + gid;
        cv[i][0] = g_cv[b * CDIM + r0];
        cv[i][1] = g_cv[b * CDIM + r0 + 8];
    }

    CP_WAIT_ALL();
    __syncthreads();

    for (int nc = 0; nc < FIN_NCHUNK; nc++) {
        __half* Xs = (nc & 1) ? Xs1 : Xs0;
        if (nc + 1 < FIN_NCHUNK) stage_x(nc + 1, (nc & 1) ? Xs0 : Xs1);

        float acc[2][4][4];
#pragma unroll
        for (int i = 0; i < 2; i++)
#pragma unroll
            for (int j = 0; j < 4; j++)
#pragma unroll
                for (int q = 0; q < 4; q++) acc[i][j][q] = 0.f;

#pragma unroll
        for (int ks = 0; ks < 8; ks++) {
            const int kb = ks * 16;
            uint32_t af[2][4], bf[4][2];
#pragma unroll
            for (int i = 0; i < 2; i++) {
                const int m = mbase + i * 16 + gid;
                af[i][0] = *reinterpret_cast<const uint32_t*>(&Ms[m * MS_H + kb + 2 * tig]);
                af[i][1] = *reinterpret_cast<const uint32_t*>(&Ms[(m + 8) * MS_H + kb + 2 * tig]);
                af[i][2] = *reinterpret_cast<const uint32_t*>(&Ms[m * MS_H + kb + 8 + 2 * tig]);
                af[i][3] = *reinterpret_cast<const uint32_t*>(&Ms[(m + 8) * MS_H + kb + 8 + 2 * tig]);
            }
#pragma unroll
            for (int j = 0; j < 4; j++) {
                const int n = nwarp + j * 8 + gid;
                bf[j][0] = *reinterpret_cast<const uint32_t*>(&Xs[n * XS_H + kb + 2 * tig]);
                bf[j][1] = *reinterpret_cast<const uint32_t*>(&Xs[n * XS_H + kb + 8 + 2 * tig]);
            }
#pragma unroll
            for (int i = 0; i < 2; i++)
#pragma unroll
                for (int j = 0; j < 4; j++)
                    mma_f16(acc[i][j][0], acc[i][j][1], acc[i][j][2], acc[i][j][3],
                            af[i][0], af[i][1], af[i][2], af[i][3], bf[j][0], bf[j][1]);
        }

        // epilogue: + cvec, streaming stores
        const int nco = n0 + nc * 64;
#pragma unroll
        for (int i = 0; i < 2; i++) {
            const int r0 = mbase + i * 16 + gid;
            float* op0 = out + ((size_t)b * CDIM + r0) * NTOK + nco;
            float* op1 = op0 + (size_t)8 * NTOK;
#pragma unroll
            for (int j = 0; j < 4; j++) {
                const int c0 = nwarp + j * 8 + tig * 2;
                __stcs(reinterpret_cast<float2*>(op0 + c0),
                       make_float2(acc[i][j][0] + cv[i][0], acc[i][j][1] + cv[i][0]));
                __stcs(reinterpret_cast<float2*>(op1 + c0),
                       make_float2(acc[i][j][2] + cv[i][1], acc[i][j][3] + cv[i][1]));
            }
        }
        __syncthreads();
    }
}

// ---------------- launch -----------------------------------------------------
extern "C" void kernel_launch(void* const* d_in, const int* in_sizes, int n_in,
                              void* d_out, int out_size) {
    (void)in_sizes; (void)n_in; (void)out_size;
    const float* x     = (const float*)d_in[0];
    const float* w_qkv = (const float*)d_in[1];
    const float* b_qkv = (const float*)d_in[2];
    const float* w_out = (const float*)d_in[3];
    const float* b_out = (const float*)d_in[4];
    float* out = (float*)d_out;

    cudaFuncSetAttribute(k_final, cudaFuncAttributeMaxDynamicSharedMemorySize,
                         SMEM_FINAL_BYTES);

    k_gram<<<dim3(PCH, BATCH), 256>>>(x);
    k_reduceG<<<dim3(8, BATCH), 256>>>();
    k_attn<<<dim3(NHEADS, BATCH), 256>>>(w_qkv, b_qkv, w_out);
    k_mred<<<dim3(8, BATCH), 256>>>(w_out, b_out);
    k_final<<<dim3(NTOK / FIN_NSPAN, BATCH), 256, SMEM_FINAL_BYTES>>>(x, out);
}

// round 17
// speedup vs baseline: 2.4716x; 1.0464x over previous
#include <cuda_runtime.h>
#include <cuda_fp16.h>
#include <cstdint>

#define BATCH 16
#define CDIM 128
#define NTOK 16384
#define NHEADS 8
#define HDIM 16
#define PCH 16
#define KC (NTOK / PCH)   // 1024

// k_final: M tile (128 x 136 halfs) + double-buffered X^T (2 x 64 x 136 halfs)
#define MS_H 136
#define XS_H 136
#define FIN_NCHUNK 8
#define FIN_NSPAN (64 * FIN_NCHUNK)   // 512 columns per CTA
#define SMEM_FINAL_BYTES ((CDIM * MS_H + 2 * 64 * XS_H) * 2)

// ---------------- scratch (static device globals; no allocations) ----------
__device__ float g_Gpart[BATCH * PCH * CDIM * CDIM]; // ~16.8 MB
__device__ float g_spart[BATCH * PCH * CDIM];
__device__ float g_G[BATCH * CDIM * CDIM];   // fp32 Gram
__device__ float g_s[BATCH * CDIM];
__device__ float g_M[BATCH * CDIM * CDIM];   // fp32 M, atomic-accumulated
__device__ float g_cv[BATCH * CDIM];

// ---------------- helpers ---------------------------------------------------
__device__ __forceinline__ uint32_t f2tf32u(float x) {
    uint32_t r;
    asm("cvt.rna.tf32.f32 %0, %1;" : "=r"(r) : "f"(x));
    return r;
}

__device__ __forceinline__ uint32_t f2h2(float a, float b) {
    __half2 h = __floats2half2_rn(a, b);   // a -> low half
    return *reinterpret_cast<uint32_t*>(&h);
}

// legacy tf32 k8 MMA (still used in k_attn)
__device__ __forceinline__ void mma_tf32(float& d0, float& d1, float& d2, float& d3,
                                         uint32_t a0, uint32_t a1, uint32_t a2, uint32_t a3,
                                         uint32_t b0, uint32_t b1) {
    asm volatile(
        "mma.sync.aligned.m16n8k8.row.col.f32.tf32.tf32.f32 "
        "{%0,%1,%2,%3}, {%4,%5,%6,%7}, {%8,%9}, {%0,%1,%2,%3};"
        : "+f"(d0), "+f"(d1), "+f"(d2), "+f"(d3)
        : "r"(a0), "r"(a1), "r"(a2), "r"(a3), "r"(b0), "r"(b1));
}

// fp16 k16 MMA, fp32 accumulate
__device__ __forceinline__ void mma_f16(float& d0, float& d1, float& d2, float& d3,
                                        uint32_t a0, uint32_t a1, uint32_t a2, uint32_t a3,
                                        uint32_t b0, uint32_t b1) {
    asm volatile(
        "mma.sync.aligned.m16n8k16.row.col.f32.f16.f16.f32 "
        "{%0,%1,%2,%3}, {%4,%5,%6,%7}, {%8,%9}, {%0,%1,%2,%3};"
        : "+f"(d0), "+f"(d1), "+f"(d2), "+f"(d3)
        : "r"(a0), "r"(a1), "r"(a2), "r"(a3), "r"(b0), "r"(b1));
}

// ---------------- kernel 1: partial Gram G = X X^T (fp16 k16 MMA) ----------
// grid (PCH, BATCH), block 256. 64-wide K tiles, double-buffered, fused rowsum.
__global__ __launch_bounds__(256, 2) void k_gram(const float* __restrict__ x) {
    __shared__ __half Xs[2][CDIM * 72];   // 128 rows x 64 k halfs, stride 72
    const int b = blockIdx.y, p = blockIdx.x;
    const int tid = threadIdx.x;
    const int lane = tid & 31, warp = tid >> 5;
    const int gid = lane >> 2, tig = lane & 3;
    const int mbase = (warp >> 2) * 64, nbase = (warp & 3) * 32;
    const float* xb = x + (size_t)b * CDIM * NTOK;
    const int k0base = p * KC;
    const int rowg = tid >> 4;     // 0..15
    const int kq = tid & 15;       // k = kq*4

    float acc[4][4][4];
#pragma unroll
    for (int i = 0; i < 4; i++)
#pragma unroll
        for (int j = 0; j < 4; j++)
#pragma unroll
            for (int q = 0; q < 4; q++) acc[i][j][q] = 0.f;

    float rs[8] = {0.f, 0.f, 0.f, 0.f, 0.f, 0.f, 0.f, 0.f};

    auto load_tile = [&](int kt, int buf) {
        const int k0 = k0base + kt * 64;
#pragma unroll
        for (int pass = 0; pass < 8; pass++) {
            const int c = pass * 16 + rowg;
            float4 v = __ldcs(reinterpret_cast<const float4*>(
                xb + (size_t)c * NTOK + k0 + kq * 4));
            rs[pass] += v.x + v.y + v.z + v.w;
            uint2 u = make_uint2(f2h2(v.x, v.y), f2h2(v.z, v.w));
            *reinterpret_cast<uint2*>(&Xs[buf][c * 72 + kq * 4]) = u;
        }
    };

    load_tile(0, 0);
    __syncthreads();

    const int NT = KC / 64;   // 16 tiles
    for (int kt = 0; kt < NT; kt++) {
        const int cur = kt & 1;
        if (kt + 1 < NT) load_tile(kt + 1, cur ^ 1);
#pragma unroll
        for (int ks = 0; ks < 4; ks++) {
            const int kb = ks * 16;
            uint32_t af[4][4], bf[4][2];
#pragma unroll
            for (int i = 0; i < 4; i++) {
                const int m = mbase + i * 16 + gid;
                af[i][0] = *reinterpret_cast<const uint32_t*>(&Xs[cur][m * 72 + kb + 2 * tig]);
                af[i][1] = *reinterpret_cast<const uint32_t*>(&Xs[cur][(m + 8) * 72 + kb + 2 * tig]);
                af[i][2] = *reinterpret_cast<const uint32_t*>(&Xs[cur][m * 72 + kb + 8 + 2 * tig]);
                af[i][3] = *reinterpret_cast<const uint32_t*>(&Xs[cur][(m + 8) * 72 + kb + 8 + 2 * tig]);
            }
#pragma unroll
            for (int j = 0; j < 4; j++) {
                const int n = nbase + j * 8 + gid;
                bf[j][0] = *reinterpret_cast<const uint32_t*>(&Xs[cur][n * 72 + kb + 2 * tig]);
                bf[j][1] = *reinterpret_cast<const uint32_t*>(&Xs[cur][n * 72 + kb + 8 + 2 * tig]);
            }
#pragma unroll
            for (int i = 0; i < 4; i++)
#pragma unroll
                for (int j = 0; j < 4; j++)
                    mma_f16(acc[i][j][0], acc[i][j][1], acc[i][j][2], acc[i][j][3],
                            af[i][0], af[i][1], af[i][2], af[i][3], bf[j][0], bf[j][1]);
        }
        __syncthreads();
    }

    // write partial G
    float* gp = g_Gpart + ((size_t)b * PCH + p) * CDIM * CDIM;
#pragma unroll
    for (int i = 0; i < 4; i++) {
        const int r0 = mbase + i * 16 + gid;
#pragma unroll
        for (int j = 0; j < 4; j++) {
            const int c0 = nbase + j * 8 + tig * 2;
            *reinterpret_cast<float2*>(&gp[r0 * CDIM + c0]) =
                make_float2(acc[i][j][0], acc[i][j][1]);
            *reinterpret_cast<float2*>(&gp[(r0 + 8) * CDIM + c0]) =
                make_float2(acc[i][j][2], acc[i][j][3]);
        }
    }

    // rowsum: reduce across the 16 kq lanes (stays within 16-lane half-warp)
#pragma unroll
    for (int off = 1; off < 16; off <<= 1)
#pragma unroll
        for (int pass = 0; pass < 8; pass++)
            rs[pass] += __shfl_xor_sync(0xffffffffu, rs[pass], off);
    if (kq == 0) {
#pragma unroll
        for (int pass = 0; pass < 8; pass++)
            g_spart[((size_t)b * PCH + p) * CDIM + pass * 16 + rowg] = rs[pass];
    }
}

// ---------------- kernel 2: reduce partials; zero g_M; init cvec -----------
// grid (8, BATCH), block 256.
__global__ __launch_bounds__(256) void k_reduceG(const float* __restrict__ b_out) {
    const int b = blockIdx.y;
    const float4* gp = reinterpret_cast<const float4*>(
        g_Gpart + (size_t)b * PCH * CDIM * CDIM);
    float4* go = reinterpret_cast<float4*>(g_G + (size_t)b * CDIM * CDIM);
    const int i0 = blockIdx.x * 256 + threadIdx.x;   // 0..2047
    const int i1 = i0 + 2048;
    float4 a0 = __ldcs(&gp[i0]);
    float4 a1 = __ldcs(&gp[i1]);
#pragma unroll
    for (int p = 1; p < PCH; p++) {
        float4 v0 = __ldcs(&gp[(size_t)p * (CDIM * CDIM / 4) + i0]);
        float4 v1 = __ldcs(&gp[(size_t)p * (CDIM * CDIM / 4) + i1]);
        a0.x += v0.x; a0.y += v0.y; a0.z += v0.z; a0.w += v0.w;
        a1.x += v1.x; a1.y += v1.y; a1.z += v1.z; a1.w += v1.w;
    }
    go[i0] = a0;
    go[i1] = a1;

    // zero g_M for k_attn atomic accumulation
    float4* mz = reinterpret_cast<float4*>(g_M + (size_t)b * CDIM * CDIM);
    const float4 z = make_float4(0.f, 0.f, 0.f, 0.f);
    mz[i0] = z;
    mz[i1] = z;

    if (blockIdx.x == 0 && threadIdx.x < CDIM) {
        float s = 0.f;
#pragma unroll
        for (int p = 0; p < PCH; p++)
            s += g_spart[((size_t)b * PCH + p) * CDIM + threadIdx.x];
        g_s[b * CDIM + threadIdx.x] = s;
        g_cv[b * CDIM + threadIdx.x] = __ldg(&b_out[threadIdx.x]);  // cvec init
    }
}

// ---------------- kernel 3: scores/softmax/T + atomic M/cvec ---------------
// grid (NHEADS, BATCH), block 256. fp32 score math; C_h -> atomicAdd g_M.
__global__ __launch_bounds__(256) void k_attn(const float* __restrict__ w_qkv,
                                              const float* __restrict__ b_qkv,
                                              const float* __restrict__ w_out) {
    __shared__ float Rs[HDIM][CDIM];
    __shared__ float Ss[HDIM][HDIM];
    __shared__ float Ts[HDIM][136];
    __shared__ float qs[HDIM], kssum[HDIM], us[HDIM];
    const int h = blockIdx.x, b = blockIdx.y;
    const int tid = threadIdx.x;
    const int lane = tid & 31, warp = tid >> 5;
    const int gid = lane >> 2, tig = lane & 3;
    const int d = tid >> 4, cg = tid & 15;
    const float* G = g_G + (size_t)b * CDIM * CDIM;
    const float* Wq = w_qkv + (size_t)(h * HDIM) * CDIM;
    const float* Wk = w_qkv + (size_t)(CDIM + h * HDIM) * CDIM;
    const float* Wv = w_qkv + (size_t)(2 * CDIM + h * HDIM) * CDIM;

    if (tid < 2 * HDIM) {
        const int dd = tid & 15;
        const float* W = (tid < HDIM) ? Wq : Wk;
        float acc = 0.f;
        for (int c = 0; c < CDIM; c++) acc += W[dd * CDIM + c] * g_s[b * CDIM + c];
        if (tid < HDIM) qs[dd] = acc; else kssum[dd] = acc;
    }

    // R = Wq_h @ G (fp32)
    {
        float a[8] = {0, 0, 0, 0, 0, 0, 0, 0};
#pragma unroll 4
        for (int c = 0; c < CDIM; c++) {
            const float wq = __ldg(&Wq[d * CDIM + c]);
            const float4* gp = reinterpret_cast<const float4*>(G + c * CDIM + cg * 8);
            const float4 g0 = __ldg(gp), g1 = __ldg(gp + 1);
            a[0] += wq * g0.x; a[1] += wq * g0.y; a[2] += wq * g0.z; a[3] += wq * g0.w;
            a[4] += wq * g1.x; a[5] += wq * g1.y; a[6] += wq * g1.z; a[7] += wq * g1.w;
        }
#pragma unroll
        for (int j = 0; j < 8; j++) Rs[d][cg * 8 + j] = a[j];
    }
    __syncthreads();

    // scores (fp32)
    {
        const int e = cg;
        float acc = 0.f;
#pragma unroll 4
        for (int c = 0; c < CDIM; c++) acc += Rs[d][c] * __ldg(&Wk[e * CDIM + c]);
        const float bq = b_qkv[h * HDIM + d];
        const float bk = b_qkv[CDIM + h * HDIM + e];
        acc += qs[d] * bk + bq * kssum[e] + (float)NTOK * bq * bk;
        Ss[d][e] = acc * 0.08838834764831845f;
    }
    __syncthreads();

    // softmax rows + u
    if (tid < HDIM) {
        float m = -1e30f;
#pragma unroll
        for (int e = 0; e < HDIM; e++) m = fmaxf(m, Ss[tid][e]);
        float ex[HDIM], sum = 0.f;
#pragma unroll
        for (int e = 0; e < HDIM; e++) { ex[e] = expf(Ss[tid][e] - m); sum += ex[e]; }
        const float inv = 1.f / sum;
        float u = 0.f;
#pragma unroll
        for (int e = 0; e < HDIM; e++) {
            const float pv = ex[e] * inv;
            Ss[tid][e] = pv;
            u += pv * __ldg(&b_qkv[2 * CDIM + h * HDIM + e]);
        }
        us[tid] = u;
    }
    __syncthreads();

    // T_h (tf32-rounded) -> Ts smem
    {
        float a[8] = {0, 0, 0, 0, 0, 0, 0, 0};
#pragma unroll
        for (int e = 0; e < HDIM; e++) {
            const float av = Ss[d][e];
            const float4* vp = reinterpret_cast<const float4*>(Wv + e * CDIM + cg * 8);
            const float4 v0 = __ldg(vp), v1 = __ldg(vp + 1);
            a[0] += av * v0.x; a[1] += av * v0.y; a[2] += av * v0.z; a[3] += av * v0.w;
            a[4] += av * v1.x; a[5] += av * v1.y; a[6] += av * v1.z; a[7] += av * v1.w;
        }
#pragma unroll
        for (int j = 0; j < 8; j++)
            Ts[d][cg * 8 + j] = __uint_as_float(f2tf32u(a[j]));
    }
    __syncthreads();

    // cvec contribution: g_cv[b][o] += W_out[o, h*16:+16] @ u_h
    if (tid < CDIM) {
        float a = 0.f;
#pragma unroll
        for (int e = 0; e < HDIM; e++)
            a += __ldg(&w_out[tid * CDIM + h * HDIM + e]) * us[e];
        atomicAdd(&g_cv[b * CDIM + tid], a);
    }

    // C_h = Wout[:, h*16:+16] @ T_h  (tf32 MMA) -> atomicAdd into g_M
    {
        float cacc[16][4];
#pragma unroll
        for (int j = 0; j < 16; j++)
#pragma unroll
            for (int q = 0; q < 4; q++) cacc[j][q] = 0.f;

        uint32_t af[2][4];
#pragma unroll
        for (int ks = 0; ks < 2; ks++) {
            const int kb = ks * 8;
            const int m = warp * 16 + gid;
            af[ks][0] = f2tf32u(__ldg(&w_out[m * CDIM + h * HDIM + kb + tig]));
            af[ks][1] = f2tf32u(__ldg(&w_out[(m + 8) * CDIM + h * HDIM + kb + tig]));
            af[ks][2] = f2tf32u(__ldg(&w_out[m * CDIM + h * HDIM + kb + tig + 4]));
            af[ks][3] = f2tf32u(__ldg(&w_out[(m + 8) * CDIM + h * HDIM + kb + tig + 4]));
        }
#pragma unroll
        for (int j = 0; j < 16; j++) {
            const int n = j * 8 + gid;
#pragma unroll
            for (int ks = 0; ks < 2; ks++) {
                const int kb = ks * 8;
                uint32_t b0 = __float_as_uint(Ts[kb + tig][n]);
                uint32_t b1 = __float_as_uint(Ts[kb + tig + 4][n]);
                mma_tf32(cacc[j][0], cacc[j][1], cacc[j][2], cacc[j][3],
                         af[ks][0], af[ks][1], af[ks][2], af[ks][3], b0, b1);
            }
        }

        float* Mg = g_M + (size_t)b * CDIM * CDIM;
        const int r0 = warp * 16 + gid;
#pragma unroll
        for (int j = 0; j < 16; j++) {
            const int c0 = j * 8 + tig * 2;
            atomicAdd(&Mg[r0 * CDIM + c0],     cacc[j][0]);
            atomicAdd(&Mg[r0 * CDIM + c0 + 1], cacc[j][1]);
            atomicAdd(&Mg[(r0 + 8) * CDIM + c0],     cacc[j][2]);
            atomicAdd(&Mg[(r0 + 8) * CDIM + c0 + 1], cacc[j][3]);
        }
    }
}

// ---------------- kernel 4: final = M @ X + c (fp16 k16 MMA) ---------------
// grid (NTOK/512, BATCH), block 256, 69.6 KB smem -> 2 CTAs/SM.
// M staged from fp32 g_M (L2-hot), converted to fp16 during staging.
__global__ __launch_bounds__(256, 2) void k_final(const float* __restrict__ x,
                                                  float* __restrict__ out) {
    extern __shared__ __half smemh[];
    __half* Ms = smemh;                      // 128 x 136 halfs
    __half* Xs0 = smemh + CDIM * MS_H;       // 64 x 136 halfs
    __half* Xs1 = Xs0 + 64 * XS_H;
    const int b = blockIdx.y;
    const int n0 = blockIdx.x * FIN_NSPAN;
    const int tid = threadIdx.x;
    const int lane = tid & 31, warp = tid >> 5;
    const int gid = lane >> 2, tig = lane & 3;
    const int mbase = (warp >> 1) * 32;   // 4 m-warps
    const int nwarp = (warp & 1) * 32;    // 2 n-warps
    const int kgrp = tid >> 5;            // 0..7 for X staging
    const float* xb = x + (size_t)b * CDIM * NTOK;
    const float4* mg = reinterpret_cast<const float4*>(g_M + (size_t)b * CDIM * CDIM);

    // stage M: 4096 float4 loads (L2-hot), cvt to fp16, STS
    {
#pragma unroll
        for (int i = 0; i < 16; i++) {
            const int idx = i * 256 + tid;     // 0..4095 float4
            const int row = idx >> 5;
            const int c4 = idx & 31;           // 4 floats each
            float4 v = __ldg(&mg[idx]);
            *reinterpret_cast<uint2*>(&Ms[row * MS_H + c4 * 4]) =
                make_uint2(f2h2(v.x, v.y), f2h2(v.z, v.w));
        }
    }

    // X chunk staging: transpose into [n][k] halfs with packed k-pairs
    auto stage_x = [&](int nc, __half* Xs) {
        const int nco = n0 + nc * 64;
#pragma unroll
        for (int pass = 0; pass < 8; pass++) {
            const int kk = pass * 16 + kgrp * 2;
#pragma unroll
            for (int nh = 0; nh < 2; nh++) {
                const int n = lane + nh * 32;
                float v0 = __ldcs(xb + (size_t)kk * NTOK + nco + n);
                float v1 = __ldcs(xb + (size_t)(kk + 1) * NTOK + nco + n);
                *reinterpret_cast<uint32_t*>(&Xs[n * XS_H + kk]) = f2h2(v0, v1);
            }
        }
    };
    stage_x(0, Xs0);

    // hoist cvec
    float cv[2][2];
#pragma unroll
    for (int i = 0; i < 2; i++) {
        const int r0 = mbase + i * 16 + gid;
        cv[i][0] = g_cv[b * CDIM + r0];
        cv[i][1] = g_cv[b * CDIM + r0 + 8];
    }

    __syncthreads();

    for (int nc = 0; nc < FIN_NCHUNK; nc++) {
        __half* Xs = (nc & 1) ? Xs1 : Xs0;
        if (nc + 1 < FIN_NCHUNK) stage_x(nc + 1, (nc & 1) ? Xs0 : Xs1);

        float acc[2][4][4];
#pragma unroll
        for (int i = 0; i < 2; i++)
#pragma unroll
            for (int j = 0; j < 4; j++)
#pragma unroll
                for (int q = 0; q < 4; q++) acc[i][j][q] = 0.f;

#pragma unroll
        for (int ks = 0; ks < 8; ks++) {
            const int kb = ks * 16;
            uint32_t af[2][4], bf[4][2];
#pragma unroll
            for (int i = 0; i < 2; i++) {
                const int m = mbase + i * 16 + gid;
                af[i][0] = *reinterpret_cast<const uint32_t*>(&Ms[m * MS_H + kb + 2 * tig]);
                af[i][1] = *reinterpret_cast<const uint32_t*>(&Ms[(m + 8) * MS_H + kb + 2 * tig]);
                af[i][2] = *reinterpret_cast<const uint32_t*>(&Ms[m * MS_H + kb + 8 + 2 * tig]);
                af[i][3] = *reinterpret_cast<const uint32_t*>(&Ms[(m + 8) * MS_H + kb + 8 + 2 * tig]);
            }
#pragma unroll
            for (int j = 0; j < 4; j++) {
                const int n = nwarp + j * 8 + gid;
                bf[j][0] = *reinterpret_cast<const uint32_t*>(&Xs[n * XS_H + kb + 2 * tig]);
                bf[j][1] = *reinterpret_cast<const uint32_t*>(&Xs[n * XS_H + kb + 8 + 2 * tig]);
            }
#pragma unroll
            for (int i = 0; i < 2; i++)
#pragma unroll
                for (int j = 0; j < 4; j++)
                    mma_f16(acc[i][j][0], acc[i][j][1], acc[i][j][2], acc[i][j][3],
                            af[i][0], af[i][1], af[i][2], af[i][3], bf[j][0], bf[j][1]);
        }

        // epilogue: + cvec, streaming stores
        const int nco = n0 + nc * 64;
#pragma unroll
        for (int i = 0; i < 2; i++) {
            const int r0 = mbase + i * 16 + gid;
            float* op0 = out + ((size_t)b * CDIM + r0) * NTOK + nco;
            float* op1 = op0 + (size_t)8 * NTOK;
#pragma unroll
            for (int j = 0; j < 4; j++) {
                const int c0 = nwarp + j * 8 + tig * 2;
                __stcs(reinterpret_cast<float2*>(op0 + c0),
                       make_float2(acc[i][j][0] + cv[i][0], acc[i][j][1] + cv[i][0]));
                __stcs(reinterpret_cast<float2*>(op1 + c0),
                       make_float2(acc[i][j][2] + cv[i][1], acc[i][j][3] + cv[i][1]));
            }
        }
        __syncthreads();
    }
}

// ---------------- launch -----------------------------------------------------
extern "C" void kernel_launch(void* const* d_in, const int* in_sizes, int n_in,
                              void* d_out, int out_size) {
    (void)in_sizes; (void)n_in; (void)out_size;
    const float* x     = (const float*)d_in[0];
    const float* w_qkv = (const float*)d_in[1];
    const float* b_qkv = (const float*)d_in[2];
    const float* w_out = (const float*)d_in[3];
    const float* b_out = (const float*)d_in[4];
    float* out = (float*)d_out;

    cudaFuncSetAttribute(k_final, cudaFuncAttributeMaxDynamicSharedMemorySize,
                         SMEM_FINAL_BYTES);

    k_gram<<<dim3(PCH, BATCH), 256>>>(x);
    k_reduceG<<<dim3(8, BATCH), 256>>>(b_out);
    k_attn<<<dim3(NHEADS, BATCH), 256>>>(w_qkv, b_qkv, w_out);
    k_final<<<dim3(NTOK / FIN_NSPAN, BATCH), 256, SMEM_FINAL_BYTES>>>(x, out);
}